// round 6
// baseline (speedup 1.0000x reference)
#include <cuda_runtime.h>

// Problem constants
constexpr int NB   = 128;   // batch
constexpr int NT   = 128;   // encoder time steps
constexpr int NIN  = 3;     // input features
constexpr int NH   = 512;   // hidden
constexpr int NTGT = 32;    // decoder steps

constexpr int ENC_CTAS = 128;          // persistent grid, 1 CTA/SM co-resident
constexpr int DEC_CTAS = 128;

// encoder smem layout
constexpr int SHW_STRIDE = 36;                       // padded w row (floats)
constexpr int SHH_STRIDE = 516;                      // padded h row (floats)
constexpr int SHW_FLOATS = NH * SHW_STRIDE;          // 18432
constexpr int SHH_FLOATS = 32 * SHH_STRIDE;          // 16512
constexpr int RED_FLOATS = 256 * 4;                  // k-split partials
constexpr int ENC_SMEM   = (SHW_FLOATS + SHH_FLOATS + RED_FLOATS) * 4;  // 143872 B

// decoder smem layout (double-staged: two W tiles + two h tiles)
constexpr int DSW = 34;                              // w stride (floats, even for float2)
constexpr int DSH = 520;                             // h stride
constexpr int DSW_FLOATS = NH * DSW;                 // 17408
constexpr int DSH_FLOATS = 16 * DSH;                 // 8320
constexpr int DEC_SMEM = (2 * DSW_FLOATS + 2 * DSH_FLOATS) * 4;  // 205824 B

// ---------------------------------------------------------------------------
// Static device scratch (allocation-free rule: __device__ globals)
// ---------------------------------------------------------------------------
__device__ float g_l0[NT * NB * (2 * NH)];      // encoder L0 concat outputs [t][b][1024]
__device__ float g_xs1[2 * NT * NB * NH];       // L1 input terms [d][t][b][512]
__device__ float g_h[2][2 * NB * NH];           // encoder state ping-pong
__device__ float g_dech[2][4 * NB * NH];        // decoder state ping-pong
__device__ unsigned g_cnt;                      // grid-barrier arrival counter (self-resetting)
__device__ unsigned g_gen;                      // grid-barrier generation (monotonic, replay-safe)

// ---------------------------------------------------------------------------
// Generation-based grid barrier (self-resetting, replay-safe).
// ---------------------------------------------------------------------------
__device__ __forceinline__ void grid_barrier(unsigned nctas)
{
    __threadfence();              // release this thread's stores to GPU scope
    __syncthreads();
    if (threadIdx.x == 0) {
        volatile unsigned* genp = &g_gen;
        unsigned gen = *genp;
        if (atomicAdd(&g_cnt, 1u) == nctas - 1) {
            g_cnt = 0;
            __threadfence();
            *genp = gen + 1;      // release
        } else {
            while (*genp == gen) { }
            __threadfence();      // acquire
        }
    }
    __syncthreads();
}

// ---------------------------------------------------------------------------
// Persistent encoder layer: all 128 time steps in ONE kernel.
// 128 CTAs = (16 j-tiles x 4 b-tiles x 2 dirs), 512 threads, tile 32b x 32j,
// k-split in 2 halves (ks) for latency hiding (4 warps/SMSP).
// Whh tile resident in smem (transposed); per step reload the 32x512 h tile
// (__ldcg) and run a sync-free FFMA loop; k-halves reduced through smem.
// ---------------------------------------------------------------------------
__global__ void __launch_bounds__(512) enc_persist(
    const float* __restrict__ x, const float* __restrict__ Wih0,
    const float* __restrict__ Whh_all, const float* __restrict__ bih,
    const float* __restrict__ bhh, int layer)
{
    extern __shared__ float sm[];
    float* sh_w = sm;                            // [NH][SHW_STRIDE] transposed weights
    float* sh_h = sm + SHW_FLOATS;               // [32][SHH_STRIDE] h tile
    float* sh_r = sm + SHW_FLOATS + SHH_FLOATS;  // [256][4] k-split partials

    const int blk = blockIdx.x;
    const int d   = blk >> 6;          // direction
    const int bt  = (blk >> 4) & 3;    // batch tile
    const int jt  = blk & 15;          // j tile
    const int b0  = bt * 32;
    const int j0  = jt * 32;
    const int tid = threadIdx.x;
    const int ks  = tid >> 8;          // k half (0/1)
    const int r   = tid & 255;
    const int tx  = r & 7;             // j group (4 j per thread)
    const int ty  = r >> 3;            // batch row (0..31)
    const int b   = b0 + ty;
    const int j   = j0 + tx * 4;

    const float* Whh = Whh_all + d * NH * NH;

    // ---- one-time: load Whh tile transposed into smem (512 threads) ----
    {
        const int wr = tid & 31;          // j row (0..31)
        const int wc = (tid >> 5) * 4;    // k col (0..60)
        for (int k0 = 0; k0 < NH; k0 += 64) {
            float4 w = __ldg((const float4*)&Whh[(j0 + wr) * NH + k0 + wc]);
            sh_w[(k0 + wc + 0) * SHW_STRIDE + wr] = w.x;
            sh_w[(k0 + wc + 1) * SHW_STRIDE + wr] = w.y;
            sh_w[(k0 + wc + 2) * SHW_STRIDE + wr] = w.z;
            sh_w[(k0 + wc + 3) * SHW_STRIDE + wr] = w.w;
        }
    }

    // ---- per-thread constants (only ks==0 carries bias/input term) ----
    float bias0 = 0.f, bias1 = 0.f, bias2 = 0.f, bias3 = 0.f;
    float wi[12];
    if (layer == 0 && ks == 0) {
        const int boff = d * NH + j;
        bias0 = bih[boff + 0] + bhh[boff + 0];
        bias1 = bih[boff + 1] + bhh[boff + 1];
        bias2 = bih[boff + 2] + bhh[boff + 2];
        bias3 = bih[boff + 3] + bhh[boff + 3];
        const float* wp = Wih0 + (d * NH + j) * NIN;
#pragma unroll
        for (int i = 0; i < 12; i++) wi[i] = wp[i];
    }
    __syncthreads();   // sh_w ready

    for (int t = 0; t < NT; t++) {
        const int td = d ? (NT - 1 - t) : t;

        // ---- load h_prev tile (skipped at t==0 since h0 == 0) ----
        if (t > 0) {
            const float* hprev = g_h[t & 1] + d * NB * NH;
            const int hr = tid >> 4;            // 0..31
            const int hc = (tid & 15) * 4;      // 0..60
#pragma unroll
            for (int k0 = 0; k0 < NH; k0 += 64) {
                *(float4*)&sh_h[hr * SHH_STRIDE + k0 + hc] =
                    __ldcg((const float4*)&hprev[(b0 + hr) * NH + k0 + hc]);
            }
            __syncthreads();
        }

        // ---- accumulator init (ks==0 only) ----
        float a0 = 0.f, a1 = 0.f, a2 = 0.f, a3 = 0.f;
        if (ks == 0) {
            if (layer == 0) {
                const float* xr = x + (b * NT + td) * NIN;
                const float x0 = xr[0], x1 = xr[1], x2 = xr[2];
                a0 = bias0 + x0 * wi[0] + x1 * wi[1]  + x2 * wi[2];
                a1 = bias1 + x0 * wi[3] + x1 * wi[4]  + x2 * wi[5];
                a2 = bias2 + x0 * wi[6] + x1 * wi[7]  + x2 * wi[8];
                a3 = bias3 + x0 * wi[9] + x1 * wi[10] + x2 * wi[11];
            } else {
                float4 xt = *(const float4*)&g_xs1[((d * NT + td) * NB + b) * NH + j];
                a0 = xt.x; a1 = xt.y; a2 = xt.z; a3 = xt.w;
            }
        }

        // ---- recurrent GEMM: sync-free, weights resident, k-split ----
        if (t > 0) {
            const float* hrow = &sh_h[ty * SHH_STRIDE + ks * 256];
            const float* wcol = &sh_w[(ks * 256) * SHW_STRIDE + tx * 4];
#pragma unroll 4
            for (int kk = 0; kk < 256; kk += 4) {
                float4 hv = *(const float4*)&hrow[kk];
                float4 w0 = *(const float4*)&wcol[(kk + 0) * SHW_STRIDE];
                float4 w1 = *(const float4*)&wcol[(kk + 1) * SHW_STRIDE];
                float4 w2 = *(const float4*)&wcol[(kk + 2) * SHW_STRIDE];
                float4 w3 = *(const float4*)&wcol[(kk + 3) * SHW_STRIDE];
                a0 += hv.x * w0.x; a1 += hv.x * w0.y; a2 += hv.x * w0.z; a3 += hv.x * w0.w;
                a0 += hv.y * w1.x; a1 += hv.y * w1.y; a2 += hv.y * w1.z; a3 += hv.y * w1.w;
                a0 += hv.z * w2.x; a1 += hv.z * w2.y; a2 += hv.z * w2.z; a3 += hv.z * w2.w;
                a0 += hv.w * w3.x; a1 += hv.w * w3.y; a2 += hv.w * w3.z; a3 += hv.w * w3.w;
            }
            // reduce k halves through smem
            if (ks == 1)
                *(float4*)&sh_r[r * 4] = make_float4(a0, a1, a2, a3);
            __syncthreads();
            if (ks == 0) {
                float4 pr = *(const float4*)&sh_r[r * 4];
                a0 += pr.x; a1 += pr.y; a2 += pr.z; a3 += pr.w;
            }
        }

        // ---- activation + writes (ks==0 threads own the outputs) ----
        if (ks == 0) {
            float4 r4 = make_float4(tanhf(a0), tanhf(a1), tanhf(a2), tanhf(a3));
            float* hnext = g_h[(t + 1) & 1] + d * NB * NH;
            *(float4*)&hnext[b * NH + j] = r4;
            if (layer == 0)
                *(float4*)&g_l0[(td * NB + b) * (2 * NH) + d * NH + j] = r4;
            if (t == NT - 1)
                *(float4*)&g_dech[0][(((layer ? 2 : 0) + d) * NB + b) * NH + j] = r4;
        }

        if (t < NT - 1)
            grid_barrier(ENC_CTAS);
    }
}

// ---------------------------------------------------------------------------
// Big GEMM: xs1[d][t][b][j] = l0[t][b][:] . Wih1[d][j][:] + bih1 + bhh1
// M = 16384, N = 512, K = 1024. Tile 64x64, 256 threads, 4x4 per thread.
// ---------------------------------------------------------------------------
__global__ void __launch_bounds__(256) xs1_gemm(
    const float* __restrict__ Wih1, const float* __restrict__ bih,
    const float* __restrict__ bhh)
{
    __shared__ __align__(16) float sh_a[64][36];
    __shared__ __align__(16) float sh_w[32][68];

    const int d  = blockIdx.z;
    const int j0 = blockIdx.x * 64;
    const int m0 = blockIdx.y * 64;
    const int tx = threadIdx.x & 15;
    const int ty = threadIdx.x >> 4;
    const int lr = threadIdx.x >> 3;
    const int lk = (threadIdx.x & 7) * 4;

    const float* Wd = Wih1 + d * NH * (2 * NH);
    float acc[4][4] = {};

    for (int k0 = 0; k0 < 2 * NH; k0 += 32) {
        *(float4*)&sh_a[lr][lk]      = *(const float4*)&g_l0[(m0 + lr) * (2 * NH) + k0 + lk];
        *(float4*)&sh_a[lr + 32][lk] = *(const float4*)&g_l0[(m0 + lr + 32) * (2 * NH) + k0 + lk];
        float4 w0 = *(const float4*)&Wd[(j0 + lr) * (2 * NH) + k0 + lk];
        float4 w1 = *(const float4*)&Wd[(j0 + lr + 32) * (2 * NH) + k0 + lk];
        sh_w[lk + 0][lr] = w0.x; sh_w[lk + 1][lr] = w0.y;
        sh_w[lk + 2][lr] = w0.z; sh_w[lk + 3][lr] = w0.w;
        sh_w[lk + 0][lr + 32] = w1.x; sh_w[lk + 1][lr + 32] = w1.y;
        sh_w[lk + 2][lr + 32] = w1.z; sh_w[lk + 3][lr + 32] = w1.w;
        __syncthreads();
#pragma unroll
        for (int kk = 0; kk < 32; kk++) {
            float4 wv = *(float4*)&sh_w[kk][tx * 4];
            float  v0 = sh_a[ty * 4 + 0][kk];
            float  v1 = sh_a[ty * 4 + 1][kk];
            float  v2 = sh_a[ty * 4 + 2][kk];
            float  v3 = sh_a[ty * 4 + 3][kk];
            acc[0][0] += v0 * wv.x; acc[0][1] += v0 * wv.y; acc[0][2] += v0 * wv.z; acc[0][3] += v0 * wv.w;
            acc[1][0] += v1 * wv.x; acc[1][1] += v1 * wv.y; acc[1][2] += v1 * wv.z; acc[1][3] += v1 * wv.w;
            acc[2][0] += v2 * wv.x; acc[2][1] += v2 * wv.y; acc[2][2] += v2 * wv.z; acc[2][3] += v2 * wv.w;
            acc[3][0] += v3 * wv.x; acc[3][1] += v3 * wv.y; acc[3][2] += v3 * wv.z; acc[3][3] += v3 * wv.w;
        }
        __syncthreads();
    }

    const int jj = j0 + tx * 4;
    const float b0v = bih[(2 + d) * NH + jj + 0] + bhh[(2 + d) * NH + jj + 0];
    const float b1v = bih[(2 + d) * NH + jj + 1] + bhh[(2 + d) * NH + jj + 1];
    const float b2v = bih[(2 + d) * NH + jj + 2] + bhh[(2 + d) * NH + jj + 2];
    const float b3v = bih[(2 + d) * NH + jj + 3] + bhh[(2 + d) * NH + jj + 3];
#pragma unroll
    for (int i = 0; i < 4; i++) {
        const int m = m0 + ty * 4 + i;
        float4 r = make_float4(acc[i][0] + b0v, acc[i][1] + b1v,
                               acc[i][2] + b2v, acc[i][3] + b3v);
        *(float4*)&g_xs1[(d * NT * NB + m) * NH + jj] = r;
    }
}

// ---------------------------------------------------------------------------
// Persistent decoder: stage-then-compute per phase.
// 128 CTAs = (16 jt x 8 bt), 256 threads, tile 16b x 32j, 2 out/thread.
// Per layer: stage W (transposed) + h tiles for BOTH gemms into smem with one
// sync, then run sync-free FFMA loops. Grid barrier between layer phases.
// ---------------------------------------------------------------------------
__device__ __forceinline__ void dec_stage_w(const float* __restrict__ W,
                                            int j0, float* __restrict__ sw)
{
    const int r  = threadIdx.x >> 3;        // 0..31 (j row)
    const int c0 = (threadIdx.x & 7) * 4;   // 0..28 (k col)
#pragma unroll
    for (int k0 = 0; k0 < NH; k0 += 32) {
        float4 w = __ldg((const float4*)&W[(j0 + r) * NH + k0 + c0]);
        sw[(k0 + c0 + 0) * DSW + r] = w.x;
        sw[(k0 + c0 + 1) * DSW + r] = w.y;
        sw[(k0 + c0 + 2) * DSW + r] = w.z;
        sw[(k0 + c0 + 3) * DSW + r] = w.w;
    }
}

__device__ __forceinline__ void dec_stage_h(const float* __restrict__ A,
                                            int b0, float* __restrict__ sh)
{
    const int row = threadIdx.x >> 4;       // 0..15
    const int c   = (threadIdx.x & 15) * 4; // 0..60
#pragma unroll
    for (int k0 = 0; k0 < NH; k0 += 64)
        *(float4*)&sh[row * DSH + k0 + c] =
            __ldcg((const float4*)&A[(b0 + row) * NH + k0 + c]);
}

__device__ __forceinline__ void dec_compute(const float* __restrict__ sw,
                                            const float* __restrict__ sh,
                                            int tx, int ty, float& a0, float& a1)
{
    const float* hrow = sh + ty * DSH;
    const float* wcol = sw + tx * 2;
#pragma unroll 4
    for (int kk = 0; kk < NH; kk += 4) {
        float4 hv = *(const float4*)&hrow[kk];
        float2 w0 = *(const float2*)&wcol[(kk + 0) * DSW];
        float2 w1 = *(const float2*)&wcol[(kk + 1) * DSW];
        float2 w2 = *(const float2*)&wcol[(kk + 2) * DSW];
        float2 w3 = *(const float2*)&wcol[(kk + 3) * DSW];
        a0 += hv.x * w0.x; a1 += hv.x * w0.y;
        a0 += hv.y * w1.x; a1 += hv.y * w1.y;
        a0 += hv.z * w2.x; a1 += hv.z * w2.y;
        a0 += hv.w * w3.x; a1 += hv.w * w3.y;
    }
}

__global__ void __launch_bounds__(256) dec_persist(
    const float* __restrict__ x,    const float* __restrict__ Wih0,
    const float* __restrict__ Wihr, const float* __restrict__ Whh,
    const float* __restrict__ bih,  const float* __restrict__ bhh,
    const float* __restrict__ linW, const float* __restrict__ linb,
    float* __restrict__ out)
{
    extern __shared__ float dsm[];
    float* swA = dsm;                              // [NH][DSW]
    float* swB = dsm + DSW_FLOATS;
    float* shA = dsm + 2 * DSW_FLOATS;             // [16][DSH]
    float* shB = dsm + 2 * DSW_FLOATS + DSH_FLOATS;

    __shared__ float s_dec[16][3];   // decin for this CTA's b-tile
    __shared__ float s_o0[16];

    const int jt = blockIdx.x & 15;
    const int bt = blockIdx.x >> 4;
    const int j0 = jt * 32;
    const int b0 = bt * 16;
    const int tx = threadIdx.x & 15;     // j pair
    const int ty = threadIdx.x >> 4;     // batch row (0..15)
    const int b  = b0 + ty;
    const int j  = j0 + tx * 2;
    const int wid  = threadIdx.x >> 5;
    const int lane = threadIdx.x & 31;

    // initial decin = x[:, -1, :]
    if (threadIdx.x < 16) {
        const float* xr = x + ((b0 + threadIdx.x) * NT + (NT - 1)) * NIN;
        s_dec[threadIdx.x][0] = xr[0];
        s_dec[threadIdx.x][1] = xr[1];
        s_dec[threadIdx.x][2] = xr[2];
    }
    __syncthreads();

    for (int t = 0; t < NTGT; t++) {
        const int p = t & 1;

        // ---- fold output dot of step t-1 + feedback update ----
        if (t > 0) {
            const float* h3 = g_dech[p] + 3 * NB * NH;   // h3 @ t-1
#pragma unroll
            for (int rr = 0; rr < 2; rr++) {
                const int br = 2 * wid + rr;
                const float* row = h3 + (b0 + br) * NH;
                float s = 0.f;
                for (int i = lane; i < NH; i += 32)
                    s += __ldcg(&row[i]) * linW[i];
#pragma unroll
                for (int o = 16; o; o >>= 1) s += __shfl_xor_sync(0xffffffffu, s, o);
                if (lane == 0) s_o0[br] = s;
            }
            __syncthreads();
            if (threadIdx.x < 16) {
                float o0 = s_o0[threadIdx.x] + linb[0];
                if (jt == 0) out[(b0 + threadIdx.x) * NTGT + (t - 1)] = o0;
                float s1 = s_dec[threadIdx.x][0] - o0;
                float s2 = s_dec[threadIdx.x][1] - s1;
                s_dec[threadIdx.x][0] = o0;
                s_dec[threadIdx.x][1] = s1;
                s_dec[threadIdx.x][2] = s2;
            }
            __syncthreads();
        }

        // ---- 4 layers, grid barrier between phases ----
        for (int l = 0; l < 4; l++) {
            // stage everything for this phase (single sync)
            dec_stage_w(Whh + l * NH * NH, j0, swA);
            dec_stage_h(g_dech[p] + l * NB * NH, b0, shA);
            if (l > 0) {
                dec_stage_w(Wihr + (l - 1) * NH * NH, j0, swB);
                dec_stage_h(g_dech[1 - p] + (l - 1) * NB * NH, b0, shB);
            }
            __syncthreads();

            float a0 = bih[l * NH + j + 0] + bhh[l * NH + j + 0];
            float a1 = bih[l * NH + j + 1] + bhh[l * NH + j + 1];

            if (l == 0) {
                const float i0 = s_dec[ty][0], i1 = s_dec[ty][1], i2 = s_dec[ty][2];
                const float* wp = Wih0 + j * NIN;
                a0 += i0 * wp[0] + i1 * wp[1] + i2 * wp[2];
                a1 += i0 * wp[3] + i1 * wp[4] + i2 * wp[5];
            }

            dec_compute(swA, shA, tx, ty, a0, a1);   // recurrent term
            if (l > 0)
                dec_compute(swB, shB, tx, ty, a0, a1);  // input term

            float* hout = g_dech[1 - p] + l * NB * NH;
            float2 r2 = make_float2(tanhf(a0), tanhf(a1));
            *(float2*)&hout[b * NH + j] = r2;

            grid_barrier(DEC_CTAS);
        }
    }

    // ---- final output (t = NTGT-1): h3 lives in g_dech[0] ----
    {
        const float* h3 = g_dech[0] + 3 * NB * NH;
#pragma unroll
        for (int rr = 0; rr < 2; rr++) {
            const int br = 2 * wid + rr;
            const float* row = h3 + (b0 + br) * NH;
            float s = 0.f;
            for (int i = lane; i < NH; i += 32)
                s += __ldcg(&row[i]) * linW[i];
#pragma unroll
            for (int o = 16; o; o >>= 1) s += __shfl_xor_sync(0xffffffffu, s, o);
            if (lane == 0) s_o0[br] = s;
        }
        __syncthreads();
        if (threadIdx.x < 16 && jt == 0)
            out[(b0 + threadIdx.x) * NTGT + (NTGT - 1)] = s_o0[threadIdx.x] + linb[0];
    }
}

// ---------------------------------------------------------------------------
// Launch sequence (graph-capturable: kernel launches only)
// ---------------------------------------------------------------------------
extern "C" void kernel_launch(void* const* d_in, const int* in_sizes, int n_in,
                              void* d_out, int out_size)
{
    const float* x        = (const float*)d_in[0];
    const float* enc_Wih0 = (const float*)d_in[2];
    const float* enc_Whh0 = (const float*)d_in[3];
    const float* enc_Wih1 = (const float*)d_in[4];
    const float* enc_Whh1 = (const float*)d_in[5];
    const float* enc_bih  = (const float*)d_in[6];
    const float* enc_bhh  = (const float*)d_in[7];
    const float* dec_Wih0 = (const float*)d_in[8];
    const float* dec_Wihr = (const float*)d_in[9];
    const float* dec_Whh  = (const float*)d_in[10];
    const float* dec_bih  = (const float*)d_in[11];
    const float* dec_bhh  = (const float*)d_in[12];
    const float* lin_W    = (const float*)d_in[13];
    const float* lin_b    = (const float*)d_in[14];
    float* out = (float*)d_out;

    cudaFuncSetAttribute(enc_persist, cudaFuncAttributeMaxDynamicSharedMemorySize,
                         ENC_SMEM);
    cudaFuncSetAttribute(dec_persist, cudaFuncAttributeMaxDynamicSharedMemorySize,
                         DEC_SMEM);

    // Encoder layer 0: persistent, all 128 steps
    enc_persist<<<ENC_CTAS, 512, ENC_SMEM>>>(x, enc_Wih0, enc_Whh0,
                                             enc_bih, enc_bhh, 0);

    // Layer-1 input terms for all t (both dirs), biases folded in
    xs1_gemm<<<dim3(8, 256, 2), 256>>>(enc_Wih1, enc_bih, enc_bhh);

    // Encoder layer 1: persistent
    enc_persist<<<ENC_CTAS, 512, ENC_SMEM>>>(x, enc_Wih0, enc_Whh1,
                                             enc_bih, enc_bhh, 1);

    // Decoder: persistent, all 32 steps x 4 layers + output/feedback
    dec_persist<<<DEC_CTAS, 256, DEC_SMEM>>>(x, dec_Wih0, dec_Wihr, dec_Whh,
                                             dec_bih, dec_bhh, lin_W, lin_b, out);
}

// round 7
// speedup vs baseline: 1.6531x; 1.6531x over previous
#include <cuda_runtime.h>
#include <cuda_bf16.h>
#include <cstdint>

// Problem constants
constexpr int NB   = 128;   // batch
constexpr int NT   = 128;   // encoder time steps
constexpr int NIN  = 3;     // input features
constexpr int NH   = 512;   // hidden
constexpr int NTGT = 32;    // decoder steps

constexpr int ENC_CTAS = 128;   // persistent grid, 1 CTA/SM co-resident

// encoder smem layout (bytes). bf16 tiles padded to 520 elems/row (1040 B,
// 65x16B -> ldmatrix row addresses conflict-free).
constexpr int EHS      = 520;                   // bf16 row stride (elements)
constexpr int TILE_B   = 32 * EHS * 2;          // 33280 B per bf16 tile
constexpr int OFF_WHI  = 0;
constexpr int OFF_WLO  = OFF_WHI + TILE_B;
constexpr int OFF_HHI  = OFF_WLO + TILE_B;
constexpr int OFF_HLO  = OFF_HHI + TILE_B;
constexpr int OFF_STG  = OFF_HLO + TILE_B;      // 133120
constexpr int STG_STRIDE = 36;                  // f32 stage row stride
constexpr int ENC_SMEM = OFF_STG + 32 * STG_STRIDE * 4;   // 137728 B

// ---------------------------------------------------------------------------
// Static device scratch (allocation-free rule: __device__ globals)
// ---------------------------------------------------------------------------
__device__ float g_l0[NT * NB * (2 * NH)];          // L0 concat outputs [t][b][1024]
__device__ float g_xs1[2 * NT * NB * NH];           // L1 input terms [d][t][b][512]
__device__ __nv_bfloat16 g_hhi[2][2 * NB * NH];     // encoder h ping-pong, bf16 hi
__device__ __nv_bfloat16 g_hlo[2][2 * NB * NH];     // encoder h ping-pong, bf16 lo
__device__ float g_dech[2][4 * NB * NH];            // decoder state ping-pong
__device__ float g_decin[2][NB * 4];                // decoder feedback input
__device__ unsigned g_cnt;                          // barrier arrival counter
__device__ unsigned g_gen;                          // barrier generation (monotonic)

// ---------------------------------------------------------------------------
// Generation-based grid barrier (self-resetting, replay-safe).
// ---------------------------------------------------------------------------
__device__ __forceinline__ void grid_barrier(unsigned nctas)
{
    __threadfence();
    __syncthreads();
    if (threadIdx.x == 0) {
        volatile unsigned* genp = &g_gen;
        unsigned gen = *genp;
        if (atomicAdd(&g_cnt, 1u) == nctas - 1) {
            g_cnt = 0;
            __threadfence();
            *genp = gen + 1;
        } else {
            while (*genp == gen) { }
            __threadfence();
        }
    }
    __syncthreads();
}

// ---------------------------------------------------------------------------
// mma.sync helpers (Ampere-style, valid on sm_103a)
// ---------------------------------------------------------------------------
__device__ __forceinline__ uint32_t s2u(const void* p)
{
    return (uint32_t)__cvta_generic_to_shared(p);
}

#define LDSM_X4(r0, r1, r2, r3, addr)                                          \
    asm volatile("ldmatrix.sync.aligned.m8n8.x4.shared.b16 {%0,%1,%2,%3}, [%4];" \
                 : "=r"(r0), "=r"(r1), "=r"(r2), "=r"(r3) : "r"(addr))

#define LDSM_X2(r0, r1, addr)                                                  \
    asm volatile("ldmatrix.sync.aligned.m8n8.x2.shared.b16 {%0,%1}, [%2];"     \
                 : "=r"(r0), "=r"(r1) : "r"(addr))

#define MMA_BF16(c0, c1, c2, c3, a0, a1, a2, a3, b0, b1)                       \
    asm volatile("mma.sync.aligned.m16n8k16.row.col.f32.bf16.bf16.f32 "        \
                 "{%0,%1,%2,%3}, {%4,%5,%6,%7}, {%8,%9}, {%0,%1,%2,%3};"       \
                 : "+f"(c0), "+f"(c1), "+f"(c2), "+f"(c3)                      \
                 : "r"(a0), "r"(a1), "r"(a2), "r"(a3), "r"(b0), "r"(b1))

__device__ __forceinline__ void split_bf16(float v, __nv_bfloat16& hi, __nv_bfloat16& lo)
{
    hi = __float2bfloat16(v);
    lo = __float2bfloat16(v - __bfloat162float(hi));
}

// ---------------------------------------------------------------------------
// Persistent encoder layer via tensor cores (bf16 hi/lo split, 3 MMA passes).
// 128 CTAs = (16 j-tiles x 4 b-tiles x 2 dirs), 256 threads, tile 32j x 32b.
// out[j][b] = sum_k W[j][k] * h[b][k]:  A = W (row-major, 16x16), B = h
// (B[k][b] = h[b][k], col-major k-contig -> ldmatrix.x2 on h rows, no trans).
// W split once into smem; h ping-pongs through global as bf16 hi/lo.
// Warp w: mj = w&1 (j sub 16), nb = w>>1 (b sub 8); 32 k-iters x 3 mma.
// ---------------------------------------------------------------------------
__global__ void __launch_bounds__(256) enc_mma(
    const float* __restrict__ x, const float* __restrict__ Wih0,
    const float* __restrict__ Whh_all, const float* __restrict__ bih,
    const float* __restrict__ bhh, int layer)
{
    extern __shared__ char sm[];
    __nv_bfloat16* sWhi = (__nv_bfloat16*)(sm + OFF_WHI);
    __nv_bfloat16* sWlo = (__nv_bfloat16*)(sm + OFF_WLO);
    __nv_bfloat16* sHhi = (__nv_bfloat16*)(sm + OFF_HHI);
    __nv_bfloat16* sHlo = (__nv_bfloat16*)(sm + OFF_HLO);
    float*         sStg = (float*)(sm + OFF_STG);          // [32 b][36] f32

    const int blk = blockIdx.x;
    const int d   = blk >> 6;          // direction
    const int bt  = (blk >> 4) & 3;    // batch tile
    const int jt  = blk & 15;          // j tile
    const int b0  = bt * 32;
    const int j0  = jt * 32;
    const int tid = threadIdx.x;
    const int lane = tid & 31;
    const int warp = tid >> 5;         // 0..7
    const int mj   = warp & 1;         // j subtile (16 rows)
    const int nb   = warp >> 1;        // b subtile (8 cols)

    const float* Whh = Whh_all + d * NH * NH;

    // ---- one-time: split W tile into smem bf16 hi/lo ----
    {
        const int r  = tid >> 3;              // 0..31 (j row)
        const int c0 = (tid & 7) * 4;
        for (int k0 = 0; k0 < NH; k0 += 32) {
            float4 w = __ldg((const float4*)&Whh[(j0 + r) * NH + k0 + c0]);
            const int o = r * EHS + k0 + c0;
            split_bf16(w.x, sWhi[o + 0], sWlo[o + 0]);
            split_bf16(w.y, sWhi[o + 1], sWlo[o + 1]);
            split_bf16(w.z, sWhi[o + 2], sWlo[o + 2]);
            split_bf16(w.w, sWhi[o + 3], sWlo[o + 3]);
        }
    }

    // ---- ldmatrix base addresses (constant across steps) ----
    // A (W tile): 4 matrices: (rows 0-7/8-15) x (k 0-7/8-15)
    const int ag = lane >> 3, ar = lane & 7;
    const uint32_t aRowOff = (uint32_t)((mj * 16 + (ag & 1) * 8 + ar) * EHS + (ag >> 1) * 8) * 2;
    const uint32_t aHiBase = s2u(sWhi) + aRowOff;
    const uint32_t aLoBase = s2u(sWlo) + aRowOff;
    // B (h tile): 2 matrices: (k 0-7 / 8-15), rows = b
    const int bg = (lane & 15) >> 3, br = lane & 7;
    const uint32_t bRowOff = (uint32_t)((nb * 8 + br) * EHS + bg * 8) * 2;
    const uint32_t bHiBase = s2u(sHhi) + bRowOff;
    const uint32_t bLoBase = s2u(sHlo) + bRowOff;

    // ---- layer-0 constants: bias + Wih rows for this thread's stage slot ----
    const int sr = tid >> 3;               // stage row (b) this thread initializes
    const int sj = (tid & 7) * 4;          // stage col base (j)
    float bias[4], wi[12];
    if (layer == 0) {
#pragma unroll
        for (int i = 0; i < 4; i++)
            bias[i] = bih[d * NH + j0 + sj + i] + bhh[d * NH + j0 + sj + i];
        const float* wp = Wih0 + (d * NH + j0 + sj) * NIN;
#pragma unroll
        for (int i = 0; i < 12; i++) wi[i] = wp[i];
    }

    // D-fragment positions for this lane (within 32x32 tile)
    const int jl = mj * 16 + (lane >> 2);        // rows jl, jl+8
    const int bl = nb * 8 + (lane & 3) * 2;      // cols bl, bl+1

    __syncthreads();   // W smem ready

    for (int t = 0; t < NT; t++) {
        const int td = d ? (NT - 1 - t) : t;

        // ---- phase 1: copy h (bf16 hi/lo) into smem + stage init ----
        if (t > 0) {
            const int p = t & 1;
            const __nv_bfloat16* srcHi = g_hhi[p] + (d * NB + b0) * NH;
            const __nv_bfloat16* srcLo = g_hlo[p] + (d * NB + b0) * NH;
            const int r  = tid >> 3;            // 0..31
            const int cc = tid & 7;             // 16B chunk base
#pragma unroll
            for (int it = 0; it < 8; it++) {
                const int c16 = cc + it * 8;    // 0..63
                uint4 vh = __ldcg((const uint4*)(srcHi + r * NH) + c16);
                uint4 vl = __ldcg((const uint4*)(srcLo + r * NH) + c16);
                *(uint4*)((char*)sHhi + r * (EHS * 2) + c16 * 16) = vh;
                *(uint4*)((char*)sHlo + r * (EHS * 2) + c16 * 16) = vl;
            }
        }
        // stage init: [b][j] tile of the non-recurrent term
        if (layer == 0) {
            const float* xr = x + ((b0 + sr) * NT + td) * NIN;
            const float x0 = xr[0], x1 = xr[1], x2 = xr[2];
            float4 v;
            v.x = bias[0] + x0 * wi[0] + x1 * wi[1]  + x2 * wi[2];
            v.y = bias[1] + x0 * wi[3] + x1 * wi[4]  + x2 * wi[5];
            v.z = bias[2] + x0 * wi[6] + x1 * wi[7]  + x2 * wi[8];
            v.w = bias[3] + x0 * wi[9] + x1 * wi[10] + x2 * wi[11];
            *(float4*)&sStg[sr * STG_STRIDE + sj] = v;
        } else {
            float4 v = __ldg((const float4*)&g_xs1[((d * NT + td) * NB + b0 + sr) * NH + j0 + sj]);
            *(float4*)&sStg[sr * STG_STRIDE + sj] = v;
        }
        __syncthreads();

        // ---- phase 2: tensor-core recurrent GEMM ----
        float c0 = 0.f, c1 = 0.f, c2 = 0.f, c3 = 0.f;
        if (t > 0) {
            uint32_t aHi = aHiBase, aLo = aLoBase, bHi = bHiBase, bLo = bLoBase;
#pragma unroll 4
            for (int kk = 0; kk < 32; kk++) {
                uint32_t a0, a1, a2, a3, e0, e1, e2, e3, r0, r1, f0, f1;
                LDSM_X4(a0, a1, a2, a3, aHi);
                LDSM_X4(e0, e1, e2, e3, aLo);
                LDSM_X2(r0, r1, bHi);
                LDSM_X2(f0, f1, bLo);
                MMA_BF16(c0, c1, c2, c3, a0, a1, a2, a3, r0, r1);  // hi*hi
                MMA_BF16(c0, c1, c2, c3, a0, a1, a2, a3, f0, f1);  // hi*lo
                MMA_BF16(c0, c1, c2, c3, e0, e1, e2, e3, r0, r1);  // lo*hi
                aHi += 32; aLo += 32; bHi += 32; bLo += 32;
            }
        }

        // ---- phase 3: add init, tanh, write back to stage (owner-only) ----
        {
            float i0 = sStg[(bl + 0) * STG_STRIDE + jl];
            float i1 = sStg[(bl + 1) * STG_STRIDE + jl];
            float i2 = sStg[(bl + 0) * STG_STRIDE + jl + 8];
            float i3 = sStg[(bl + 1) * STG_STRIDE + jl + 8];
            sStg[(bl + 0) * STG_STRIDE + jl]     = tanhf(c0 + i0);
            sStg[(bl + 1) * STG_STRIDE + jl]     = tanhf(c1 + i1);
            sStg[(bl + 0) * STG_STRIDE + jl + 8] = tanhf(c2 + i2);
            sStg[(bl + 1) * STG_STRIDE + jl + 8] = tanhf(c3 + i3);
        }
        __syncthreads();

        // ---- phase 4: vectorized outputs from stage ----
        {
            float4 v = *(const float4*)&sStg[sr * STG_STRIDE + sj];
            __nv_bfloat16 h0, h1, h2, h3, l0b, l1b, l2b, l3b;
            split_bf16(v.x, h0, l0b); split_bf16(v.y, h1, l1b);
            split_bf16(v.z, h2, l2b); split_bf16(v.w, h3, l3b);
            const int p1 = (t + 1) & 1;
            const int gidx = (d * NB + b0 + sr) * NH + j0 + sj;
            uint2 phi, plo;
            phi.x = (uint32_t)__bfloat16_as_ushort(h0) | ((uint32_t)__bfloat16_as_ushort(h1) << 16);
            phi.y = (uint32_t)__bfloat16_as_ushort(h2) | ((uint32_t)__bfloat16_as_ushort(h3) << 16);
            plo.x = (uint32_t)__bfloat16_as_ushort(l0b) | ((uint32_t)__bfloat16_as_ushort(l1b) << 16);
            plo.y = (uint32_t)__bfloat16_as_ushort(l2b) | ((uint32_t)__bfloat16_as_ushort(l3b) << 16);
            *(uint2*)(g_hhi[p1] + gidx) = phi;
            *(uint2*)(g_hlo[p1] + gidx) = plo;
            if (layer == 0)
                *(float4*)&g_l0[(td * NB + b0 + sr) * (2 * NH) + d * NH + j0 + sj] = v;
            if (t == NT - 1)
                *(float4*)&g_dech[0][(((layer ? 2 : 0) + d) * NB + b0 + sr) * NH + j0 + sj] = v;
        }

        if (t < NT - 1)
            grid_barrier(ENC_CTAS);
    }
}

// ---------------------------------------------------------------------------
// Big GEMM: xs1[d][t][b][j] = l0[t][b][:] . Wih1[d][j][:] + bih1 + bhh1
// M = 16384, N = 512, K = 1024. Tile 64x64, 256 threads, 4x4 per thread.
// ---------------------------------------------------------------------------
__global__ void __launch_bounds__(256) xs1_gemm(
    const float* __restrict__ Wih1, const float* __restrict__ bih,
    const float* __restrict__ bhh)
{
    __shared__ __align__(16) float sh_a[64][36];
    __shared__ __align__(16) float sh_w[32][68];

    const int d  = blockIdx.z;
    const int j0 = blockIdx.x * 64;
    const int m0 = blockIdx.y * 64;
    const int tx = threadIdx.x & 15;
    const int ty = threadIdx.x >> 4;
    const int lr = threadIdx.x >> 3;
    const int lk = (threadIdx.x & 7) * 4;

    const float* Wd = Wih1 + d * NH * (2 * NH);
    float acc[4][4] = {};

    for (int k0 = 0; k0 < 2 * NH; k0 += 32) {
        *(float4*)&sh_a[lr][lk]      = *(const float4*)&g_l0[(m0 + lr) * (2 * NH) + k0 + lk];
        *(float4*)&sh_a[lr + 32][lk] = *(const float4*)&g_l0[(m0 + lr + 32) * (2 * NH) + k0 + lk];
        float4 w0 = *(const float4*)&Wd[(j0 + lr) * (2 * NH) + k0 + lk];
        float4 w1 = *(const float4*)&Wd[(j0 + lr + 32) * (2 * NH) + k0 + lk];
        sh_w[lk + 0][lr] = w0.x; sh_w[lk + 1][lr] = w0.y;
        sh_w[lk + 2][lr] = w0.z; sh_w[lk + 3][lr] = w0.w;
        sh_w[lk + 0][lr + 32] = w1.x; sh_w[lk + 1][lr + 32] = w1.y;
        sh_w[lk + 2][lr + 32] = w1.z; sh_w[lk + 3][lr + 32] = w1.w;
        __syncthreads();
#pragma unroll
        for (int kk = 0; kk < 32; kk++) {
            float4 wv = *(float4*)&sh_w[kk][tx * 4];
            float  v0 = sh_a[ty * 4 + 0][kk];
            float  v1 = sh_a[ty * 4 + 1][kk];
            float  v2 = sh_a[ty * 4 + 2][kk];
            float  v3 = sh_a[ty * 4 + 3][kk];
            acc[0][0] += v0 * wv.x; acc[0][1] += v0 * wv.y; acc[0][2] += v0 * wv.z; acc[0][3] += v0 * wv.w;
            acc[1][0] += v1 * wv.x; acc[1][1] += v1 * wv.y; acc[1][2] += v1 * wv.z; acc[1][3] += v1 * wv.w;
            acc[2][0] += v2 * wv.x; acc[2][1] += v2 * wv.y; acc[2][2] += v2 * wv.z; acc[2][3] += v2 * wv.w;
            acc[3][0] += v3 * wv.x; acc[3][1] += v3 * wv.y; acc[3][2] += v3 * wv.z; acc[3][3] += v3 * wv.w;
        }
        __syncthreads();
    }

    const int jj = j0 + tx * 4;
    const float b0v = bih[(2 + d) * NH + jj + 0] + bhh[(2 + d) * NH + jj + 0];
    const float b1v = bih[(2 + d) * NH + jj + 1] + bhh[(2 + d) * NH + jj + 1];
    const float b2v = bih[(2 + d) * NH + jj + 2] + bhh[(2 + d) * NH + jj + 2];
    const float b3v = bih[(2 + d) * NH + jj + 3] + bhh[(2 + d) * NH + jj + 3];
#pragma unroll
    for (int i = 0; i < 4; i++) {
        const int m = m0 + ty * 4 + i;
        float4 r = make_float4(acc[i][0] + b0v, acc[i][1] + b1v,
                               acc[i][2] + b2v, acc[i][3] + b3v);
        *(float4*)&g_xs1[(d * NT * NB + m) * NH + jj] = r;
    }
}

// ---------------------------------------------------------------------------
// Decoder (R4 launch-based version): tile 16b x 32j, 128 threads.
// ---------------------------------------------------------------------------
__device__ __forceinline__ void gemm16x32(
    const float* __restrict__ V, const float* __restrict__ W,
    int b0, int j0, int tx, int ty,
    float& a0, float& a1, float& a2, float& a3,
    float (*sh_v)[36], float (*sh_w)[36])
{
    const int lb = threadIdx.x >> 3;
    const int lk = (threadIdx.x & 7) * 4;
    for (int k0 = 0; k0 < NH; k0 += 32) {
        *(float4*)&sh_v[lb][lk] = *(const float4*)&V[(b0 + lb) * NH + k0 + lk];
        float4 w0 = *(const float4*)&W[(j0 + lb) * NH + k0 + lk];
        float4 w1 = *(const float4*)&W[(j0 + lb + 16) * NH + k0 + lk];
        sh_w[lk + 0][lb] = w0.x; sh_w[lk + 1][lb] = w0.y;
        sh_w[lk + 2][lb] = w0.z; sh_w[lk + 3][lb] = w0.w;
        sh_w[lk + 0][lb + 16] = w1.x; sh_w[lk + 1][lb + 16] = w1.y;
        sh_w[lk + 2][lb + 16] = w1.z; sh_w[lk + 3][lb + 16] = w1.w;
        __syncthreads();
#pragma unroll
        for (int kk = 0; kk < 32; kk++) {
            float  hv = sh_v[ty][kk];
            float4 wv = *(float4*)&sh_w[kk][tx * 4];
            a0 += hv * wv.x; a1 += hv * wv.y; a2 += hv * wv.z; a3 += hv * wv.w;
        }
        __syncthreads();
    }
}

__global__ void __launch_bounds__(128) dec_layer(
    const float* __restrict__ x,   const float* __restrict__ Wih0,
    const float* __restrict__ Wihr, const float* __restrict__ Whh,
    const float* __restrict__ bih, const float* __restrict__ bhh,
    int t, int l)
{
    __shared__ __align__(16) float sh_v[16][36];
    __shared__ __align__(16) float sh_w[32][36];

    const int p  = t & 1;
    const int j0 = blockIdx.x * 32;
    const int b0 = blockIdx.y * 16;
    const int tx = threadIdx.x & 7;
    const int ty = threadIdx.x >> 3;
    const int b  = b0 + ty;
    const int j  = j0 + tx * 4;

    float a0 = bih[l * NH + j + 0] + bhh[l * NH + j + 0];
    float a1 = bih[l * NH + j + 1] + bhh[l * NH + j + 1];
    float a2 = bih[l * NH + j + 2] + bhh[l * NH + j + 2];
    float a3 = bih[l * NH + j + 3] + bhh[l * NH + j + 3];

    if (l == 0) {
        float i0, i1, i2;
        if (t == 0) {
            const float* xr = x + (b * NT + (NT - 1)) * NIN;
            i0 = xr[0]; i1 = xr[1]; i2 = xr[2];
        } else {
            const float* dr = g_decin[p] + b * 4;
            i0 = dr[0]; i1 = dr[1]; i2 = dr[2];
        }
        const float* wi = Wih0 + j * NIN;
        a0 += i0 * wi[0] + i1 * wi[1]  + i2 * wi[2];
        a1 += i0 * wi[3] + i1 * wi[4]  + i2 * wi[5];
        a2 += i0 * wi[6] + i1 * wi[7]  + i2 * wi[8];
        a3 += i0 * wi[9] + i1 * wi[10] + i2 * wi[11];
    }

    gemm16x32(g_dech[p] + l * NB * NH, Whh + l * NH * NH,
              b0, j0, tx, ty, a0, a1, a2, a3, sh_v, sh_w);
    if (l > 0)
        gemm16x32(g_dech[1 - p] + (l - 1) * NB * NH, Wihr + (l - 1) * NH * NH,
                  b0, j0, tx, ty, a0, a1, a2, a3, sh_v, sh_w);

    float* hout = g_dech[1 - p] + l * NB * NH;
    float4 r = make_float4(tanhf(a0), tanhf(a1), tanhf(a2), tanhf(a3));
    *(float4*)&hout[b * NH + j] = r;
}

__global__ void __launch_bounds__(128) out_step(
    const float* __restrict__ x, const float* __restrict__ linW,
    const float* __restrict__ linb, float* __restrict__ out, int t)
{
    const int p    = t & 1;
    const int warp = threadIdx.x >> 5;
    const int lane = threadIdx.x & 31;
    const int b    = blockIdx.x * 4 + warp;

    const float* h3 = g_dech[1 - p] + 3 * NB * NH + b * NH;
    float s = 0.f;
#pragma unroll
    for (int j = lane; j < NH; j += 32) s += h3[j] * linW[j];
#pragma unroll
    for (int o = 16; o; o >>= 1) s += __shfl_xor_sync(0xffffffffu, s, o);

    if (lane == 0) {
        float o0 = s + linb[0];
        float xi0, xi1;
        if (t == 0) {
            const float* xr = x + (b * NT + (NT - 1)) * NIN;
            xi0 = xr[0]; xi1 = xr[1];
        } else {
            xi0 = g_decin[p][b * 4 + 0];
            xi1 = g_decin[p][b * 4 + 1];
        }
        float s1 = xi0 - o0;
        float s2 = xi1 - s1;
        g_decin[1 - p][b * 4 + 0] = o0;
        g_decin[1 - p][b * 4 + 1] = s1;
        g_decin[1 - p][b * 4 + 2] = s2;
        out[b * NTGT + t] = o0;
    }
}

// ---------------------------------------------------------------------------
// Launch sequence (graph-capturable: kernel launches only)
// ---------------------------------------------------------------------------
extern "C" void kernel_launch(void* const* d_in, const int* in_sizes, int n_in,
                              void* d_out, int out_size)
{
    const float* x        = (const float*)d_in[0];
    const float* enc_Wih0 = (const float*)d_in[2];
    const float* enc_Whh0 = (const float*)d_in[3];
    const float* enc_Wih1 = (const float*)d_in[4];
    const float* enc_Whh1 = (const float*)d_in[5];
    const float* enc_bih  = (const float*)d_in[6];
    const float* enc_bhh  = (const float*)d_in[7];
    const float* dec_Wih0 = (const float*)d_in[8];
    const float* dec_Wihr = (const float*)d_in[9];
    const float* dec_Whh  = (const float*)d_in[10];
    const float* dec_bih  = (const float*)d_in[11];
    const float* dec_bhh  = (const float*)d_in[12];
    const float* lin_W    = (const float*)d_in[13];
    const float* lin_b    = (const float*)d_in[14];
    float* out = (float*)d_out;

    cudaFuncSetAttribute(enc_mma, cudaFuncAttributeMaxDynamicSharedMemorySize,
                         ENC_SMEM);

    // Encoder layer 0: persistent, tensor-core steps
    enc_mma<<<ENC_CTAS, 256, ENC_SMEM>>>(x, enc_Wih0, enc_Whh0,
                                         enc_bih, enc_bhh, 0);

    // Layer-1 input terms for all t (both dirs), biases folded in
    xs1_gemm<<<dim3(8, 256, 2), 256>>>(enc_Wih1, enc_bih, enc_bhh);

    // Encoder layer 1: persistent, tensor-core steps
    enc_mma<<<ENC_CTAS, 256, ENC_SMEM>>>(x, enc_Wih0, enc_Whh1,
                                         enc_bih, enc_bhh, 1);

    // Decoder: 32 steps x (4 layers + output/feedback), launch-based (R4)
    for (int t = 0; t < NTGT; t++) {
        for (int l = 0; l < 4; l++)
            dec_layer<<<dim3(16, 8), 128>>>(x, dec_Wih0, dec_Wihr, dec_Whh,
                                            dec_bih, dec_bhh, t, l);
        out_step<<<32, 128>>>(x, lin_W, lin_b, out, t);
    }
}

// round 8
// speedup vs baseline: 2.4261x; 1.4677x over previous
#include <cuda_runtime.h>
#include <cuda_bf16.h>
#include <cstdint>

// Problem constants
constexpr int NB   = 128;   // batch
constexpr int NT   = 128;   // encoder time steps
constexpr int NIN  = 3;     // input features
constexpr int NH   = 512;   // hidden
constexpr int NTGT = 32;    // decoder steps

constexpr int ENC_CTAS = 128;   // persistent grid, 1 CTA/SM co-resident
constexpr int DEC_CTAS = 128;

// ---------------- encoder smem layout (proven R7) ----------------
constexpr int EHS      = 520;                   // bf16 row stride (elements)
constexpr int TILE_B   = 32 * EHS * 2;          // 33280 B per bf16 tile
constexpr int OFF_WHI  = 0;
constexpr int OFF_WLO  = OFF_WHI + TILE_B;
constexpr int OFF_HHI  = OFF_WLO + TILE_B;
constexpr int OFF_HLO  = OFF_HHI + TILE_B;
constexpr int OFF_STG  = OFF_HLO + TILE_B;
constexpr int STG_STRIDE = 36;
constexpr int ENC_SMEM = OFF_STG + 32 * STG_STRIDE * 4;   // 137728 B

// ---------------- decoder smem layout ----------------
// K up to 1024 (recurrent 0..511 | input 512..1023). Row stride 1032 bf16
// (2064 B = 129 x 16B -> ldmatrix conflict-free, 4-bank shift per row).
constexpr int DEHS     = 1032;
constexpr int DW_TILE  = 32 * DEHS * 2;         // 66048 B (one W tile, hi or lo)
constexpr int DH_TILE  = 16 * DEHS * 2;         // 33024 B (one h tile)
constexpr int OFF_DWHI = 0;
constexpr int OFF_DWLO = OFF_DWHI + DW_TILE;
constexpr int OFF_DHHI = OFF_DWLO + DW_TILE;    // 132096
constexpr int OFF_DHLO = OFF_DHHI + DH_TILE;    // 165120
constexpr int OFF_DSTG = OFF_DHLO + DH_TILE;    // 198144  [16][36] f32
constexpr int OFF_DPRT = OFF_DSTG + 16 * 36 * 4; // 200448 [4][16][36] f32
constexpr int DEC_SMEM = OFF_DPRT + 4 * 16 * 36 * 4;      // 209664 B

constexpr int WMAT     = NH * NH;               // 262144
constexpr int WIHR_OFF = 4 * WMAT;              // Wihr base in g_dW*

// ---------------------------------------------------------------------------
// Static device scratch
// ---------------------------------------------------------------------------
__device__ float g_l0[NT * NB * (2 * NH)];          // L0 concat outputs [t][b][1024]
__device__ float g_xs1[2 * NT * NB * NH];           // L1 input terms [d][t][b][512]
__device__ __nv_bfloat16 g_hhi[2][2 * NB * NH];     // encoder h ping-pong, bf16 hi
__device__ __nv_bfloat16 g_hlo[2][2 * NB * NH];     // encoder h ping-pong, bf16 lo
__device__ __nv_bfloat16 g_dWhi[7 * WMAT];          // decoder weights bf16 hi (Whh[4]|Wihr[3])
__device__ __nv_bfloat16 g_dWlo[7 * WMAT];          // decoder weights bf16 lo
__device__ __nv_bfloat16 g_dhhi[2][4 * NB * NH];    // decoder h ping-pong, bf16 hi
__device__ __nv_bfloat16 g_dhlo[2][4 * NB * NH];    // decoder h ping-pong, bf16 lo
__device__ float g_h3[2][NB * NH];                  // decoder layer-3 h fp32 (for out dot)
__device__ unsigned g_cnt;                          // barrier arrival counter
__device__ unsigned g_gen;                          // barrier generation (monotonic)

// ---------------------------------------------------------------------------
// Generation-based grid barrier (self-resetting, replay-safe).
// ---------------------------------------------------------------------------
__device__ __forceinline__ void grid_barrier(unsigned nctas)
{
    __threadfence();
    __syncthreads();
    if (threadIdx.x == 0) {
        volatile unsigned* genp = &g_gen;
        unsigned gen = *genp;
        if (atomicAdd(&g_cnt, 1u) == nctas - 1) {
            g_cnt = 0;
            __threadfence();
            *genp = gen + 1;
        } else {
            while (*genp == gen) { }
            __threadfence();
        }
    }
    __syncthreads();
}

// ---------------------------------------------------------------------------
// mma.sync helpers
// ---------------------------------------------------------------------------
__device__ __forceinline__ uint32_t s2u(const void* p)
{
    return (uint32_t)__cvta_generic_to_shared(p);
}

#define LDSM_X4(r0, r1, r2, r3, addr)                                          \
    asm volatile("ldmatrix.sync.aligned.m8n8.x4.shared.b16 {%0,%1,%2,%3}, [%4];" \
                 : "=r"(r0), "=r"(r1), "=r"(r2), "=r"(r3) : "r"(addr))

#define LDSM_X2(r0, r1, addr)                                                  \
    asm volatile("ldmatrix.sync.aligned.m8n8.x2.shared.b16 {%0,%1}, [%2];"     \
                 : "=r"(r0), "=r"(r1) : "r"(addr))

#define MMA_BF16(c0, c1, c2, c3, a0, a1, a2, a3, b0, b1)                       \
    asm volatile("mma.sync.aligned.m16n8k16.row.col.f32.bf16.bf16.f32 "        \
                 "{%0,%1,%2,%3}, {%4,%5,%6,%7}, {%8,%9}, {%0,%1,%2,%3};"       \
                 : "+f"(c0), "+f"(c1), "+f"(c2), "+f"(c3)                      \
                 : "r"(a0), "r"(a1), "r"(a2), "r"(a3), "r"(b0), "r"(b1))

__device__ __forceinline__ void split_bf16(float v, __nv_bfloat16& hi, __nv_bfloat16& lo)
{
    hi = __float2bfloat16(v);
    lo = __float2bfloat16(v - __bfloat162float(hi));
}

// ---------------------------------------------------------------------------
// Persistent encoder layer via tensor cores (bf16 hi/lo, 3 MMA passes). R7.
// ---------------------------------------------------------------------------
__global__ void __launch_bounds__(256) enc_mma(
    const float* __restrict__ x, const float* __restrict__ Wih0,
    const float* __restrict__ Whh_all, const float* __restrict__ bih,
    const float* __restrict__ bhh, int layer)
{
    extern __shared__ char sm[];
    __nv_bfloat16* sWhi = (__nv_bfloat16*)(sm + OFF_WHI);
    __nv_bfloat16* sWlo = (__nv_bfloat16*)(sm + OFF_WLO);
    __nv_bfloat16* sHhi = (__nv_bfloat16*)(sm + OFF_HHI);
    __nv_bfloat16* sHlo = (__nv_bfloat16*)(sm + OFF_HLO);
    float*         sStg = (float*)(sm + OFF_STG);

    const int blk = blockIdx.x;
    const int d   = blk >> 6;
    const int bt  = (blk >> 4) & 3;
    const int jt  = blk & 15;
    const int b0  = bt * 32;
    const int j0  = jt * 32;
    const int tid = threadIdx.x;
    const int lane = tid & 31;
    const int warp = tid >> 5;
    const int mj   = warp & 1;
    const int nb   = warp >> 1;

    const float* Whh = Whh_all + d * NH * NH;

    {
        const int r  = tid >> 3;
        const int c0 = (tid & 7) * 4;
        for (int k0 = 0; k0 < NH; k0 += 32) {
            float4 w = __ldg((const float4*)&Whh[(j0 + r) * NH + k0 + c0]);
            const int o = r * EHS + k0 + c0;
            split_bf16(w.x, sWhi[o + 0], sWlo[o + 0]);
            split_bf16(w.y, sWhi[o + 1], sWlo[o + 1]);
            split_bf16(w.z, sWhi[o + 2], sWlo[o + 2]);
            split_bf16(w.w, sWhi[o + 3], sWlo[o + 3]);
        }
    }

    const int ag = lane >> 3, ar = lane & 7;
    const uint32_t aRowOff = (uint32_t)((mj * 16 + (ag & 1) * 8 + ar) * EHS + (ag >> 1) * 8) * 2;
    const uint32_t aHiBase = s2u(sWhi) + aRowOff;
    const uint32_t aLoBase = s2u(sWlo) + aRowOff;
    const int bg = (lane & 15) >> 3, br = lane & 7;
    const uint32_t bRowOff = (uint32_t)((nb * 8 + br) * EHS + bg * 8) * 2;
    const uint32_t bHiBase = s2u(sHhi) + bRowOff;
    const uint32_t bLoBase = s2u(sHlo) + bRowOff;

    const int sr = tid >> 3;
    const int sj = (tid & 7) * 4;
    float bias[4], wi[12];
    if (layer == 0) {
#pragma unroll
        for (int i = 0; i < 4; i++)
            bias[i] = bih[d * NH + j0 + sj + i] + bhh[d * NH + j0 + sj + i];
        const float* wp = Wih0 + (d * NH + j0 + sj) * NIN;
#pragma unroll
        for (int i = 0; i < 12; i++) wi[i] = wp[i];
    }

    const int jl = mj * 16 + (lane >> 2);
    const int bl = nb * 8 + (lane & 3) * 2;

    __syncthreads();

    for (int t = 0; t < NT; t++) {
        const int td = d ? (NT - 1 - t) : t;

        if (t > 0) {
            const int p = t & 1;
            const __nv_bfloat16* srcHi = g_hhi[p] + (d * NB + b0) * NH;
            const __nv_bfloat16* srcLo = g_hlo[p] + (d * NB + b0) * NH;
            const int r  = tid >> 3;
            const int cc = tid & 7;
#pragma unroll
            for (int it = 0; it < 8; it++) {
                const int c16 = cc + it * 8;
                uint4 vh = __ldcg((const uint4*)(srcHi + r * NH) + c16);
                uint4 vl = __ldcg((const uint4*)(srcLo + r * NH) + c16);
                *(uint4*)((char*)sHhi + r * (EHS * 2) + c16 * 16) = vh;
                *(uint4*)((char*)sHlo + r * (EHS * 2) + c16 * 16) = vl;
            }
        }
        if (layer == 0) {
            const float* xr = x + ((b0 + sr) * NT + td) * NIN;
            const float x0 = xr[0], x1 = xr[1], x2 = xr[2];
            float4 v;
            v.x = bias[0] + x0 * wi[0] + x1 * wi[1]  + x2 * wi[2];
            v.y = bias[1] + x0 * wi[3] + x1 * wi[4]  + x2 * wi[5];
            v.z = bias[2] + x0 * wi[6] + x1 * wi[7]  + x2 * wi[8];
            v.w = bias[3] + x0 * wi[9] + x1 * wi[10] + x2 * wi[11];
            *(float4*)&sStg[sr * STG_STRIDE + sj] = v;
        } else {
            float4 v = __ldg((const float4*)&g_xs1[((d * NT + td) * NB + b0 + sr) * NH + j0 + sj]);
            *(float4*)&sStg[sr * STG_STRIDE + sj] = v;
        }
        __syncthreads();

        float c0 = 0.f, c1 = 0.f, c2 = 0.f, c3 = 0.f;
        if (t > 0) {
            uint32_t aHi = aHiBase, aLo = aLoBase, bHi = bHiBase, bLo = bLoBase;
#pragma unroll 4
            for (int kk = 0; kk < 32; kk++) {
                uint32_t a0, a1, a2, a3, e0, e1, e2, e3, r0, r1, f0, f1;
                LDSM_X4(a0, a1, a2, a3, aHi);
                LDSM_X4(e0, e1, e2, e3, aLo);
                LDSM_X2(r0, r1, bHi);
                LDSM_X2(f0, f1, bLo);
                MMA_BF16(c0, c1, c2, c3, a0, a1, a2, a3, r0, r1);
                MMA_BF16(c0, c1, c2, c3, a0, a1, a2, a3, f0, f1);
                MMA_BF16(c0, c1, c2, c3, e0, e1, e2, e3, r0, r1);
                aHi += 32; aLo += 32; bHi += 32; bLo += 32;
            }
        }

        {
            float i0 = sStg[(bl + 0) * STG_STRIDE + jl];
            float i1 = sStg[(bl + 1) * STG_STRIDE + jl];
            float i2 = sStg[(bl + 0) * STG_STRIDE + jl + 8];
            float i3 = sStg[(bl + 1) * STG_STRIDE + jl + 8];
            sStg[(bl + 0) * STG_STRIDE + jl]     = tanhf(c0 + i0);
            sStg[(bl + 1) * STG_STRIDE + jl]     = tanhf(c1 + i1);
            sStg[(bl + 0) * STG_STRIDE + jl + 8] = tanhf(c2 + i2);
            sStg[(bl + 1) * STG_STRIDE + jl + 8] = tanhf(c3 + i3);
        }
        __syncthreads();

        {
            float4 v = *(const float4*)&sStg[sr * STG_STRIDE + sj];
            __nv_bfloat16 h0, h1, h2, h3, l0b, l1b, l2b, l3b;
            split_bf16(v.x, h0, l0b); split_bf16(v.y, h1, l1b);
            split_bf16(v.z, h2, l2b); split_bf16(v.w, h3, l3b);
            const int p1 = (t + 1) & 1;
            const int gidx = (d * NB + b0 + sr) * NH + j0 + sj;
            uint2 phi, plo;
            phi.x = (uint32_t)__bfloat16_as_ushort(h0) | ((uint32_t)__bfloat16_as_ushort(h1) << 16);
            phi.y = (uint32_t)__bfloat16_as_ushort(h2) | ((uint32_t)__bfloat16_as_ushort(h3) << 16);
            plo.x = (uint32_t)__bfloat16_as_ushort(l0b) | ((uint32_t)__bfloat16_as_ushort(l1b) << 16);
            plo.y = (uint32_t)__bfloat16_as_ushort(l2b) | ((uint32_t)__bfloat16_as_ushort(l3b) << 16);
            *(uint2*)(g_hhi[p1] + gidx) = phi;
            *(uint2*)(g_hlo[p1] + gidx) = plo;
            if (layer == 0)
                *(float4*)&g_l0[(td * NB + b0 + sr) * (2 * NH) + d * NH + j0 + sj] = v;
            if (t == NT - 1) {
                // hand initial decoder state to dec_persist (bf16 hi/lo)
                const int slot = (layer ? 2 : 0) + d;
                const int di = (slot * NB + b0 + sr) * NH + j0 + sj;
                *(uint2*)(g_dhhi[0] + di) = phi;
                *(uint2*)(g_dhlo[0] + di) = plo;
            }
        }

        if (t < NT - 1)
            grid_barrier(ENC_CTAS);
    }
}

// ---------------------------------------------------------------------------
// Big GEMM: xs1 (unchanged, fp32)
// ---------------------------------------------------------------------------
__global__ void __launch_bounds__(256) xs1_gemm(
    const float* __restrict__ Wih1, const float* __restrict__ bih,
    const float* __restrict__ bhh)
{
    __shared__ __align__(16) float sh_a[64][36];
    __shared__ __align__(16) float sh_w[32][68];

    const int d  = blockIdx.z;
    const int j0 = blockIdx.x * 64;
    const int m0 = blockIdx.y * 64;
    const int tx = threadIdx.x & 15;
    const int ty = threadIdx.x >> 4;
    const int lr = threadIdx.x >> 3;
    const int lk = (threadIdx.x & 7) * 4;

    const float* Wd = Wih1 + d * NH * (2 * NH);
    float acc[4][4] = {};

    for (int k0 = 0; k0 < 2 * NH; k0 += 32) {
        *(float4*)&sh_a[lr][lk]      = *(const float4*)&g_l0[(m0 + lr) * (2 * NH) + k0 + lk];
        *(float4*)&sh_a[lr + 32][lk] = *(const float4*)&g_l0[(m0 + lr + 32) * (2 * NH) + k0 + lk];
        float4 w0 = *(const float4*)&Wd[(j0 + lr) * (2 * NH) + k0 + lk];
        float4 w1 = *(const float4*)&Wd[(j0 + lr + 32) * (2 * NH) + k0 + lk];
        sh_w[lk + 0][lr] = w0.x; sh_w[lk + 1][lr] = w0.y;
        sh_w[lk + 2][lr] = w0.z; sh_w[lk + 3][lr] = w0.w;
        sh_w[lk + 0][lr + 32] = w1.x; sh_w[lk + 1][lr + 32] = w1.y;
        sh_w[lk + 2][lr + 32] = w1.z; sh_w[lk + 3][lr + 32] = w1.w;
        __syncthreads();
#pragma unroll
        for (int kk = 0; kk < 32; kk++) {
            float4 wv = *(float4*)&sh_w[kk][tx * 4];
            float  v0 = sh_a[ty * 4 + 0][kk];
            float  v1 = sh_a[ty * 4 + 1][kk];
            float  v2 = sh_a[ty * 4 + 2][kk];
            float  v3 = sh_a[ty * 4 + 3][kk];
            acc[0][0] += v0 * wv.x; acc[0][1] += v0 * wv.y; acc[0][2] += v0 * wv.z; acc[0][3] += v0 * wv.w;
            acc[1][0] += v1 * wv.x; acc[1][1] += v1 * wv.y; acc[1][2] += v1 * wv.z; acc[1][3] += v1 * wv.w;
            acc[2][0] += v2 * wv.x; acc[2][1] += v2 * wv.y; acc[2][2] += v2 * wv.z; acc[2][3] += v2 * wv.w;
            acc[3][0] += v3 * wv.x; acc[3][1] += v3 * wv.y; acc[3][2] += v3 * wv.z; acc[3][3] += v3 * wv.w;
        }
        __syncthreads();
    }

    const int jj = j0 + tx * 4;
    const float b0v = bih[(2 + d) * NH + jj + 0] + bhh[(2 + d) * NH + jj + 0];
    const float b1v = bih[(2 + d) * NH + jj + 1] + bhh[(2 + d) * NH + jj + 1];
    const float b2v = bih[(2 + d) * NH + jj + 2] + bhh[(2 + d) * NH + jj + 2];
    const float b3v = bih[(2 + d) * NH + jj + 3] + bhh[(2 + d) * NH + jj + 3];
#pragma unroll
    for (int i = 0; i < 4; i++) {
        const int m = m0 + ty * 4 + i;
        float4 r = make_float4(acc[i][0] + b0v, acc[i][1] + b1v,
                               acc[i][2] + b2v, acc[i][3] + b3v);
        *(float4*)&g_xs1[(d * NT * NB + m) * NH + jj] = r;
    }
}

// ---------------------------------------------------------------------------
// Persistent decoder via tensor cores.
// 128 CTAs = (16 jt x 8 bt), 256 threads, out tile 32j x 16b per phase.
// Warps: mj = warp&1 (j half), kw = warp>>1 (K quarter of 256).
// Per layer phase: stage W (recurrent | input concat along K) + h tiles as
// bf16 hi/lo, one sync, ldmatrix+mma 3-pass, partials into sPart[kw],
// owner reduce + tanh + bf16 split store. Grid barrier per phase.
// Output dot + feedback folded at the top of each step.
// ---------------------------------------------------------------------------
__global__ void __launch_bounds__(256) dec_persist(
    const float* __restrict__ x,    const float* __restrict__ Wih0,
    const float* __restrict__ Wihr, const float* __restrict__ Whh,
    const float* __restrict__ bih,  const float* __restrict__ bhh,
    const float* __restrict__ linW, const float* __restrict__ linb,
    float* __restrict__ out)
{
    extern __shared__ char sm[];
    __nv_bfloat16* sWhi = (__nv_bfloat16*)(sm + OFF_DWHI);
    __nv_bfloat16* sWlo = (__nv_bfloat16*)(sm + OFF_DWLO);
    __nv_bfloat16* sHhi = (__nv_bfloat16*)(sm + OFF_DHHI);
    __nv_bfloat16* sHlo = (__nv_bfloat16*)(sm + OFF_DHLO);
    float*         sStg = (float*)(sm + OFF_DSTG);          // [16][36]
    float*         sPrt = (float*)(sm + OFF_DPRT);          // [4][16][36]

    __shared__ float s_dec[16][3];
    __shared__ float s_o0[16];

    const int jt = blockIdx.x & 15;
    const int bt = blockIdx.x >> 4;
    const int j0 = jt * 32;
    const int b0 = bt * 16;
    const int tid  = threadIdx.x;
    const int lane = tid & 31;
    const int warp = tid >> 5;
    const int mj   = warp & 1;          // j half (16 rows)
    const int kw   = warp >> 1;         // K quarter (256)

    // ---- one-time: convert decoder weights to bf16 hi/lo (grid-strided) ----
    {
        const int stride4 = DEC_CTAS * 256 * 4;
        const int g4 = (blockIdx.x * 256 + tid) * 4;
        for (int i = g4; i < 4 * WMAT; i += stride4) {
            float4 w = *(const float4*)&Whh[i];
            split_bf16(w.x, g_dWhi[i + 0], g_dWlo[i + 0]);
            split_bf16(w.y, g_dWhi[i + 1], g_dWlo[i + 1]);
            split_bf16(w.z, g_dWhi[i + 2], g_dWlo[i + 2]);
            split_bf16(w.w, g_dWhi[i + 3], g_dWlo[i + 3]);
        }
        for (int i = g4; i < 3 * WMAT; i += stride4) {
            float4 w = *(const float4*)&Wihr[i];
            split_bf16(w.x, g_dWhi[WIHR_OFF + i + 0], g_dWlo[WIHR_OFF + i + 0]);
            split_bf16(w.y, g_dWhi[WIHR_OFF + i + 1], g_dWlo[WIHR_OFF + i + 1]);
            split_bf16(w.z, g_dWhi[WIHR_OFF + i + 2], g_dWlo[WIHR_OFF + i + 2]);
            split_bf16(w.w, g_dWhi[WIHR_OFF + i + 3], g_dWlo[WIHR_OFF + i + 3]);
        }
    }
    // initial decin = x[:, -1, :]
    if (tid < 16) {
        const float* xr = x + ((b0 + tid) * NT + (NT - 1)) * NIN;
        s_dec[tid][0] = xr[0];
        s_dec[tid][1] = xr[1];
        s_dec[tid][2] = xr[2];
    }
    grid_barrier(DEC_CTAS);   // weights converted + s_dec visible (has syncthreads)

    // ---- ldmatrix base addresses (per-warp constants) ----
    const int ag = lane >> 3, ar = lane & 7;
    const uint32_t aOff = (uint32_t)((mj * 16 + (ag & 1) * 8 + ar) * DEHS
                                     + (ag >> 1) * 8 + kw * 256) * 2;
    const uint32_t aHiBase = s2u(sWhi) + aOff;
    const uint32_t aLoBase = s2u(sWlo) + aOff;
    // B: x4 = two n8 tiles x two k-halves. lane>>4 = n-tile, (lane&15)>>3 = k-half.
    const uint32_t bOff = (uint32_t)(((lane >> 4) * 8 + (lane & 7)) * DEHS
                                     + ((lane >> 3) & 1) * 8 + kw * 256) * 2;
    const uint32_t bHiBase = s2u(sHhi) + bOff;
    const uint32_t bLoBase = s2u(sHlo) + bOff;

    const int sr = tid >> 4;            // owner: batch row 0..15
    const int sj = (tid & 15) * 2;      // owner: j pair
    const int jl = mj * 16 + (lane >> 2);   // c-frag j row
    const int bl = (lane & 3) * 2;          // c-frag b col (ntile adds 8)

    for (int t = 0; t < NTGT; t++) {
        const int p = t & 1;

        // ---- output dot of step t-1 + feedback ----
        if (t > 0) {
            const float* h3 = g_h3[p];
#pragma unroll
            for (int rr = 0; rr < 2; rr++) {
                const int brow = warp * 2 + rr;
                const float* row = h3 + (b0 + brow) * NH;
                float s = 0.f;
#pragma unroll
                for (int i = lane; i < NH; i += 32)
                    s += __ldcg(&row[i]) * linW[i];
#pragma unroll
                for (int o = 16; o; o >>= 1) s += __shfl_xor_sync(0xffffffffu, s, o);
                if (lane == 0) s_o0[brow] = s;
            }
            __syncthreads();
            if (tid < 16) {
                float o0 = s_o0[tid] + linb[0];
                if (jt == 0) out[(b0 + tid) * NTGT + (t - 1)] = o0;
                float s1 = s_dec[tid][0] - o0;
                float s2 = s_dec[tid][1] - s1;
                s_dec[tid][0] = o0;
                s_dec[tid][1] = s1;
                s_dec[tid][2] = s2;
            }
            __syncthreads();
        }

        for (int l = 0; l < 4; l++) {
            const int nk = (l == 0) ? 2 : 4;   // active K quarters

            // ---- stage W tiles (bf16, pre-converted) ----
            {
                const int r  = tid >> 3;        // 0..31 (j row)
                const int c8 = tid & 7;
                const __nv_bfloat16* shi = g_dWhi + l * WMAT + (j0 + r) * NH;
                const __nv_bfloat16* slo = g_dWlo + l * WMAT + (j0 + r) * NH;
#pragma unroll
                for (int c = c8; c < 64; c += 8) {
                    *(uint4*)(sWhi + r * DEHS + c * 8) = __ldg((const uint4*)(shi + c * 8));
                    *(uint4*)(sWlo + r * DEHS + c * 8) = __ldg((const uint4*)(slo + c * 8));
                }
                if (l > 0) {
                    const __nv_bfloat16* shi2 = g_dWhi + WIHR_OFF + (l - 1) * WMAT + (j0 + r) * NH;
                    const __nv_bfloat16* slo2 = g_dWlo + WIHR_OFF + (l - 1) * WMAT + (j0 + r) * NH;
#pragma unroll
                    for (int c = c8; c < 64; c += 8) {
                        *(uint4*)(sWhi + r * DEHS + 512 + c * 8) = __ldg((const uint4*)(shi2 + c * 8));
                        *(uint4*)(sWlo + r * DEHS + 512 + c * 8) = __ldg((const uint4*)(slo2 + c * 8));
                    }
                }
            }
            // ---- stage h tiles (bf16 hi/lo from ping-pong) ----
            {
                const int r   = tid >> 4;       // 0..15 (b row)
                const int c16 = tid & 15;
                const __nv_bfloat16* rhi = g_dhhi[p] + (l * NB + b0 + r) * NH;
                const __nv_bfloat16* rlo = g_dhlo[p] + (l * NB + b0 + r) * NH;
#pragma unroll
                for (int c = c16; c < 64; c += 16) {
                    *(uint4*)(sHhi + r * DEHS + c * 8) = __ldcg((const uint4*)(rhi + c * 8));
                    *(uint4*)(sHlo + r * DEHS + c * 8) = __ldcg((const uint4*)(rlo + c * 8));
                }
                if (l > 0) {
                    const __nv_bfloat16* ihi = g_dhhi[1 - p] + ((l - 1) * NB + b0 + r) * NH;
                    const __nv_bfloat16* ilo = g_dhlo[1 - p] + ((l - 1) * NB + b0 + r) * NH;
#pragma unroll
                    for (int c = c16; c < 64; c += 16) {
                        *(uint4*)(sHhi + r * DEHS + 512 + c * 8) = __ldcg((const uint4*)(ihi + c * 8));
                        *(uint4*)(sHlo + r * DEHS + 512 + c * 8) = __ldcg((const uint4*)(ilo + c * 8));
                    }
                }
            }
            // ---- stage init: bias (+ Wih0 . decin for layer 0) ----
            {
                float v0 = bih[l * NH + j0 + sj + 0] + bhh[l * NH + j0 + sj + 0];
                float v1 = bih[l * NH + j0 + sj + 1] + bhh[l * NH + j0 + sj + 1];
                if (l == 0) {
                    const float i0 = s_dec[sr][0], i1 = s_dec[sr][1], i2 = s_dec[sr][2];
                    const float* wp = Wih0 + (j0 + sj) * NIN;
                    v0 += i0 * wp[0] + i1 * wp[1] + i2 * wp[2];
                    v1 += i0 * wp[3] + i1 * wp[4] + i2 * wp[5];
                }
                sStg[sr * 36 + sj + 0] = v0;
                sStg[sr * 36 + sj + 1] = v1;
            }
            __syncthreads();

            // ---- tensor-core GEMM over this warp's K quarter ----
            if (kw < nk) {
                float c00 = 0.f, c01 = 0.f, c02 = 0.f, c03 = 0.f;
                float c10 = 0.f, c11 = 0.f, c12 = 0.f, c13 = 0.f;
                uint32_t aHi = aHiBase, aLo = aLoBase, bHi = bHiBase, bLo = bLoBase;
#pragma unroll 4
                for (int kk = 0; kk < 16; kk++) {
                    uint32_t a0, a1, a2, a3, e0, e1, e2, e3;
                    uint32_t r0, r1, r2, r3, f0, f1, f2, f3;
                    LDSM_X4(a0, a1, a2, a3, aHi);
                    LDSM_X4(e0, e1, e2, e3, aLo);
                    LDSM_X4(r0, r1, r2, r3, bHi);
                    LDSM_X4(f0, f1, f2, f3, bLo);
                    MMA_BF16(c00, c01, c02, c03, a0, a1, a2, a3, r0, r1);
                    MMA_BF16(c00, c01, c02, c03, a0, a1, a2, a3, f0, f1);
                    MMA_BF16(c00, c01, c02, c03, e0, e1, e2, e3, r0, r1);
                    MMA_BF16(c10, c11, c12, c13, a0, a1, a2, a3, r2, r3);
                    MMA_BF16(c10, c11, c12, c13, a0, a1, a2, a3, f2, f3);
                    MMA_BF16(c10, c11, c12, c13, e0, e1, e2, e3, r2, r3);
                    aHi += 32; aLo += 32; bHi += 32; bLo += 32;
                }
                float* pp = sPrt + kw * (16 * 36);
                pp[(bl + 0) * 36 + jl]     = c00;
                pp[(bl + 1) * 36 + jl]     = c01;
                pp[(bl + 0) * 36 + jl + 8] = c02;
                pp[(bl + 1) * 36 + jl + 8] = c03;
                pp[(bl + 8) * 36 + jl]     = c10;
                pp[(bl + 9) * 36 + jl]     = c11;
                pp[(bl + 8) * 36 + jl + 8] = c12;
                pp[(bl + 9) * 36 + jl + 8] = c13;
            }
            __syncthreads();

            // ---- owner reduce + tanh + split store ----
            {
                float v0 = sStg[sr * 36 + sj + 0];
                float v1 = sStg[sr * 36 + sj + 1];
#pragma unroll
                for (int q = 0; q < 4; q++) {
                    if (q < nk) {
                        v0 += sPrt[q * 576 + sr * 36 + sj + 0];
                        v1 += sPrt[q * 576 + sr * 36 + sj + 1];
                    }
                }
                v0 = tanhf(v0); v1 = tanhf(v1);
                __nv_bfloat16 h0, h1, l0b, l1b;
                split_bf16(v0, h0, l0b);
                split_bf16(v1, h1, l1b);
                const int idx = (l * NB + b0 + sr) * NH + j0 + sj;
                uint32_t phi = (uint32_t)__bfloat16_as_ushort(h0) |
                               ((uint32_t)__bfloat16_as_ushort(h1) << 16);
                uint32_t plo = (uint32_t)__bfloat16_as_ushort(l0b) |
                               ((uint32_t)__bfloat16_as_ushort(l1b) << 16);
                *(uint32_t*)(g_dhhi[1 - p] + idx) = phi;
                *(uint32_t*)(g_dhlo[1 - p] + idx) = plo;
                if (l == 3)
                    *(float2*)&g_h3[1 - p][(b0 + sr) * NH + j0 + sj] = make_float2(v0, v1);
            }

            grid_barrier(DEC_CTAS);
        }
    }

    // ---- final output (t = NTGT-1): h3 lives in g_h3[NTGT & 1] = [0] ----
    {
        const float* h3 = g_h3[NTGT & 1];
#pragma unroll
        for (int rr = 0; rr < 2; rr++) {
            const int brow = warp * 2 + rr;
            const float* row = h3 + (b0 + brow) * NH;
            float s = 0.f;
#pragma unroll
            for (int i = lane; i < NH; i += 32)
                s += __ldcg(&row[i]) * linW[i];
#pragma unroll
            for (int o = 16; o; o >>= 1) s += __shfl_xor_sync(0xffffffffu, s, o);
            if (lane == 0) s_o0[brow] = s;
        }
        __syncthreads();
        if (tid < 16 && jt == 0)
            out[(b0 + tid) * NTGT + (NTGT - 1)] = s_o0[tid] + linb[0];
    }
}

// ---------------------------------------------------------------------------
// Launch sequence (graph-capturable: kernel launches only)
// ---------------------------------------------------------------------------
extern "C" void kernel_launch(void* const* d_in, const int* in_sizes, int n_in,
                              void* d_out, int out_size)
{
    const float* x        = (const float*)d_in[0];
    const float* enc_Wih0 = (const float*)d_in[2];
    const float* enc_Whh0 = (const float*)d_in[3];
    const float* enc_Wih1 = (const float*)d_in[4];
    const float* enc_Whh1 = (const float*)d_in[5];
    const float* enc_bih  = (const float*)d_in[6];
    const float* enc_bhh  = (const float*)d_in[7];
    const float* dec_Wih0 = (const float*)d_in[8];
    const float* dec_Wihr = (const float*)d_in[9];
    const float* dec_Whh  = (const float*)d_in[10];
    const float* dec_bih  = (const float*)d_in[11];
    const float* dec_bhh  = (const float*)d_in[12];
    const float* lin_W    = (const float*)d_in[13];
    const float* lin_b    = (const float*)d_in[14];
    float* out = (float*)d_out;

    cudaFuncSetAttribute(enc_mma, cudaFuncAttributeMaxDynamicSharedMemorySize,
                         ENC_SMEM);
    cudaFuncSetAttribute(dec_persist, cudaFuncAttributeMaxDynamicSharedMemorySize,
                         DEC_SMEM);

    // Encoder layer 0: persistent, tensor-core steps
    enc_mma<<<ENC_CTAS, 256, ENC_SMEM>>>(x, enc_Wih0, enc_Whh0,
                                         enc_bih, enc_bhh, 0);

    // Layer-1 input terms for all t (both dirs), biases folded in
    xs1_gemm<<<dim3(8, 256, 2), 256>>>(enc_Wih1, enc_bih, enc_bhh);

    // Encoder layer 1: persistent, tensor-core steps
    enc_mma<<<ENC_CTAS, 256, ENC_SMEM>>>(x, enc_Wih0, enc_Whh1,
                                         enc_bih, enc_bhh, 1);

    // Decoder: persistent, tensor-core phases
    dec_persist<<<DEC_CTAS, 256, DEC_SMEM>>>(x, dec_Wih0, dec_Wihr, dec_Whh,
                                             dec_bih, dec_bhh, lin_W, lin_b, out);
}

// round 9
// speedup vs baseline: 3.0969x; 1.2765x over previous
#include <cuda_runtime.h>
#include <cuda_bf16.h>
#include <cstdint>

// Problem constants
constexpr int NB   = 128;   // batch
constexpr int NT   = 128;   // encoder time steps
constexpr int NIN  = 3;     // input features
constexpr int NH   = 512;   // hidden
constexpr int NTGT = 32;    // decoder steps

constexpr int ENC_CTAS = 128;
constexpr int DEC_CTAS = 128;

// ---------------- encoder smem layout (proven R7) ----------------
constexpr int EHS      = 520;
constexpr int TILE_B   = 32 * EHS * 2;
constexpr int OFF_WHI  = 0;
constexpr int OFF_WLO  = OFF_WHI + TILE_B;
constexpr int OFF_HHI  = OFF_WLO + TILE_B;
constexpr int OFF_HLO  = OFF_HHI + TILE_B;
constexpr int OFF_STG  = OFF_HLO + TILE_B;
constexpr int STG_STRIDE = 36;
constexpr int ENC_SMEM = OFF_STG + 32 * STG_STRIDE * 4;

// ---------------- decoder smem layout (proven R8) ----------------
constexpr int DEHS     = 1032;
constexpr int DW_TILE  = 32 * DEHS * 2;
constexpr int DH_TILE  = 16 * DEHS * 2;
constexpr int OFF_DWHI = 0;
constexpr int OFF_DWLO = OFF_DWHI + DW_TILE;
constexpr int OFF_DHHI = OFF_DWLO + DW_TILE;
constexpr int OFF_DHLO = OFF_DHHI + DH_TILE;
constexpr int OFF_DSTG = OFF_DHLO + DH_TILE;
constexpr int OFF_DPRT = OFF_DSTG + 16 * 36 * 4;
constexpr int DEC_SMEM = OFF_DPRT + 4 * 16 * 36 * 4;

constexpr int WMAT     = NH * NH;
constexpr int WIHR_OFF = 4 * WMAT;

// ---------------- xs1 mma smem layout ----------------
constexpr int XAS    = 72;                       // bf16 row stride (144 B)
constexpr int X_SA   = 128 * XAS * 2;            // 18432 B per A buffer
constexpr int X_SB   = 64 * XAS * 2;             // 9216 B per B buffer
constexpr int XS1_SMEM = 2 * X_SA + 2 * X_SB;    // 55296 B

// ---------------------------------------------------------------------------
// Static device scratch
// ---------------------------------------------------------------------------
__device__ __nv_bfloat16 g_l0hi[NT * NB * (2 * NH)];   // L0 outputs bf16 hi
__device__ __nv_bfloat16 g_l0lo[NT * NB * (2 * NH)];   // L0 outputs bf16 lo
__device__ __nv_bfloat16 g_xWhi[2 * NH * (2 * NH)];    // Wih1 bf16 hi
__device__ __nv_bfloat16 g_xWlo[2 * NH * (2 * NH)];    // Wih1 bf16 lo
__device__ float g_xs1[2 * NT * NB * NH];              // L1 input terms fp32
__device__ __nv_bfloat16 g_hhi[2][2 * NB * NH];
__device__ __nv_bfloat16 g_hlo[2][2 * NB * NH];
__device__ __nv_bfloat16 g_dWhi[7 * WMAT];
__device__ __nv_bfloat16 g_dWlo[7 * WMAT];
__device__ __nv_bfloat16 g_dhhi[2][4 * NB * NH];
__device__ __nv_bfloat16 g_dhlo[2][4 * NB * NH];
__device__ float g_h3[2][NB * NH];
__device__ unsigned g_cnt;                   // full-grid barrier
__device__ unsigned g_gen;
__device__ unsigned g_gcnt[16 * 32];         // group barriers (padded 128 B)
__device__ unsigned g_ggen[16 * 32];

// ---------------------------------------------------------------------------
// Barriers (generation-based, self-resetting, replay-safe)
// ---------------------------------------------------------------------------
__device__ __forceinline__ void grid_barrier(unsigned nctas)
{
    __threadfence();
    __syncthreads();
    if (threadIdx.x == 0) {
        volatile unsigned* genp = &g_gen;
        unsigned gen = *genp;
        if (atomicAdd(&g_cnt, 1u) == nctas - 1) {
            g_cnt = 0;
            __threadfence();
            *genp = gen + 1;
        } else {
            while (*genp == gen) { }
            __threadfence();
        }
    }
    __syncthreads();
}

__device__ __forceinline__ void group_barrier(int g, unsigned n)
{
    __threadfence();
    __syncthreads();
    if (threadIdx.x == 0) {
        volatile unsigned* genp = &g_ggen[g * 32];
        unsigned gen = *genp;
        if (atomicAdd(&g_gcnt[g * 32], 1u) == n - 1) {
            g_gcnt[g * 32] = 0;
            __threadfence();
            *genp = gen + 1;
        } else {
            while (*genp == gen) { }
            __threadfence();
        }
    }
    __syncthreads();
}

// ---------------------------------------------------------------------------
// mma.sync helpers
// ---------------------------------------------------------------------------
__device__ __forceinline__ uint32_t s2u(const void* p)
{
    return (uint32_t)__cvta_generic_to_shared(p);
}

#define LDSM_X4(r0, r1, r2, r3, addr)                                          \
    asm volatile("ldmatrix.sync.aligned.m8n8.x4.shared.b16 {%0,%1,%2,%3}, [%4];" \
                 : "=r"(r0), "=r"(r1), "=r"(r2), "=r"(r3) : "r"(addr))

#define LDSM_X2(r0, r1, addr)                                                  \
    asm volatile("ldmatrix.sync.aligned.m8n8.x2.shared.b16 {%0,%1}, [%2];"     \
                 : "=r"(r0), "=r"(r1) : "r"(addr))

#define MMA_BF16(c0, c1, c2, c3, a0, a1, a2, a3, b0, b1)                       \
    asm volatile("mma.sync.aligned.m16n8k16.row.col.f32.bf16.bf16.f32 "        \
                 "{%0,%1,%2,%3}, {%4,%5,%6,%7}, {%8,%9}, {%0,%1,%2,%3};"       \
                 : "+f"(c0), "+f"(c1), "+f"(c2), "+f"(c3)                      \
                 : "r"(a0), "r"(a1), "r"(a2), "r"(a3), "r"(b0), "r"(b1))

__device__ __forceinline__ void split_bf16(float v, __nv_bfloat16& hi, __nv_bfloat16& lo)
{
    hi = __float2bfloat16(v);
    lo = __float2bfloat16(v - __bfloat162float(hi));
}

// ---------------------------------------------------------------------------
// Pre-split Wih1 into bf16 hi/lo
// ---------------------------------------------------------------------------
__global__ void __launch_bounds__(256) split_wih1(const float* __restrict__ W)
{
    const int i = (blockIdx.x * 256 + threadIdx.x) * 4;
    if (i < 2 * NH * 2 * NH) {
        float4 w = *(const float4*)&W[i];
        split_bf16(w.x, g_xWhi[i + 0], g_xWlo[i + 0]);
        split_bf16(w.y, g_xWhi[i + 1], g_xWlo[i + 1]);
        split_bf16(w.z, g_xWhi[i + 2], g_xWlo[i + 2]);
        split_bf16(w.w, g_xWhi[i + 3], g_xWlo[i + 3]);
    }
}

// ---------------------------------------------------------------------------
// Persistent encoder layer via tensor cores (R7, + group barriers, + bf16 l0)
// ---------------------------------------------------------------------------
__global__ void __launch_bounds__(256) enc_mma(
    const float* __restrict__ x, const float* __restrict__ Wih0,
    const float* __restrict__ Whh_all, const float* __restrict__ bih,
    const float* __restrict__ bhh, int layer)
{
    extern __shared__ char sm[];
    __nv_bfloat16* sWhi = (__nv_bfloat16*)(sm + OFF_WHI);
    __nv_bfloat16* sWlo = (__nv_bfloat16*)(sm + OFF_WLO);
    __nv_bfloat16* sHhi = (__nv_bfloat16*)(sm + OFF_HHI);
    __nv_bfloat16* sHlo = (__nv_bfloat16*)(sm + OFF_HLO);
    float*         sStg = (float*)(sm + OFF_STG);

    const int blk = blockIdx.x;
    const int d   = blk >> 6;
    const int bt  = (blk >> 4) & 3;
    const int jt  = blk & 15;
    const int grp = blk >> 4;          // (d, bt) group: 16 CTAs share h state
    const int b0  = bt * 32;
    const int j0  = jt * 32;
    const int tid = threadIdx.x;
    const int lane = tid & 31;
    const int warp = tid >> 5;
    const int mj   = warp & 1;
    const int nb   = warp >> 1;

    const float* Whh = Whh_all + d * NH * NH;

    {
        const int r  = tid >> 3;
        const int c0 = (tid & 7) * 4;
        for (int k0 = 0; k0 < NH; k0 += 32) {
            float4 w = __ldg((const float4*)&Whh[(j0 + r) * NH + k0 + c0]);
            const int o = r * EHS + k0 + c0;
            split_bf16(w.x, sWhi[o + 0], sWlo[o + 0]);
            split_bf16(w.y, sWhi[o + 1], sWlo[o + 1]);
            split_bf16(w.z, sWhi[o + 2], sWlo[o + 2]);
            split_bf16(w.w, sWhi[o + 3], sWlo[o + 3]);
        }
    }

    const int ag = lane >> 3, ar = lane & 7;
    const uint32_t aRowOff = (uint32_t)((mj * 16 + (ag & 1) * 8 + ar) * EHS + (ag >> 1) * 8) * 2;
    const uint32_t aHiBase = s2u(sWhi) + aRowOff;
    const uint32_t aLoBase = s2u(sWlo) + aRowOff;
    const int bg = (lane & 15) >> 3, br = lane & 7;
    const uint32_t bRowOff = (uint32_t)((nb * 8 + br) * EHS + bg * 8) * 2;
    const uint32_t bHiBase = s2u(sHhi) + bRowOff;
    const uint32_t bLoBase = s2u(sHlo) + bRowOff;

    const int sr = tid >> 3;
    const int sj = (tid & 7) * 4;
    float bias[4], wi[12];
    if (layer == 0) {
#pragma unroll
        for (int i = 0; i < 4; i++)
            bias[i] = bih[d * NH + j0 + sj + i] + bhh[d * NH + j0 + sj + i];
        const float* wp = Wih0 + (d * NH + j0 + sj) * NIN;
#pragma unroll
        for (int i = 0; i < 12; i++) wi[i] = wp[i];
    }

    const int jl = mj * 16 + (lane >> 2);
    const int bl = nb * 8 + (lane & 3) * 2;

    __syncthreads();

    for (int t = 0; t < NT; t++) {
        const int td = d ? (NT - 1 - t) : t;

        if (t > 0) {
            const int p = t & 1;
            const __nv_bfloat16* srcHi = g_hhi[p] + (d * NB + b0) * NH;
            const __nv_bfloat16* srcLo = g_hlo[p] + (d * NB + b0) * NH;
            const int r  = tid >> 3;
            const int cc = tid & 7;
#pragma unroll
            for (int it = 0; it < 8; it++) {
                const int c16 = cc + it * 8;
                uint4 vh = __ldcg((const uint4*)(srcHi + r * NH) + c16);
                uint4 vl = __ldcg((const uint4*)(srcLo + r * NH) + c16);
                *(uint4*)((char*)sHhi + r * (EHS * 2) + c16 * 16) = vh;
                *(uint4*)((char*)sHlo + r * (EHS * 2) + c16 * 16) = vl;
            }
        }
        if (layer == 0) {
            const float* xr = x + ((b0 + sr) * NT + td) * NIN;
            const float x0 = xr[0], x1 = xr[1], x2 = xr[2];
            float4 v;
            v.x = bias[0] + x0 * wi[0] + x1 * wi[1]  + x2 * wi[2];
            v.y = bias[1] + x0 * wi[3] + x1 * wi[4]  + x2 * wi[5];
            v.z = bias[2] + x0 * wi[6] + x1 * wi[7]  + x2 * wi[8];
            v.w = bias[3] + x0 * wi[9] + x1 * wi[10] + x2 * wi[11];
            *(float4*)&sStg[sr * STG_STRIDE + sj] = v;
        } else {
            float4 v = __ldg((const float4*)&g_xs1[((d * NT + td) * NB + b0 + sr) * NH + j0 + sj]);
            *(float4*)&sStg[sr * STG_STRIDE + sj] = v;
        }
        __syncthreads();

        float c0 = 0.f, c1 = 0.f, c2 = 0.f, c3 = 0.f;
        if (t > 0) {
            uint32_t aHi = aHiBase, aLo = aLoBase, bHi = bHiBase, bLo = bLoBase;
#pragma unroll 4
            for (int kk = 0; kk < 32; kk++) {
                uint32_t a0, a1, a2, a3, e0, e1, e2, e3, r0, r1, f0, f1;
                LDSM_X4(a0, a1, a2, a3, aHi);
                LDSM_X4(e0, e1, e2, e3, aLo);
                LDSM_X2(r0, r1, bHi);
                LDSM_X2(f0, f1, bLo);
                MMA_BF16(c0, c1, c2, c3, a0, a1, a2, a3, r0, r1);
                MMA_BF16(c0, c1, c2, c3, a0, a1, a2, a3, f0, f1);
                MMA_BF16(c0, c1, c2, c3, e0, e1, e2, e3, r0, r1);
                aHi += 32; aLo += 32; bHi += 32; bLo += 32;
            }
        }

        {
            float i0 = sStg[(bl + 0) * STG_STRIDE + jl];
            float i1 = sStg[(bl + 1) * STG_STRIDE + jl];
            float i2 = sStg[(bl + 0) * STG_STRIDE + jl + 8];
            float i3 = sStg[(bl + 1) * STG_STRIDE + jl + 8];
            sStg[(bl + 0) * STG_STRIDE + jl]     = tanhf(c0 + i0);
            sStg[(bl + 1) * STG_STRIDE + jl]     = tanhf(c1 + i1);
            sStg[(bl + 0) * STG_STRIDE + jl + 8] = tanhf(c2 + i2);
            sStg[(bl + 1) * STG_STRIDE + jl + 8] = tanhf(c3 + i3);
        }
        __syncthreads();

        {
            float4 v = *(const float4*)&sStg[sr * STG_STRIDE + sj];
            __nv_bfloat16 h0, h1, h2, h3, l0b, l1b, l2b, l3b;
            split_bf16(v.x, h0, l0b); split_bf16(v.y, h1, l1b);
            split_bf16(v.z, h2, l2b); split_bf16(v.w, h3, l3b);
            const int p1 = (t + 1) & 1;
            const int gidx = (d * NB + b0 + sr) * NH + j0 + sj;
            uint2 phi, plo;
            phi.x = (uint32_t)__bfloat16_as_ushort(h0) | ((uint32_t)__bfloat16_as_ushort(h1) << 16);
            phi.y = (uint32_t)__bfloat16_as_ushort(h2) | ((uint32_t)__bfloat16_as_ushort(h3) << 16);
            plo.x = (uint32_t)__bfloat16_as_ushort(l0b) | ((uint32_t)__bfloat16_as_ushort(l1b) << 16);
            plo.y = (uint32_t)__bfloat16_as_ushort(l2b) | ((uint32_t)__bfloat16_as_ushort(l3b) << 16);
            *(uint2*)(g_hhi[p1] + gidx) = phi;
            *(uint2*)(g_hlo[p1] + gidx) = plo;
            if (layer == 0) {
                const int li = (td * NB + b0 + sr) * (2 * NH) + d * NH + j0 + sj;
                *(uint2*)(g_l0hi + li) = phi;
                *(uint2*)(g_l0lo + li) = plo;
            }
            if (t == NT - 1) {
                const int slot = (layer ? 2 : 0) + d;
                const int di = (slot * NB + b0 + sr) * NH + j0 + sj;
                *(uint2*)(g_dhhi[0] + di) = phi;
                *(uint2*)(g_dhlo[0] + di) = plo;
            }
        }

        if (t < NT - 1)
            group_barrier(grp, 16);
    }
}

// ---------------------------------------------------------------------------
// xs1 via tensor cores: xs1[d][m][j] = l0[m][:] . Wih1[d][j][:] + bias
// M = 16384, N = 512 (per dir), K = 1024. bf16 hi/lo 3-pass.
// Tile 128m x 64n, K chunks of 64. 8 warps = 4(m) x 2(n); warp = 32m x 32n.
// ---------------------------------------------------------------------------
__global__ void __launch_bounds__(256) xs1_mma(
    const float* __restrict__ bih, const float* __restrict__ bhh)
{
    extern __shared__ char sm[];
    __nv_bfloat16* sAhi = (__nv_bfloat16*)(sm);
    __nv_bfloat16* sBhi = (__nv_bfloat16*)(sm + 2 * X_SA);

    const int d  = blockIdx.z;
    const int j0 = blockIdx.x * 64;
    const int m0 = blockIdx.y * 128;
    const int tid  = threadIdx.x;
    const int lane = tid & 31;
    const int warp = tid >> 5;
    const int wm = warp & 3;        // 32-row m block
    const int wn = warp >> 2;       // 32-col n block

    const int ag = lane >> 3, ar = lane & 7;
    const uint32_t aBase = s2u(sAhi) +
        (uint32_t)((wm * 32 + (ag & 1) * 8 + ar) * XAS + (ag >> 1) * 8) * 2;
    const uint32_t bBase = s2u(sBhi) +
        (uint32_t)((wn * 32 + (lane >> 4) * 8 + (lane & 7)) * XAS + ((lane >> 3) & 1) * 8) * 2;

    float acc[2][4][4];
#pragma unroll
    for (int i = 0; i < 2; i++)
#pragma unroll
        for (int n = 0; n < 4; n++)
#pragma unroll
            for (int q = 0; q < 4; q++) acc[i][n][q] = 0.f;

    const int r  = tid >> 3;          // 0..31
    const int c8 = (tid & 7) * 8;     // element col (8 bf16 = 16 B)

    for (int k0 = 0; k0 < 2 * NH; k0 += 64) {
        if (k0) __syncthreads();
#pragma unroll
        for (int rr = r; rr < 128; rr += 32) {
            const int gi = (m0 + rr) * (2 * NH) + k0 + c8;
            *(uint4*)((char*)sAhi + (rr * XAS + c8) * 2)        = __ldg((const uint4*)(g_l0hi + gi));
            *(uint4*)((char*)sAhi + X_SA + (rr * XAS + c8) * 2) = __ldg((const uint4*)(g_l0lo + gi));
        }
#pragma unroll
        for (int rr = r; rr < 64; rr += 32) {
            const int gi = (d * NH + j0 + rr) * (2 * NH) + k0 + c8;
            *(uint4*)((char*)sBhi + (rr * XAS + c8) * 2)        = __ldg((const uint4*)(g_xWhi + gi));
            *(uint4*)((char*)sBhi + X_SB + (rr * XAS + c8) * 2) = __ldg((const uint4*)(g_xWlo + gi));
        }
        __syncthreads();

#pragma unroll
        for (int kk = 0; kk < 4; kk++) {
            uint32_t ah[2][4], al[2][4];
#pragma unroll
            for (int mt = 0; mt < 2; mt++) {
                const uint32_t addr = aBase + (uint32_t)(mt * 16 * XAS + kk * 16) * 2;
                LDSM_X4(ah[mt][0], ah[mt][1], ah[mt][2], ah[mt][3], addr);
                LDSM_X4(al[mt][0], al[mt][1], al[mt][2], al[mt][3], addr + X_SA);
            }
#pragma unroll
            for (int np = 0; np < 2; np++) {
                const uint32_t addr = bBase + (uint32_t)(np * 16 * XAS + kk * 16) * 2;
                uint32_t bh0, bh1, bh2, bh3, bl0, bl1, bl2, bl3;
                LDSM_X4(bh0, bh1, bh2, bh3, addr);
                LDSM_X4(bl0, bl1, bl2, bl3, addr + X_SB);
#pragma unroll
                for (int mt = 0; mt < 2; mt++) {
                    float* a0 = acc[mt][np * 2 + 0];
                    float* a1 = acc[mt][np * 2 + 1];
                    MMA_BF16(a0[0], a0[1], a0[2], a0[3],
                             ah[mt][0], ah[mt][1], ah[mt][2], ah[mt][3], bh0, bh1);
                    MMA_BF16(a0[0], a0[1], a0[2], a0[3],
                             ah[mt][0], ah[mt][1], ah[mt][2], ah[mt][3], bl0, bl1);
                    MMA_BF16(a0[0], a0[1], a0[2], a0[3],
                             al[mt][0], al[mt][1], al[mt][2], al[mt][3], bh0, bh1);
                    MMA_BF16(a1[0], a1[1], a1[2], a1[3],
                             ah[mt][0], ah[mt][1], ah[mt][2], ah[mt][3], bh2, bh3);
                    MMA_BF16(a1[0], a1[1], a1[2], a1[3],
                             ah[mt][0], ah[mt][1], ah[mt][2], ah[mt][3], bl2, bl3);
                    MMA_BF16(a1[0], a1[1], a1[2], a1[3],
                             al[mt][0], al[mt][1], al[mt][2], al[mt][3], bh2, bh3);
                }
            }
        }
    }

    // epilogue: add bias, store fp32
#pragma unroll
    for (int nt = 0; nt < 4; nt++) {
        const int j = j0 + wn * 32 + nt * 8 + (lane & 3) * 2;
        const float bj0 = __ldg(&bih[(2 + d) * NH + j])     + __ldg(&bhh[(2 + d) * NH + j]);
        const float bj1 = __ldg(&bih[(2 + d) * NH + j + 1]) + __ldg(&bhh[(2 + d) * NH + j + 1]);
#pragma unroll
        for (int mt = 0; mt < 2; mt++) {
            const int m = m0 + wm * 32 + mt * 16 + (lane >> 2);
            *(float2*)&g_xs1[(d * NT * NB + m) * NH + j] =
                make_float2(acc[mt][nt][0] + bj0, acc[mt][nt][1] + bj1);
            *(float2*)&g_xs1[(d * NT * NB + m + 8) * NH + j] =
                make_float2(acc[mt][nt][2] + bj0, acc[mt][nt][3] + bj1);
        }
    }
}

// ---------------------------------------------------------------------------
// Persistent decoder via tensor cores (R8, + per-bt group barriers)
// ---------------------------------------------------------------------------
__global__ void __launch_bounds__(256) dec_persist(
    const float* __restrict__ x,    const float* __restrict__ Wih0,
    const float* __restrict__ Wihr, const float* __restrict__ Whh,
    const float* __restrict__ bih,  const float* __restrict__ bhh,
    const float* __restrict__ linW, const float* __restrict__ linb,
    float* __restrict__ out)
{
    extern __shared__ char sm[];
    __nv_bfloat16* sWhi = (__nv_bfloat16*)(sm + OFF_DWHI);
    __nv_bfloat16* sWlo = (__nv_bfloat16*)(sm + OFF_DWLO);
    __nv_bfloat16* sHhi = (__nv_bfloat16*)(sm + OFF_DHHI);
    __nv_bfloat16* sHlo = (__nv_bfloat16*)(sm + OFF_DHLO);
    float*         sStg = (float*)(sm + OFF_DSTG);
    float*         sPrt = (float*)(sm + OFF_DPRT);

    __shared__ float s_dec[16][3];
    __shared__ float s_o0[16];

    const int jt = blockIdx.x & 15;
    const int bt = blockIdx.x >> 4;
    const int grp = 8 + bt;             // decoder groups 8..15
    const int j0 = jt * 32;
    const int b0 = bt * 16;
    const int tid  = threadIdx.x;
    const int lane = tid & 31;
    const int warp = tid >> 5;
    const int mj   = warp & 1;
    const int kw   = warp >> 1;

    // one-time: convert decoder weights to bf16 hi/lo (grid-strided)
    {
        const int stride4 = DEC_CTAS * 256 * 4;
        const int g4 = (blockIdx.x * 256 + tid) * 4;
        for (int i = g4; i < 4 * WMAT; i += stride4) {
            float4 w = *(const float4*)&Whh[i];
            split_bf16(w.x, g_dWhi[i + 0], g_dWlo[i + 0]);
            split_bf16(w.y, g_dWhi[i + 1], g_dWlo[i + 1]);
            split_bf16(w.z, g_dWhi[i + 2], g_dWlo[i + 2]);
            split_bf16(w.w, g_dWhi[i + 3], g_dWlo[i + 3]);
        }
        for (int i = g4; i < 3 * WMAT; i += stride4) {
            float4 w = *(const float4*)&Wihr[i];
            split_bf16(w.x, g_dWhi[WIHR_OFF + i + 0], g_dWlo[WIHR_OFF + i + 0]);
            split_bf16(w.y, g_dWhi[WIHR_OFF + i + 1], g_dWlo[WIHR_OFF + i + 1]);
            split_bf16(w.z, g_dWhi[WIHR_OFF + i + 2], g_dWlo[WIHR_OFF + i + 2]);
            split_bf16(w.w, g_dWhi[WIHR_OFF + i + 3], g_dWlo[WIHR_OFF + i + 3]);
        }
    }
    if (tid < 16) {
        const float* xr = x + ((b0 + tid) * NT + (NT - 1)) * NIN;
        s_dec[tid][0] = xr[0];
        s_dec[tid][1] = xr[1];
        s_dec[tid][2] = xr[2];
    }
    grid_barrier(DEC_CTAS);

    const int ag = lane >> 3, ar = lane & 7;
    const uint32_t aOff = (uint32_t)((mj * 16 + (ag & 1) * 8 + ar) * DEHS
                                     + (ag >> 1) * 8 + kw * 256) * 2;
    const uint32_t aHiBase = s2u(sWhi) + aOff;
    const uint32_t aLoBase = s2u(sWlo) + aOff;
    const uint32_t bOff = (uint32_t)(((lane >> 4) * 8 + (lane & 7)) * DEHS
                                     + ((lane >> 3) & 1) * 8 + kw * 256) * 2;
    const uint32_t bHiBase = s2u(sHhi) + bOff;
    const uint32_t bLoBase = s2u(sHlo) + bOff;

    const int sr = tid >> 4;
    const int sj = (tid & 15) * 2;
    const int jl = mj * 16 + (lane >> 2);
    const int bl = (lane & 3) * 2;

    for (int t = 0; t < NTGT; t++) {
        const int p = t & 1;

        if (t > 0) {
            const float* h3 = g_h3[p];
#pragma unroll
            for (int rr = 0; rr < 2; rr++) {
                const int brow = warp * 2 + rr;
                const float* row = h3 + (b0 + brow) * NH;
                float s = 0.f;
#pragma unroll
                for (int i = lane; i < NH; i += 32)
                    s += __ldcg(&row[i]) * linW[i];
#pragma unroll
                for (int o = 16; o; o >>= 1) s += __shfl_xor_sync(0xffffffffu, s, o);
                if (lane == 0) s_o0[brow] = s;
            }
            __syncthreads();
            if (tid < 16) {
                float o0 = s_o0[tid] + linb[0];
                if (jt == 0) out[(b0 + tid) * NTGT + (t - 1)] = o0;
                float s1 = s_dec[tid][0] - o0;
                float s2 = s_dec[tid][1] - s1;
                s_dec[tid][0] = o0;
                s_dec[tid][1] = s1;
                s_dec[tid][2] = s2;
            }
            __syncthreads();
        }

        for (int l = 0; l < 4; l++) {
            const int nk = (l == 0) ? 2 : 4;

            {
                const int r  = tid >> 3;
                const int c8 = tid & 7;
                const __nv_bfloat16* shi = g_dWhi + l * WMAT + (j0 + r) * NH;
                const __nv_bfloat16* slo = g_dWlo + l * WMAT + (j0 + r) * NH;
#pragma unroll
                for (int c = c8; c < 64; c += 8) {
                    *(uint4*)(sWhi + r * DEHS + c * 8) = __ldg((const uint4*)(shi + c * 8));
                    *(uint4*)(sWlo + r * DEHS + c * 8) = __ldg((const uint4*)(slo + c * 8));
                }
                if (l > 0) {
                    const __nv_bfloat16* shi2 = g_dWhi + WIHR_OFF + (l - 1) * WMAT + (j0 + r) * NH;
                    const __nv_bfloat16* slo2 = g_dWlo + WIHR_OFF + (l - 1) * WMAT + (j0 + r) * NH;
#pragma unroll
                    for (int c = c8; c < 64; c += 8) {
                        *(uint4*)(sWhi + r * DEHS + 512 + c * 8) = __ldg((const uint4*)(shi2 + c * 8));
                        *(uint4*)(sWlo + r * DEHS + 512 + c * 8) = __ldg((const uint4*)(slo2 + c * 8));
                    }
                }
            }
            {
                const int r   = tid >> 4;
                const int c16 = tid & 15;
                const __nv_bfloat16* rhi = g_dhhi[p] + (l * NB + b0 + r) * NH;
                const __nv_bfloat16* rlo = g_dhlo[p] + (l * NB + b0 + r) * NH;
#pragma unroll
                for (int c = c16; c < 64; c += 16) {
                    *(uint4*)(sHhi + r * DEHS + c * 8) = __ldcg((const uint4*)(rhi + c * 8));
                    *(uint4*)(sHlo + r * DEHS + c * 8) = __ldcg((const uint4*)(rlo + c * 8));
                }
                if (l > 0) {
                    const __nv_bfloat16* ihi = g_dhhi[1 - p] + ((l - 1) * NB + b0 + r) * NH;
                    const __nv_bfloat16* ilo = g_dhlo[1 - p] + ((l - 1) * NB + b0 + r) * NH;
#pragma unroll
                    for (int c = c16; c < 64; c += 16) {
                        *(uint4*)(sHhi + r * DEHS + 512 + c * 8) = __ldcg((const uint4*)(ihi + c * 8));
                        *(uint4*)(sHlo + r * DEHS + 512 + c * 8) = __ldcg((const uint4*)(ilo + c * 8));
                    }
                }
            }
            {
                float v0 = bih[l * NH + j0 + sj + 0] + bhh[l * NH + j0 + sj + 0];
                float v1 = bih[l * NH + j0 + sj + 1] + bhh[l * NH + j0 + sj + 1];
                if (l == 0) {
                    const float i0 = s_dec[sr][0], i1 = s_dec[sr][1], i2 = s_dec[sr][2];
                    const float* wp = Wih0 + (j0 + sj) * NIN;
                    v0 += i0 * wp[0] + i1 * wp[1] + i2 * wp[2];
                    v1 += i0 * wp[3] + i1 * wp[4] + i2 * wp[5];
                }
                sStg[sr * 36 + sj + 0] = v0;
                sStg[sr * 36 + sj + 1] = v1;
            }
            __syncthreads();

            if (kw < nk) {
                float c00 = 0.f, c01 = 0.f, c02 = 0.f, c03 = 0.f;
                float c10 = 0.f, c11 = 0.f, c12 = 0.f, c13 = 0.f;
                uint32_t aHi = aHiBase, aLo = aLoBase, bHi = bHiBase, bLo = bLoBase;
#pragma unroll 4
                for (int kk = 0; kk < 16; kk++) {
                    uint32_t a0, a1, a2, a3, e0, e1, e2, e3;
                    uint32_t r0, r1, r2, r3, f0, f1, f2, f3;
                    LDSM_X4(a0, a1, a2, a3, aHi);
                    LDSM_X4(e0, e1, e2, e3, aLo);
                    LDSM_X4(r0, r1, r2, r3, bHi);
                    LDSM_X4(f0, f1, f2, f3, bLo);
                    MMA_BF16(c00, c01, c02, c03, a0, a1, a2, a3, r0, r1);
                    MMA_BF16(c00, c01, c02, c03, a0, a1, a2, a3, f0, f1);
                    MMA_BF16(c00, c01, c02, c03, e0, e1, e2, e3, r0, r1);
                    MMA_BF16(c10, c11, c12, c13, a0, a1, a2, a3, r2, r3);
                    MMA_BF16(c10, c11, c12, c13, a0, a1, a2, a3, f2, f3);
                    MMA_BF16(c10, c11, c12, c13, e0, e1, e2, e3, r2, r3);
                    aHi += 32; aLo += 32; bHi += 32; bLo += 32;
                }
                float* pp = sPrt + kw * (16 * 36);
                pp[(bl + 0) * 36 + jl]     = c00;
                pp[(bl + 1) * 36 + jl]     = c01;
                pp[(bl + 0) * 36 + jl + 8] = c02;
                pp[(bl + 1) * 36 + jl + 8] = c03;
                pp[(bl + 8) * 36 + jl]     = c10;
                pp[(bl + 9) * 36 + jl]     = c11;
                pp[(bl + 8) * 36 + jl + 8] = c12;
                pp[(bl + 9) * 36 + jl + 8] = c13;
            }
            __syncthreads();

            {
                float v0 = sStg[sr * 36 + sj + 0];
                float v1 = sStg[sr * 36 + sj + 1];
#pragma unroll
                for (int q = 0; q < 4; q++) {
                    if (q < nk) {
                        v0 += sPrt[q * 576 + sr * 36 + sj + 0];
                        v1 += sPrt[q * 576 + sr * 36 + sj + 1];
                    }
                }
                v0 = tanhf(v0); v1 = tanhf(v1);
                __nv_bfloat16 h0, h1, l0b, l1b;
                split_bf16(v0, h0, l0b);
                split_bf16(v1, h1, l1b);
                const int idx = (l * NB + b0 + sr) * NH + j0 + sj;
                uint32_t phi = (uint32_t)__bfloat16_as_ushort(h0) |
                               ((uint32_t)__bfloat16_as_ushort(h1) << 16);
                uint32_t plo = (uint32_t)__bfloat16_as_ushort(l0b) |
                               ((uint32_t)__bfloat16_as_ushort(l1b) << 16);
                *(uint32_t*)(g_dhhi[1 - p] + idx) = phi;
                *(uint32_t*)(g_dhlo[1 - p] + idx) = plo;
                if (l == 3)
                    *(float2*)&g_h3[1 - p][(b0 + sr) * NH + j0 + sj] = make_float2(v0, v1);
            }

            group_barrier(grp, 16);
        }
    }

    {
        const float* h3 = g_h3[NTGT & 1];
#pragma unroll
        for (int rr = 0; rr < 2; rr++) {
            const int brow = warp * 2 + rr;
            const float* row = h3 + (b0 + brow) * NH;
            float s = 0.f;
#pragma unroll
            for (int i = lane; i < NH; i += 32)
                s += __ldcg(&row[i]) * linW[i];
#pragma unroll
            for (int o = 16; o; o >>= 1) s += __shfl_xor_sync(0xffffffffu, s, o);
            if (lane == 0) s_o0[brow] = s;
        }
        __syncthreads();
        if (tid < 16 && jt == 0)
            out[(b0 + tid) * NTGT + (NTGT - 1)] = s_o0[tid] + linb[0];
    }
}

// ---------------------------------------------------------------------------
// Launch sequence (graph-capturable: kernel launches only)
// ---------------------------------------------------------------------------
extern "C" void kernel_launch(void* const* d_in, const int* in_sizes, int n_in,
                              void* d_out, int out_size)
{
    const float* x        = (const float*)d_in[0];
    const float* enc_Wih0 = (const float*)d_in[2];
    const float* enc_Whh0 = (const float*)d_in[3];
    const float* enc_Wih1 = (const float*)d_in[4];
    const float* enc_Whh1 = (const float*)d_in[5];
    const float* enc_bih  = (const float*)d_in[6];
    const float* enc_bhh  = (const float*)d_in[7];
    const float* dec_Wih0 = (const float*)d_in[8];
    const float* dec_Wihr = (const float*)d_in[9];
    const float* dec_Whh  = (const float*)d_in[10];
    const float* dec_bih  = (const float*)d_in[11];
    const float* dec_bhh  = (const float*)d_in[12];
    const float* lin_W    = (const float*)d_in[13];
    const float* lin_b    = (const float*)d_in[14];
    float* out = (float*)d_out;

    cudaFuncSetAttribute(enc_mma, cudaFuncAttributeMaxDynamicSharedMemorySize,
                         ENC_SMEM);
    cudaFuncSetAttribute(dec_persist, cudaFuncAttributeMaxDynamicSharedMemorySize,
                         DEC_SMEM);
    cudaFuncSetAttribute(xs1_mma, cudaFuncAttributeMaxDynamicSharedMemorySize,
                         XS1_SMEM);

    // Pre-split Wih1 (independent of encoder)
    split_wih1<<<1024, 256>>>(enc_Wih1);

    // Encoder layer 0
    enc_mma<<<ENC_CTAS, 256, ENC_SMEM>>>(x, enc_Wih0, enc_Whh0,
                                         enc_bih, enc_bhh, 0);

    // Layer-1 input terms, tensor cores
    xs1_mma<<<dim3(8, 128, 2), 256, XS1_SMEM>>>(enc_bih, enc_bhh);

    // Encoder layer 1
    enc_mma<<<ENC_CTAS, 256, ENC_SMEM>>>(x, enc_Wih0, enc_Whh1,
                                         enc_bih, enc_bhh, 1);

    // Decoder
    dec_persist<<<DEC_CTAS, 256, DEC_SMEM>>>(x, dec_Wih0, dec_Wihr, dec_Whh,
                                             dec_bih, dec_bhh, lin_W, lin_b, out);
}

// round 10
// speedup vs baseline: 3.3829x; 1.0924x over previous
#include <cuda_runtime.h>
#include <cuda_bf16.h>
#include <cstdint>

// Problem constants
constexpr int NB   = 128;   // batch
constexpr int NT   = 128;   // encoder time steps
constexpr int NIN  = 3;     // input features
constexpr int NH   = 512;   // hidden
constexpr int NTGT = 32;    // decoder steps

constexpr int ENC_CTAS = 128;
constexpr int DEC_CTAS = 128;

// ---------------- encoder smem layout (R10: W in regs, smaller smem) ------
constexpr int EHS      = 520;                   // bf16 row stride (elements)
constexpr int E_TILE   = 32 * EHS * 2;          // 33280 B (one 32x512 bf16 tile)
constexpr int OFF_EHHI = 0;                     // h hi (aliases W staging)
constexpr int OFF_EHLO = OFF_EHHI + E_TILE;     // h lo
constexpr int OFF_ESTG = OFF_EHLO + E_TILE;     // [32][36] f32 stage
constexpr int OFF_EPRT = OFF_ESTG + 32 * 36 * 4; // [4][32][36] f32 partials
constexpr int ENC_SMEM = OFF_EPRT + 4 * 32 * 36 * 4;   // 89600 B

// ---------------- decoder smem layout (proven R8) ----------------
constexpr int DEHS     = 1032;
constexpr int DW_TILE  = 32 * DEHS * 2;
constexpr int DH_TILE  = 16 * DEHS * 2;
constexpr int OFF_DWHI = 0;
constexpr int OFF_DWLO = OFF_DWHI + DW_TILE;
constexpr int OFF_DHHI = OFF_DWLO + DW_TILE;
constexpr int OFF_DHLO = OFF_DHHI + DH_TILE;
constexpr int OFF_DSTG = OFF_DHLO + DH_TILE;
constexpr int OFF_DPRT = OFF_DSTG + 16 * 36 * 4;
constexpr int DEC_SMEM = OFF_DPRT + 4 * 16 * 36 * 4;

constexpr int WMAT     = NH * NH;
constexpr int WIHR_OFF = 4 * WMAT;

// ---------------- xs1 mma smem layout ----------------
constexpr int XAS    = 72;
constexpr int X_SA   = 128 * XAS * 2;
constexpr int X_SB   = 64 * XAS * 2;
constexpr int XS1_SMEM = 2 * X_SA + 2 * X_SB;

// ---------------------------------------------------------------------------
// Static device scratch
// ---------------------------------------------------------------------------
__device__ __nv_bfloat16 g_l0hi[NT * NB * (2 * NH)];
__device__ __nv_bfloat16 g_l0lo[NT * NB * (2 * NH)];
__device__ __nv_bfloat16 g_xWhi[2 * NH * (2 * NH)];
__device__ __nv_bfloat16 g_xWlo[2 * NH * (2 * NH)];
__device__ float g_xs1[2 * NT * NB * NH];
__device__ __nv_bfloat16 g_hhi[2][2 * NB * NH];
__device__ __nv_bfloat16 g_hlo[2][2 * NB * NH];
__device__ __nv_bfloat16 g_dWhi[7 * WMAT];
__device__ __nv_bfloat16 g_dWlo[7 * WMAT];
__device__ __nv_bfloat16 g_dhhi[2][4 * NB * NH];
__device__ __nv_bfloat16 g_dhlo[2][4 * NB * NH];
__device__ float g_h3[2][NB * NH];
__device__ unsigned g_cnt;
__device__ unsigned g_gen;
__device__ unsigned g_gcnt[16 * 32];
__device__ unsigned g_ggen[16 * 32];

// ---------------------------------------------------------------------------
// Barriers (generation-based, self-resetting, replay-safe)
// ---------------------------------------------------------------------------
__device__ __forceinline__ void grid_barrier(unsigned nctas)
{
    __threadfence();
    __syncthreads();
    if (threadIdx.x == 0) {
        volatile unsigned* genp = &g_gen;
        unsigned gen = *genp;
        if (atomicAdd(&g_cnt, 1u) == nctas - 1) {
            g_cnt = 0;
            __threadfence();
            *genp = gen + 1;
        } else {
            while (*genp == gen) { }
            __threadfence();
        }
    }
    __syncthreads();
}

__device__ __forceinline__ void group_barrier(int g, unsigned n)
{
    __threadfence();
    __syncthreads();
    if (threadIdx.x == 0) {
        volatile unsigned* genp = &g_ggen[g * 32];
        unsigned gen = *genp;
        if (atomicAdd(&g_gcnt[g * 32], 1u) == n - 1) {
            g_gcnt[g * 32] = 0;
            __threadfence();
            *genp = gen + 1;
        } else {
            while (*genp == gen) { }
            __threadfence();
        }
    }
    __syncthreads();
}

// ---------------------------------------------------------------------------
// mma.sync + cp.async helpers
// ---------------------------------------------------------------------------
__device__ __forceinline__ uint32_t s2u(const void* p)
{
    return (uint32_t)__cvta_generic_to_shared(p);
}

#define LDSM_X4(r0, r1, r2, r3, addr)                                          \
    asm volatile("ldmatrix.sync.aligned.m8n8.x4.shared.b16 {%0,%1,%2,%3}, [%4];" \
                 : "=r"(r0), "=r"(r1), "=r"(r2), "=r"(r3) : "r"(addr))

#define MMA_BF16(c0, c1, c2, c3, a0, a1, a2, a3, b0, b1)                       \
    asm volatile("mma.sync.aligned.m16n8k16.row.col.f32.bf16.bf16.f32 "        \
                 "{%0,%1,%2,%3}, {%4,%5,%6,%7}, {%8,%9}, {%0,%1,%2,%3};"       \
                 : "+f"(c0), "+f"(c1), "+f"(c2), "+f"(c3)                      \
                 : "r"(a0), "r"(a1), "r"(a2), "r"(a3), "r"(b0), "r"(b1))

#define CP_ASYNC16(saddr, gptr)                                                \
    asm volatile("cp.async.cg.shared.global [%0], [%1], 16;"                   \
                 :: "r"(saddr), "l"(gptr))
#define CP_COMMIT()  asm volatile("cp.async.commit_group;")
#define CP_WAIT0()   asm volatile("cp.async.wait_group 0;" ::: "memory")

__device__ __forceinline__ void split_bf16(float v, __nv_bfloat16& hi, __nv_bfloat16& lo)
{
    hi = __float2bfloat16(v);
    lo = __float2bfloat16(v - __bfloat162float(hi));
}

// ---------------------------------------------------------------------------
// Pre-split Wih1 into bf16 hi/lo
// ---------------------------------------------------------------------------
__global__ void __launch_bounds__(256) split_wih1(const float* __restrict__ W)
{
    const int i = (blockIdx.x * 256 + threadIdx.x) * 4;
    if (i < 2 * NH * 2 * NH) {
        float4 w = *(const float4*)&W[i];
        split_bf16(w.x, g_xWhi[i + 0], g_xWlo[i + 0]);
        split_bf16(w.y, g_xWhi[i + 1], g_xWlo[i + 1]);
        split_bf16(w.z, g_xWhi[i + 2], g_xWlo[i + 2]);
        split_bf16(w.w, g_xWhi[i + 3], g_xWlo[i + 3]);
    }
}

// ---------------------------------------------------------------------------
// Persistent encoder layer (R10): W fragments resident in registers.
// 128 CTAs = (16 jt x 4 bt x 2 dirs), 256 threads, out tile 32j x 32b.
// Warps: kw = warp&3 (K quarter of 128), mj = warp>>2 (j half of 16).
// One-time: stage W tile to smem, ldmatrix A frags (hi/lo) into registers,
// then smem is reused for the per-step h tile. Per step: stage h, 8 k-chunks
// of B ldmatrix + 3-pass MMA, kw-partials reduced through smem, owner
// epilogue (tanh + bf16 split + stores). Group barrier per step.
// ---------------------------------------------------------------------------
__global__ void __launch_bounds__(256) enc_mma(
    const float* __restrict__ x, const float* __restrict__ Wih0,
    const float* __restrict__ Whh_all, const float* __restrict__ bih,
    const float* __restrict__ bhh, int layer)
{
    extern __shared__ char sm[];
    __nv_bfloat16* sHhi = (__nv_bfloat16*)(sm + OFF_EHHI);   // aliases W staging
    __nv_bfloat16* sHlo = (__nv_bfloat16*)(sm + OFF_EHLO);
    float*         sStg = (float*)(sm + OFF_ESTG);           // [32][36]
    float*         sPrt = (float*)(sm + OFF_EPRT);           // [4][32][36]

    const int blk = blockIdx.x;
    const int d   = blk >> 6;
    const int bt  = (blk >> 4) & 3;
    const int jt  = blk & 15;
    const int grp = blk >> 4;          // (d, bt) group of 16 CTAs
    const int b0  = bt * 32;
    const int j0  = jt * 32;
    const int tid = threadIdx.x;
    const int lane = tid & 31;
    const int warp = tid >> 5;
    const int kw   = warp & 3;         // K quarter (128 cols)
    const int mj   = warp >> 2;        // j half (16 rows)

    const float* Whh = Whh_all + d * NH * NH;

    // ---- one-time: stage W tile (bf16 hi/lo) into smem ----
    {
        const int r  = tid >> 3;
        const int c0 = (tid & 7) * 4;
        for (int k0 = 0; k0 < NH; k0 += 32) {
            float4 w = __ldg((const float4*)&Whh[(j0 + r) * NH + k0 + c0]);
            const int o = r * EHS + k0 + c0;
            split_bf16(w.x, sHhi[o + 0], sHlo[o + 0]);
            split_bf16(w.y, sHhi[o + 1], sHlo[o + 1]);
            split_bf16(w.z, sHhi[o + 2], sHlo[o + 2]);
            split_bf16(w.w, sHhi[o + 3], sHlo[o + 3]);
        }
    }
    __syncthreads();

    // ---- preload A fragments (16j x 128K per warp, hi+lo) into registers ----
    uint32_t aHi[8][4], aLo[8][4];
    {
        const int ag = lane >> 3, ar = lane & 7;
        const uint32_t rowOff = (uint32_t)((mj * 16 + (ag & 1) * 8 + ar) * EHS) * 2;
        const uint32_t colSel = (uint32_t)(kw * 128 + (ag >> 1) * 8) * 2;
#pragma unroll
        for (int q = 0; q < 8; q++) {
            const uint32_t off = rowOff + colSel + q * 32;
            LDSM_X4(aHi[q][0], aHi[q][1], aHi[q][2], aHi[q][3], s2u(sHhi) + off);
            LDSM_X4(aLo[q][0], aLo[q][1], aLo[q][2], aLo[q][3], s2u(sHlo) + off);
        }
    }
    __syncthreads();   // W smem dead; reuse for h

    // ---- B (h) ldmatrix bases: rows = b, cols = kw quarter ----
    const uint32_t bRow = (uint32_t)(((lane >> 4) * 8 + (lane & 7)) * EHS) * 2;
    const uint32_t bCol = (uint32_t)(((lane >> 3) & 1) * 8 + kw * 128) * 2;
    const uint32_t bHi0 = s2u(sHhi) + bRow + bCol;
    const uint32_t bHi1 = bHi0 + 16 * EHS * 2;      // b rows 16..31
    const uint32_t bLo0 = s2u(sHlo) + bRow + bCol;
    const uint32_t bLo1 = bLo0 + 16 * EHS * 2;

    // ---- owner slots + layer-0 constants ----
    const int sr = tid >> 3;               // b row 0..31
    const int sj = (tid & 7) * 4;          // j group of 4
    float bias[4], wi[12];
    if (layer == 0) {
#pragma unroll
        for (int i = 0; i < 4; i++)
            bias[i] = bih[d * NH + j0 + sj + i] + bhh[d * NH + j0 + sj + i];
        const float* wp = Wih0 + (d * NH + j0 + sj) * NIN;
#pragma unroll
        for (int i = 0; i < 12; i++) wi[i] = wp[i];
    }

    // c-frag positions for partial writes
    const int jl = mj * 16 + (lane >> 2);
    const int bl = (lane & 3) * 2;
    float* pp = sPrt + kw * (32 * 36);

    for (int t = 0; t < NT; t++) {
        const int td = d ? (NT - 1 - t) : t;

        // ---- stage h tile (bf16 hi/lo) ----
        if (t > 0) {
            const int p = t & 1;
            const __nv_bfloat16* srcHi = g_hhi[p] + (d * NB + b0) * NH;
            const __nv_bfloat16* srcLo = g_hlo[p] + (d * NB + b0) * NH;
            const int r  = tid >> 3;
            const int cc = tid & 7;
#pragma unroll
            for (int it = 0; it < 8; it++) {
                const int c16 = cc + it * 8;
                uint4 vh = __ldcg((const uint4*)(srcHi + r * NH) + c16);
                uint4 vl = __ldcg((const uint4*)(srcLo + r * NH) + c16);
                *(uint4*)((char*)sHhi + r * (EHS * 2) + c16 * 16) = vh;
                *(uint4*)((char*)sHlo + r * (EHS * 2) + c16 * 16) = vl;
            }
        }
        // ---- stage init (non-recurrent term) ----
        if (layer == 0) {
            const float* xr = x + ((b0 + sr) * NT + td) * NIN;
            const float x0 = xr[0], x1 = xr[1], x2 = xr[2];
            float4 v;
            v.x = bias[0] + x0 * wi[0] + x1 * wi[1]  + x2 * wi[2];
            v.y = bias[1] + x0 * wi[3] + x1 * wi[4]  + x2 * wi[5];
            v.z = bias[2] + x0 * wi[6] + x1 * wi[7]  + x2 * wi[8];
            v.w = bias[3] + x0 * wi[9] + x1 * wi[10] + x2 * wi[11];
            *(float4*)&sStg[sr * 36 + sj] = v;
        } else {
            float4 v = __ldg((const float4*)&g_xs1[((d * NT + td) * NB + b0 + sr) * NH + j0 + sj]);
            *(float4*)&sStg[sr * 36 + sj] = v;
        }
        __syncthreads();

        // ---- MMA over this warp's K quarter (A from registers) ----
        if (t > 0) {
            float acc[4][4];
#pragma unroll
            for (int n = 0; n < 4; n++)
#pragma unroll
                for (int q = 0; q < 4; q++) acc[n][q] = 0.f;

#pragma unroll
            for (int q = 0; q < 8; q++) {
                uint32_t h0, h1, h2, h3, h4, h5, h6, h7;
                uint32_t l0, l1, l2, l3, l4, l5, l6, l7;
                LDSM_X4(h0, h1, h2, h3, bHi0 + q * 32);
                LDSM_X4(h4, h5, h6, h7, bHi1 + q * 32);
                LDSM_X4(l0, l1, l2, l3, bLo0 + q * 32);
                LDSM_X4(l4, l5, l6, l7, bLo1 + q * 32);
                // b 0-7
                MMA_BF16(acc[0][0], acc[0][1], acc[0][2], acc[0][3],
                         aHi[q][0], aHi[q][1], aHi[q][2], aHi[q][3], h0, h1);
                MMA_BF16(acc[0][0], acc[0][1], acc[0][2], acc[0][3],
                         aHi[q][0], aHi[q][1], aHi[q][2], aHi[q][3], l0, l1);
                MMA_BF16(acc[0][0], acc[0][1], acc[0][2], acc[0][3],
                         aLo[q][0], aLo[q][1], aLo[q][2], aLo[q][3], h0, h1);
                // b 8-15
                MMA_BF16(acc[1][0], acc[1][1], acc[1][2], acc[1][3],
                         aHi[q][0], aHi[q][1], aHi[q][2], aHi[q][3], h2, h3);
                MMA_BF16(acc[1][0], acc[1][1], acc[1][2], acc[1][3],
                         aHi[q][0], aHi[q][1], aHi[q][2], aHi[q][3], l2, l3);
                MMA_BF16(acc[1][0], acc[1][1], acc[1][2], acc[1][3],
                         aLo[q][0], aLo[q][1], aLo[q][2], aLo[q][3], h2, h3);
                // b 16-23
                MMA_BF16(acc[2][0], acc[2][1], acc[2][2], acc[2][3],
                         aHi[q][0], aHi[q][1], aHi[q][2], aHi[q][3], h4, h5);
                MMA_BF16(acc[2][0], acc[2][1], acc[2][2], acc[2][3],
                         aHi[q][0], aHi[q][1], aHi[q][2], aHi[q][3], l4, l5);
                MMA_BF16(acc[2][0], acc[2][1], acc[2][2], acc[2][3],
                         aLo[q][0], aLo[q][1], aLo[q][2], aLo[q][3], h4, h5);
                // b 24-31
                MMA_BF16(acc[3][0], acc[3][1], acc[3][2], acc[3][3],
                         aHi[q][0], aHi[q][1], aHi[q][2], aHi[q][3], h6, h7);
                MMA_BF16(acc[3][0], acc[3][1], acc[3][2], acc[3][3],
                         aHi[q][0], aHi[q][1], aHi[q][2], aHi[q][3], l6, l7);
                MMA_BF16(acc[3][0], acc[3][1], acc[3][2], acc[3][3],
                         aLo[q][0], aLo[q][1], aLo[q][2], aLo[q][3], h6, h7);
            }
            // write kw partials
#pragma unroll
            for (int n = 0; n < 4; n++) {
                pp[(n * 8 + bl + 0) * 36 + jl]     = acc[n][0];
                pp[(n * 8 + bl + 1) * 36 + jl]     = acc[n][1];
                pp[(n * 8 + bl + 0) * 36 + jl + 8] = acc[n][2];
                pp[(n * 8 + bl + 1) * 36 + jl + 8] = acc[n][3];
            }
        }
        __syncthreads();

        // ---- owner epilogue: reduce kw partials + tanh + split + store ----
        {
            float v[4];
            float4 st = *(const float4*)&sStg[sr * 36 + sj];
            v[0] = st.x; v[1] = st.y; v[2] = st.z; v[3] = st.w;
            if (t > 0) {
#pragma unroll
                for (int q = 0; q < 4; q++) {
#pragma unroll
                    for (int i = 0; i < 4; i++)
                        v[i] += sPrt[q * (32 * 36) + sr * 36 + sj + i];
                }
            }
#pragma unroll
            for (int i = 0; i < 4; i++) v[i] = tanhf(v[i]);

            __nv_bfloat16 h0, h1, h2, h3, l0b, l1b, l2b, l3b;
            split_bf16(v[0], h0, l0b); split_bf16(v[1], h1, l1b);
            split_bf16(v[2], h2, l2b); split_bf16(v[3], h3, l3b);
            const int p1 = (t + 1) & 1;
            const int gidx = (d * NB + b0 + sr) * NH + j0 + sj;
            uint2 phi, plo;
            phi.x = (uint32_t)__bfloat16_as_ushort(h0) | ((uint32_t)__bfloat16_as_ushort(h1) << 16);
            phi.y = (uint32_t)__bfloat16_as_ushort(h2) | ((uint32_t)__bfloat16_as_ushort(h3) << 16);
            plo.x = (uint32_t)__bfloat16_as_ushort(l0b) | ((uint32_t)__bfloat16_as_ushort(l1b) << 16);
            plo.y = (uint32_t)__bfloat16_as_ushort(l2b) | ((uint32_t)__bfloat16_as_ushort(l3b) << 16);
            *(uint2*)(g_hhi[p1] + gidx) = phi;
            *(uint2*)(g_hlo[p1] + gidx) = plo;
            if (layer == 0) {
                const int li = (td * NB + b0 + sr) * (2 * NH) + d * NH + j0 + sj;
                *(uint2*)(g_l0hi + li) = phi;
                *(uint2*)(g_l0lo + li) = plo;
            }
            if (t == NT - 1) {
                const int slot = (layer ? 2 : 0) + d;
                const int di = (slot * NB + b0 + sr) * NH + j0 + sj;
                *(uint2*)(g_dhhi[0] + di) = phi;
                *(uint2*)(g_dhlo[0] + di) = plo;
            }
        }

        if (t < NT - 1)
            group_barrier(grp, 16);
    }
}

// ---------------------------------------------------------------------------
// xs1 via tensor cores (unchanged from R9)
// ---------------------------------------------------------------------------
__global__ void __launch_bounds__(256) xs1_mma(
    const float* __restrict__ bih, const float* __restrict__ bhh)
{
    extern __shared__ char sm[];
    __nv_bfloat16* sAhi = (__nv_bfloat16*)(sm);
    __nv_bfloat16* sBhi = (__nv_bfloat16*)(sm + 2 * X_SA);

    const int d  = blockIdx.z;
    const int j0 = blockIdx.x * 64;
    const int m0 = blockIdx.y * 128;
    const int tid  = threadIdx.x;
    const int lane = tid & 31;
    const int warp = tid >> 5;
    const int wm = warp & 3;
    const int wn = warp >> 2;

    const int ag = lane >> 3, ar = lane & 7;
    const uint32_t aBase = s2u(sAhi) +
        (uint32_t)((wm * 32 + (ag & 1) * 8 + ar) * XAS + (ag >> 1) * 8) * 2;
    const uint32_t bBase = s2u(sBhi) +
        (uint32_t)((wn * 32 + (lane >> 4) * 8 + (lane & 7)) * XAS + ((lane >> 3) & 1) * 8) * 2;

    float acc[2][4][4];
#pragma unroll
    for (int i = 0; i < 2; i++)
#pragma unroll
        for (int n = 0; n < 4; n++)
#pragma unroll
            for (int q = 0; q < 4; q++) acc[i][n][q] = 0.f;

    const int r  = tid >> 3;
    const int c8 = (tid & 7) * 8;

    for (int k0 = 0; k0 < 2 * NH; k0 += 64) {
        if (k0) __syncthreads();
#pragma unroll
        for (int rr = r; rr < 128; rr += 32) {
            const int gi = (m0 + rr) * (2 * NH) + k0 + c8;
            *(uint4*)((char*)sAhi + (rr * XAS + c8) * 2)        = __ldg((const uint4*)(g_l0hi + gi));
            *(uint4*)((char*)sAhi + X_SA + (rr * XAS + c8) * 2) = __ldg((const uint4*)(g_l0lo + gi));
        }
#pragma unroll
        for (int rr = r; rr < 64; rr += 32) {
            const int gi = (d * NH + j0 + rr) * (2 * NH) + k0 + c8;
            *(uint4*)((char*)sBhi + (rr * XAS + c8) * 2)        = __ldg((const uint4*)(g_xWhi + gi));
            *(uint4*)((char*)sBhi + X_SB + (rr * XAS + c8) * 2) = __ldg((const uint4*)(g_xWlo + gi));
        }
        __syncthreads();

#pragma unroll
        for (int kk = 0; kk < 4; kk++) {
            uint32_t ah[2][4], al[2][4];
#pragma unroll
            for (int mt = 0; mt < 2; mt++) {
                const uint32_t addr = aBase + (uint32_t)(mt * 16 * XAS + kk * 16) * 2;
                LDSM_X4(ah[mt][0], ah[mt][1], ah[mt][2], ah[mt][3], addr);
                LDSM_X4(al[mt][0], al[mt][1], al[mt][2], al[mt][3], addr + X_SA);
            }
#pragma unroll
            for (int np = 0; np < 2; np++) {
                const uint32_t addr = bBase + (uint32_t)(np * 16 * XAS + kk * 16) * 2;
                uint32_t bh0, bh1, bh2, bh3, bl0, bl1, bl2, bl3;
                LDSM_X4(bh0, bh1, bh2, bh3, addr);
                LDSM_X4(bl0, bl1, bl2, bl3, addr + X_SB);
#pragma unroll
                for (int mt = 0; mt < 2; mt++) {
                    float* a0 = acc[mt][np * 2 + 0];
                    float* a1 = acc[mt][np * 2 + 1];
                    MMA_BF16(a0[0], a0[1], a0[2], a0[3],
                             ah[mt][0], ah[mt][1], ah[mt][2], ah[mt][3], bh0, bh1);
                    MMA_BF16(a0[0], a0[1], a0[2], a0[3],
                             ah[mt][0], ah[mt][1], ah[mt][2], ah[mt][3], bl0, bl1);
                    MMA_BF16(a0[0], a0[1], a0[2], a0[3],
                             al[mt][0], al[mt][1], al[mt][2], al[mt][3], bh0, bh1);
                    MMA_BF16(a1[0], a1[1], a1[2], a1[3],
                             ah[mt][0], ah[mt][1], ah[mt][2], ah[mt][3], bh2, bh3);
                    MMA_BF16(a1[0], a1[1], a1[2], a1[3],
                             ah[mt][0], ah[mt][1], ah[mt][2], ah[mt][3], bl2, bl3);
                    MMA_BF16(a1[0], a1[1], a1[2], a1[3],
                             al[mt][0], al[mt][1], al[mt][2], al[mt][3], bh2, bh3);
                }
            }
        }
    }

#pragma unroll
    for (int nt = 0; nt < 4; nt++) {
        const int j = j0 + wn * 32 + nt * 8 + (lane & 3) * 2;
        const float bj0 = __ldg(&bih[(2 + d) * NH + j])     + __ldg(&bhh[(2 + d) * NH + j]);
        const float bj1 = __ldg(&bih[(2 + d) * NH + j + 1]) + __ldg(&bhh[(2 + d) * NH + j + 1]);
#pragma unroll
        for (int mt = 0; mt < 2; mt++) {
            const int m = m0 + wm * 32 + mt * 16 + (lane >> 2);
            *(float2*)&g_xs1[(d * NT * NB + m) * NH + j] =
                make_float2(acc[mt][nt][0] + bj0, acc[mt][nt][1] + bj1);
            *(float2*)&g_xs1[(d * NT * NB + m + 8) * NH + j] =
                make_float2(acc[mt][nt][2] + bj0, acc[mt][nt][3] + bj1);
        }
    }
}

// ---------------------------------------------------------------------------
// Decoder W prefetch (cp.async): no dependency on the group barrier.
// ---------------------------------------------------------------------------
__device__ __forceinline__ void dec_prefetch_W(int l, int j0, int tid,
                                               uint32_t swhi, uint32_t swlo)
{
    const int r  = tid >> 3;
    const int c8 = tid & 7;
    const __nv_bfloat16* shi = g_dWhi + l * WMAT + (j0 + r) * NH;
    const __nv_bfloat16* slo = g_dWlo + l * WMAT + (j0 + r) * NH;
#pragma unroll
    for (int c = c8; c < 64; c += 8) {
        CP_ASYNC16(swhi + (uint32_t)(r * DEHS + c * 8) * 2, shi + c * 8);
        CP_ASYNC16(swlo + (uint32_t)(r * DEHS + c * 8) * 2, slo + c * 8);
    }
    if (l > 0) {
        const __nv_bfloat16* shi2 = g_dWhi + WIHR_OFF + (l - 1) * WMAT + (j0 + r) * NH;
        const __nv_bfloat16* slo2 = g_dWlo + WIHR_OFF + (l - 1) * WMAT + (j0 + r) * NH;
#pragma unroll
        for (int c = c8; c < 64; c += 8) {
            CP_ASYNC16(swhi + (uint32_t)(r * DEHS + 512 + c * 8) * 2, shi2 + c * 8);
            CP_ASYNC16(swlo + (uint32_t)(r * DEHS + 512 + c * 8) * 2, slo2 + c * 8);
        }
    }
    CP_COMMIT();
}

// ---------------------------------------------------------------------------
// Persistent decoder via tensor cores (R8/R9 + cp.async W prefetch)
// ---------------------------------------------------------------------------
__global__ void __launch_bounds__(256) dec_persist(
    const float* __restrict__ x,    const float* __restrict__ Wih0,
    const float* __restrict__ Wihr, const float* __restrict__ Whh,
    const float* __restrict__ bih,  const float* __restrict__ bhh,
    const float* __restrict__ linW, const float* __restrict__ linb,
    float* __restrict__ out)
{
    extern __shared__ char sm[];
    __nv_bfloat16* sWhi = (__nv_bfloat16*)(sm + OFF_DWHI);
    __nv_bfloat16* sWlo = (__nv_bfloat16*)(sm + OFF_DWLO);
    __nv_bfloat16* sHhi = (__nv_bfloat16*)(sm + OFF_DHHI);
    __nv_bfloat16* sHlo = (__nv_bfloat16*)(sm + OFF_DHLO);
    float*         sStg = (float*)(sm + OFF_DSTG);
    float*         sPrt = (float*)(sm + OFF_DPRT);

    __shared__ float s_dec[16][3];
    __shared__ float s_o0[16];

    const int jt = blockIdx.x & 15;
    const int bt = blockIdx.x >> 4;
    const int grp = 8 + bt;
    const int j0 = jt * 32;
    const int b0 = bt * 16;
    const int tid  = threadIdx.x;
    const int lane = tid & 31;
    const int warp = tid >> 5;
    const int mj   = warp & 1;
    const int kw   = warp >> 1;

    // one-time: convert decoder weights to bf16 hi/lo (grid-strided)
    {
        const int stride4 = DEC_CTAS * 256 * 4;
        const int g4 = (blockIdx.x * 256 + tid) * 4;
        for (int i = g4; i < 4 * WMAT; i += stride4) {
            float4 w = *(const float4*)&Whh[i];
            split_bf16(w.x, g_dWhi[i + 0], g_dWlo[i + 0]);
            split_bf16(w.y, g_dWhi[i + 1], g_dWlo[i + 1]);
            split_bf16(w.z, g_dWhi[i + 2], g_dWlo[i + 2]);
            split_bf16(w.w, g_dWhi[i + 3], g_dWlo[i + 3]);
        }
        for (int i = g4; i < 3 * WMAT; i += stride4) {
            float4 w = *(const float4*)&Wihr[i];
            split_bf16(w.x, g_dWhi[WIHR_OFF + i + 0], g_dWlo[WIHR_OFF + i + 0]);
            split_bf16(w.y, g_dWhi[WIHR_OFF + i + 1], g_dWlo[WIHR_OFF + i + 1]);
            split_bf16(w.z, g_dWhi[WIHR_OFF + i + 2], g_dWlo[WIHR_OFF + i + 2]);
            split_bf16(w.w, g_dWhi[WIHR_OFF + i + 3], g_dWlo[WIHR_OFF + i + 3]);
        }
    }
    if (tid < 16) {
        const float* xr = x + ((b0 + tid) * NT + (NT - 1)) * NIN;
        s_dec[tid][0] = xr[0];
        s_dec[tid][1] = xr[1];
        s_dec[tid][2] = xr[2];
    }
    grid_barrier(DEC_CTAS);

    // initial W prefetch for (t=0, l=0)
    dec_prefetch_W(0, j0, tid, s2u(sWhi), s2u(sWlo));

    const int ag = lane >> 3, ar = lane & 7;
    const uint32_t aOff = (uint32_t)((mj * 16 + (ag & 1) * 8 + ar) * DEHS
                                     + (ag >> 1) * 8 + kw * 256) * 2;
    const uint32_t aHiBase = s2u(sWhi) + aOff;
    const uint32_t aLoBase = s2u(sWlo) + aOff;
    const uint32_t bOff = (uint32_t)(((lane >> 4) * 8 + (lane & 7)) * DEHS
                                     + ((lane >> 3) & 1) * 8 + kw * 256) * 2;
    const uint32_t bHiBase = s2u(sHhi) + bOff;
    const uint32_t bLoBase = s2u(sHlo) + bOff;

    const int sr = tid >> 4;
    const int sj = (tid & 15) * 2;
    const int jl = mj * 16 + (lane >> 2);
    const int bl = (lane & 3) * 2;

    for (int t = 0; t < NTGT; t++) {
        const int p = t & 1;

        if (t > 0) {
            const float* h3 = g_h3[p];
#pragma unroll
            for (int rr = 0; rr < 2; rr++) {
                const int brow = warp * 2 + rr;
                const float* row = h3 + (b0 + brow) * NH;
                float s = 0.f;
#pragma unroll
                for (int i = lane; i < NH; i += 32)
                    s += __ldcg(&row[i]) * linW[i];
#pragma unroll
                for (int o = 16; o; o >>= 1) s += __shfl_xor_sync(0xffffffffu, s, o);
                if (lane == 0) s_o0[brow] = s;
            }
            __syncthreads();
            if (tid < 16) {
                float o0 = s_o0[tid] + linb[0];
                if (jt == 0) out[(b0 + tid) * NTGT + (t - 1)] = o0;
                float s1 = s_dec[tid][0] - o0;
                float s2 = s_dec[tid][1] - s1;
                s_dec[tid][0] = o0;
                s_dec[tid][1] = s1;
                s_dec[tid][2] = s2;
            }
            __syncthreads();
        }

        for (int l = 0; l < 4; l++) {
            const int nk = (l == 0) ? 2 : 4;

            // ---- stage h tiles (needs this phase's barrier-published state) ----
            {
                const int r   = tid >> 4;
                const int c16 = tid & 15;
                const __nv_bfloat16* rhi = g_dhhi[p] + (l * NB + b0 + r) * NH;
                const __nv_bfloat16* rlo = g_dhlo[p] + (l * NB + b0 + r) * NH;
#pragma unroll
                for (int c = c16; c < 64; c += 16) {
                    *(uint4*)(sHhi + r * DEHS + c * 8) = __ldcg((const uint4*)(rhi + c * 8));
                    *(uint4*)(sHlo + r * DEHS + c * 8) = __ldcg((const uint4*)(rlo + c * 8));
                }
                if (l > 0) {
                    const __nv_bfloat16* ihi = g_dhhi[1 - p] + ((l - 1) * NB + b0 + r) * NH;
                    const __nv_bfloat16* ilo = g_dhlo[1 - p] + ((l - 1) * NB + b0 + r) * NH;
#pragma unroll
                    for (int c = c16; c < 64; c += 16) {
                        *(uint4*)(sHhi + r * DEHS + 512 + c * 8) = __ldcg((const uint4*)(ihi + c * 8));
                        *(uint4*)(sHlo + r * DEHS + 512 + c * 8) = __ldcg((const uint4*)(ilo + c * 8));
                    }
                }
            }
            // ---- stage init ----
            {
                float v0 = bih[l * NH + j0 + sj + 0] + bhh[l * NH + j0 + sj + 0];
                float v1 = bih[l * NH + j0 + sj + 1] + bhh[l * NH + j0 + sj + 1];
                if (l == 0) {
                    const float i0 = s_dec[sr][0], i1 = s_dec[sr][1], i2 = s_dec[sr][2];
                    const float* wp = Wih0 + (j0 + sj) * NIN;
                    v0 += i0 * wp[0] + i1 * wp[1] + i2 * wp[2];
                    v1 += i0 * wp[3] + i1 * wp[4] + i2 * wp[5];
                }
                sStg[sr * 36 + sj + 0] = v0;
                sStg[sr * 36 + sj + 1] = v1;
            }
            CP_WAIT0();         // W prefetch complete
            __syncthreads();

            if (kw < nk) {
                float c00 = 0.f, c01 = 0.f, c02 = 0.f, c03 = 0.f;
                float c10 = 0.f, c11 = 0.f, c12 = 0.f, c13 = 0.f;
                uint32_t aHi = aHiBase, aLo = aLoBase, bHi = bHiBase, bLo = bLoBase;
#pragma unroll 4
                for (int kk = 0; kk < 16; kk++) {
                    uint32_t a0, a1, a2, a3, e0, e1, e2, e3;
                    uint32_t r0, r1, r2, r3, f0, f1, f2, f3;
                    LDSM_X4(a0, a1, a2, a3, aHi);
                    LDSM_X4(e0, e1, e2, e3, aLo);
                    LDSM_X4(r0, r1, r2, r3, bHi);
                    LDSM_X4(f0, f1, f2, f3, bLo);
                    MMA_BF16(c00, c01, c02, c03, a0, a1, a2, a3, r0, r1);
                    MMA_BF16(c00, c01, c02, c03, a0, a1, a2, a3, f0, f1);
                    MMA_BF16(c00, c01, c02, c03, e0, e1, e2, e3, r0, r1);
                    MMA_BF16(c10, c11, c12, c13, a0, a1, a2, a3, r2, r3);
                    MMA_BF16(c10, c11, c12, c13, a0, a1, a2, a3, f2, f3);
                    MMA_BF16(c10, c11, c12, c13, e0, e1, e2, e3, r2, r3);
                    aHi += 32; aLo += 32; bHi += 32; bLo += 32;
                }
                float* pp = sPrt + kw * (16 * 36);
                pp[(bl + 0) * 36 + jl]     = c00;
                pp[(bl + 1) * 36 + jl]     = c01;
                pp[(bl + 0) * 36 + jl + 8] = c02;
                pp[(bl + 1) * 36 + jl + 8] = c03;
                pp[(bl + 8) * 36 + jl]     = c10;
                pp[(bl + 9) * 36 + jl]     = c11;
                pp[(bl + 8) * 36 + jl + 8] = c12;
                pp[(bl + 9) * 36 + jl + 8] = c13;
            }
            __syncthreads();    // all LDSM on sW done -> safe to prefetch next W

            // ---- prefetch next phase's W (overlaps epilogue + barrier) ----
            if (!(t == NTGT - 1 && l == 3))
                dec_prefetch_W((l == 3) ? 0 : l + 1, j0, tid, s2u(sWhi), s2u(sWlo));

            // ---- owner reduce + tanh + split store ----
            {
                float v0 = sStg[sr * 36 + sj + 0];
                float v1 = sStg[sr * 36 + sj + 1];
#pragma unroll
                for (int q = 0; q < 4; q++) {
                    if (q < nk) {
                        v0 += sPrt[q * 576 + sr * 36 + sj + 0];
                        v1 += sPrt[q * 576 + sr * 36 + sj + 1];
                    }
                }
                v0 = tanhf(v0); v1 = tanhf(v1);
                __nv_bfloat16 h0, h1, l0b, l1b;
                split_bf16(v0, h0, l0b);
                split_bf16(v1, h1, l1b);
                const int idx = (l * NB + b0 + sr) * NH + j0 + sj;
                uint32_t phi = (uint32_t)__bfloat16_as_ushort(h0) |
                               ((uint32_t)__bfloat16_as_ushort(h1) << 16);
                uint32_t plo = (uint32_t)__bfloat16_as_ushort(l0b) |
                               ((uint32_t)__bfloat16_as_ushort(l1b) << 16);
                *(uint32_t*)(g_dhhi[1 - p] + idx) = phi;
                *(uint32_t*)(g_dhlo[1 - p] + idx) = plo;
                if (l == 3)
                    *(float2*)&g_h3[1 - p][(b0 + sr) * NH + j0 + sj] = make_float2(v0, v1);
            }

            group_barrier(grp, 16);
        }
    }

    {
        const float* h3 = g_h3[NTGT & 1];
#pragma unroll
        for (int rr = 0; rr < 2; rr++) {
            const int brow = warp * 2 + rr;
            const float* row = h3 + (b0 + brow) * NH;
            float s = 0.f;
#pragma unroll
            for (int i = lane; i < NH; i += 32)
                s += __ldcg(&row[i]) * linW[i];
#pragma unroll
            for (int o = 16; o; o >>= 1) s += __shfl_xor_sync(0xffffffffu, s, o);
            if (lane == 0) s_o0[brow] = s;
        }
        __syncthreads();
        if (tid < 16 && jt == 0)
            out[(b0 + tid) * NTGT + (NTGT - 1)] = s_o0[tid] + linb[0];
    }
}

// ---------------------------------------------------------------------------
// Launch sequence (graph-capturable: kernel launches only)
// ---------------------------------------------------------------------------
extern "C" void kernel_launch(void* const* d_in, const int* in_sizes, int n_in,
                              void* d_out, int out_size)
{
    const float* x        = (const float*)d_in[0];
    const float* enc_Wih0 = (const float*)d_in[2];
    const float* enc_Whh0 = (const float*)d_in[3];
    const float* enc_Wih1 = (const float*)d_in[4];
    const float* enc_Whh1 = (const float*)d_in[5];
    const float* enc_bih  = (const float*)d_in[6];
    const float* enc_bhh  = (const float*)d_in[7];
    const float* dec_Wih0 = (const float*)d_in[8];
    const float* dec_Wihr = (const float*)d_in[9];
    const float* dec_Whh  = (const float*)d_in[10];
    const float* dec_bih  = (const float*)d_in[11];
    const float* dec_bhh  = (const float*)d_in[12];
    const float* lin_W    = (const float*)d_in[13];
    const float* lin_b    = (const float*)d_in[14];
    float* out = (float*)d_out;

    cudaFuncSetAttribute(enc_mma, cudaFuncAttributeMaxDynamicSharedMemorySize,
                         ENC_SMEM);
    cudaFuncSetAttribute(dec_persist, cudaFuncAttributeMaxDynamicSharedMemorySize,
                         DEC_SMEM);
    cudaFuncSetAttribute(xs1_mma, cudaFuncAttributeMaxDynamicSharedMemorySize,
                         XS1_SMEM);

    // Pre-split Wih1 (independent of encoder)
    split_wih1<<<1024, 256>>>(enc_Wih1);

    // Encoder layer 0
    enc_mma<<<ENC_CTAS, 256, ENC_SMEM>>>(x, enc_Wih0, enc_Whh0,
                                         enc_bih, enc_bhh, 0);

    // Layer-1 input terms, tensor cores
    xs1_mma<<<dim3(8, 128, 2), 256, XS1_SMEM>>>(enc_bih, enc_bhh);

    // Encoder layer 1
    enc_mma<<<ENC_CTAS, 256, ENC_SMEM>>>(x, enc_Wih0, enc_Whh1,
                                         enc_bih, enc_bhh, 1);

    // Decoder
    dec_persist<<<DEC_CTAS, 256, DEC_SMEM>>>(x, dec_Wih0, dec_Wihr, dec_Whh,
                                             dec_bih, dec_bhh, lin_W, lin_b, out);
}

// round 11
// speedup vs baseline: 3.6750x; 1.0864x over previous
#include <cuda_runtime.h>
#include <cuda_bf16.h>
#include <cstdint>

// Problem constants
constexpr int NB   = 128;   // batch
constexpr int NT   = 128;   // encoder time steps
constexpr int NIN  = 3;     // input features
constexpr int NH   = 512;   // hidden
constexpr int NTGT = 32;    // decoder steps

constexpr int ENC_CTAS = 256;   // 2 dirs x 8 bt x 16 jt, 2 CTAs/SM
constexpr int DEC_CTAS = 128;

// ---------------- encoder smem layout (R11: b-tile 16, 2 CTA/SM) ----------
constexpr int EHS      = 520;                   // bf16 row stride (elements)
constexpr int E_UNION  = 32 * EHS * 2;          // 33280 B: W staging (32 rows) / h tile (16 rows)
constexpr int OFF_ESTG = 2 * E_UNION;           // 66560: [16][36] f32 stage
constexpr int OFF_EPRT = OFF_ESTG + 16 * 36 * 4;   // [4][16][36] f32 partials
constexpr int ENC_SMEM = OFF_EPRT + 4 * 16 * 36 * 4;   // 78080 B (x2 = 156 KB/SM)

// ---------------- decoder smem layout (proven R8) ----------------
constexpr int DEHS     = 1032;
constexpr int DW_TILE  = 32 * DEHS * 2;
constexpr int DH_TILE  = 16 * DEHS * 2;
constexpr int OFF_DWHI = 0;
constexpr int OFF_DWLO = OFF_DWHI + DW_TILE;
constexpr int OFF_DHHI = OFF_DWLO + DW_TILE;
constexpr int OFF_DHLO = OFF_DHHI + DH_TILE;
constexpr int OFF_DSTG = OFF_DHLO + DH_TILE;
constexpr int OFF_DPRT = OFF_DSTG + 16 * 36 * 4;
constexpr int DEC_SMEM = OFF_DPRT + 4 * 16 * 36 * 4;

constexpr int WMAT     = NH * NH;
constexpr int WIHR_OFF = 4 * WMAT;

// ---------------- xs1 mma smem layout ----------------
constexpr int XAS    = 72;
constexpr int X_SA   = 128 * XAS * 2;
constexpr int X_SB   = 64 * XAS * 2;
constexpr int XS1_SMEM = 2 * X_SA + 2 * X_SB;

// ---------------------------------------------------------------------------
// Static device scratch
// ---------------------------------------------------------------------------
__device__ __nv_bfloat16 g_l0hi[NT * NB * (2 * NH)];
__device__ __nv_bfloat16 g_l0lo[NT * NB * (2 * NH)];
__device__ __nv_bfloat16 g_xWhi[2 * NH * (2 * NH)];
__device__ __nv_bfloat16 g_xWlo[2 * NH * (2 * NH)];
__device__ float g_xs1[2 * NT * NB * NH];
__device__ __nv_bfloat16 g_hhi[2][2 * NB * NH];
__device__ __nv_bfloat16 g_hlo[2][2 * NB * NH];
__device__ __nv_bfloat16 g_dWhi[7 * WMAT];
__device__ __nv_bfloat16 g_dWlo[7 * WMAT];
__device__ __nv_bfloat16 g_dhhi[2][4 * NB * NH];
__device__ __nv_bfloat16 g_dhlo[2][4 * NB * NH];
__device__ float g_h3[2][NB * NH];
__device__ unsigned g_cnt;
__device__ unsigned g_gen;
__device__ unsigned g_gcnt[16 * 32];
__device__ unsigned g_ggen[16 * 32];

// ---------------------------------------------------------------------------
// Barriers (generation-based, self-resetting, replay-safe)
// ---------------------------------------------------------------------------
__device__ __forceinline__ void grid_barrier(unsigned nctas)
{
    __threadfence();
    __syncthreads();
    if (threadIdx.x == 0) {
        volatile unsigned* genp = &g_gen;
        unsigned gen = *genp;
        if (atomicAdd(&g_cnt, 1u) == nctas - 1) {
            g_cnt = 0;
            __threadfence();
            *genp = gen + 1;
        } else {
            while (*genp == gen) { }
            __threadfence();
        }
    }
    __syncthreads();
}

__device__ __forceinline__ void group_barrier(int g, unsigned n)
{
    __threadfence();
    __syncthreads();
    if (threadIdx.x == 0) {
        volatile unsigned* genp = &g_ggen[g * 32];
        unsigned gen = *genp;
        if (atomicAdd(&g_gcnt[g * 32], 1u) == n - 1) {
            g_gcnt[g * 32] = 0;
            __threadfence();
            *genp = gen + 1;
        } else {
            while (*genp == gen) { }
            __threadfence();
        }
    }
    __syncthreads();
}

// ---------------------------------------------------------------------------
// mma.sync + cp.async helpers
// ---------------------------------------------------------------------------
__device__ __forceinline__ uint32_t s2u(const void* p)
{
    return (uint32_t)__cvta_generic_to_shared(p);
}

#define LDSM_X4(r0, r1, r2, r3, addr)                                          \
    asm volatile("ldmatrix.sync.aligned.m8n8.x4.shared.b16 {%0,%1,%2,%3}, [%4];" \
                 : "=r"(r0), "=r"(r1), "=r"(r2), "=r"(r3) : "r"(addr))

#define MMA_BF16(c0, c1, c2, c3, a0, a1, a2, a3, b0, b1)                       \
    asm volatile("mma.sync.aligned.m16n8k16.row.col.f32.bf16.bf16.f32 "        \
                 "{%0,%1,%2,%3}, {%4,%5,%6,%7}, {%8,%9}, {%0,%1,%2,%3};"       \
                 : "+f"(c0), "+f"(c1), "+f"(c2), "+f"(c3)                      \
                 : "r"(a0), "r"(a1), "r"(a2), "r"(a3), "r"(b0), "r"(b1))

#define CP_ASYNC16(saddr, gptr)                                                \
    asm volatile("cp.async.cg.shared.global [%0], [%1], 16;"                   \
                 :: "r"(saddr), "l"(gptr))
#define CP_COMMIT()  asm volatile("cp.async.commit_group;")
#define CP_WAIT0()   asm volatile("cp.async.wait_group 0;" ::: "memory")

__device__ __forceinline__ void split_bf16(float v, __nv_bfloat16& hi, __nv_bfloat16& lo)
{
    hi = __float2bfloat16(v);
    lo = __float2bfloat16(v - __bfloat162float(hi));
}

// ---------------------------------------------------------------------------
// Pre-split Wih1 into bf16 hi/lo
// ---------------------------------------------------------------------------
__global__ void __launch_bounds__(256) split_wih1(const float* __restrict__ W)
{
    const int i = (blockIdx.x * 256 + threadIdx.x) * 4;
    if (i < 2 * NH * 2 * NH) {
        float4 w = *(const float4*)&W[i];
        split_bf16(w.x, g_xWhi[i + 0], g_xWlo[i + 0]);
        split_bf16(w.y, g_xWhi[i + 1], g_xWlo[i + 1]);
        split_bf16(w.z, g_xWhi[i + 2], g_xWlo[i + 2]);
        split_bf16(w.w, g_xWhi[i + 3], g_xWlo[i + 3]);
    }
}

// ---------------------------------------------------------------------------
// Persistent encoder layer (R11): 256 CTAs, 2/SM, tile 32j x 16b.
// Two independent recurrence chains (fwd/bwd, different b-tiles) co-resident
// per SM: one chain's compute hides the other's barrier + L2 latency.
// W fragments live in registers (R10); smem W-staging region is reused as the
// per-step h tile (16 rows).
// ---------------------------------------------------------------------------
__global__ void __launch_bounds__(256, 2) enc_mma(
    const float* __restrict__ x, const float* __restrict__ Wih0,
    const float* __restrict__ Whh_all, const float* __restrict__ bih,
    const float* __restrict__ bhh, int layer)
{
    extern __shared__ char sm[];
    __nv_bfloat16* sHhi = (__nv_bfloat16*)(sm);             // W-hi staging / h-hi tile
    __nv_bfloat16* sHlo = (__nv_bfloat16*)(sm + E_UNION);   // W-lo staging / h-lo tile
    float*         sStg = (float*)(sm + OFF_ESTG);          // [16][36]
    float*         sPrt = (float*)(sm + OFF_EPRT);          // [4][16][36]

    const int blk = blockIdx.x;
    const int d   = blk >> 7;          // direction
    const int rem = blk & 127;
    const int bt  = rem >> 4;          // batch tile (0..7)
    const int jt  = rem & 15;          // j tile
    const int grp = blk >> 4;          // (d, bt) group of 16 CTAs -> 0..15
    const int b0  = bt * 16;
    const int j0  = jt * 32;
    const int tid = threadIdx.x;
    const int lane = tid & 31;
    const int warp = tid >> 5;
    const int kw   = warp & 3;         // K quarter (128 cols)
    const int mj   = warp >> 2;        // j half (16 rows)

    const float* Whh = Whh_all + d * NH * NH;

    // ---- one-time: stage W tile (32j x 512k, bf16 hi/lo) into smem ----
    {
        const int r  = tid >> 3;
        const int c0 = (tid & 7) * 4;
        for (int k0 = 0; k0 < NH; k0 += 32) {
            float4 w = __ldg((const float4*)&Whh[(j0 + r) * NH + k0 + c0]);
            const int o = r * EHS + k0 + c0;
            split_bf16(w.x, sHhi[o + 0], sHlo[o + 0]);
            split_bf16(w.y, sHhi[o + 1], sHlo[o + 1]);
            split_bf16(w.z, sHhi[o + 2], sHlo[o + 2]);
            split_bf16(w.w, sHhi[o + 3], sHlo[o + 3]);
        }
    }
    __syncthreads();

    // ---- preload A fragments (16j x 128K per warp, hi+lo) into registers ----
    uint32_t aHi[8][4], aLo[8][4];
    {
        const int ag = lane >> 3, ar = lane & 7;
        const uint32_t rowOff = (uint32_t)((mj * 16 + (ag & 1) * 8 + ar) * EHS) * 2;
        const uint32_t colSel = (uint32_t)(kw * 128 + (ag >> 1) * 8) * 2;
#pragma unroll
        for (int q = 0; q < 8; q++) {
            const uint32_t off = rowOff + colSel + q * 32;
            LDSM_X4(aHi[q][0], aHi[q][1], aHi[q][2], aHi[q][3], s2u(sHhi) + off);
            LDSM_X4(aLo[q][0], aLo[q][1], aLo[q][2], aLo[q][3], s2u(sHlo) + off);
        }
    }
    __syncthreads();   // W smem dead; region reused for h (16 rows)

    // ---- B (h) ldmatrix bases: 16-row tile (2 n8 groups x 2 k-halves) ----
    const uint32_t bOff = (uint32_t)(((lane >> 4) * 8 + (lane & 7)) * EHS
                                     + ((lane >> 3) & 1) * 8 + kw * 128) * 2;
    const uint32_t bHiBase = s2u(sHhi) + bOff;
    const uint32_t bLoBase = s2u(sHlo) + bOff;

    // ---- owner slots (2 j per thread) + layer-0 constants ----
    const int sr = tid >> 4;               // b row 0..15
    const int sj = (tid & 15) * 2;         // j pair
    float bias0 = 0.f, bias1 = 0.f, wi[6];
    if (layer == 0) {
        bias0 = bih[d * NH + j0 + sj + 0] + bhh[d * NH + j0 + sj + 0];
        bias1 = bih[d * NH + j0 + sj + 1] + bhh[d * NH + j0 + sj + 1];
        const float* wp = Wih0 + (d * NH + j0 + sj) * NIN;
#pragma unroll
        for (int i = 0; i < 6; i++) wi[i] = wp[i];
    }

    // c-frag positions for partial writes
    const int jl = mj * 16 + (lane >> 2);
    const int bl = (lane & 3) * 2;
    float* pp = sPrt + kw * (16 * 36);

    for (int t = 0; t < NT; t++) {
        const int td = d ? (NT - 1 - t) : t;

        // ---- stage h tile (16 rows, bf16 hi/lo) ----
        if (t > 0) {
            const int p = t & 1;
            const __nv_bfloat16* srcHi = g_hhi[p] + (d * NB + b0) * NH;
            const __nv_bfloat16* srcLo = g_hlo[p] + (d * NB + b0) * NH;
            const int r  = tid >> 4;            // 0..15
            const int cc = tid & 15;            // 16B-chunk base
#pragma unroll
            for (int it = 0; it < 4; it++) {
                const int c16 = cc + it * 16;   // 0..63
                uint4 vh = __ldcg((const uint4*)(srcHi + r * NH) + c16);
                uint4 vl = __ldcg((const uint4*)(srcLo + r * NH) + c16);
                *(uint4*)((char*)sHhi + r * (EHS * 2) + c16 * 16) = vh;
                *(uint4*)((char*)sHlo + r * (EHS * 2) + c16 * 16) = vl;
            }
        }
        // ---- stage init (non-recurrent term, 2 j per owner) ----
        {
            float v0, v1;
            if (layer == 0) {
                const float* xr = x + ((b0 + sr) * NT + td) * NIN;
                const float x0 = xr[0], x1 = xr[1], x2 = xr[2];
                v0 = bias0 + x0 * wi[0] + x1 * wi[1] + x2 * wi[2];
                v1 = bias1 + x0 * wi[3] + x1 * wi[4] + x2 * wi[5];
            } else {
                float2 v = __ldg((const float2*)&g_xs1[((d * NT + td) * NB + b0 + sr) * NH + j0 + sj]);
                v0 = v.x; v1 = v.y;
            }
            sStg[sr * 36 + sj + 0] = v0;
            sStg[sr * 36 + sj + 1] = v1;
        }
        __syncthreads();

        // ---- MMA over this warp's K quarter (A from registers) ----
        if (t > 0) {
            float acc[2][4];
#pragma unroll
            for (int n = 0; n < 2; n++)
#pragma unroll
                for (int q = 0; q < 4; q++) acc[n][q] = 0.f;

#pragma unroll
            for (int q = 0; q < 8; q++) {
                uint32_t r0, r1, r2, r3, f0, f1, f2, f3;
                LDSM_X4(r0, r1, r2, r3, bHiBase + q * 32);
                LDSM_X4(f0, f1, f2, f3, bLoBase + q * 32);
                // b rows 0-7
                MMA_BF16(acc[0][0], acc[0][1], acc[0][2], acc[0][3],
                         aHi[q][0], aHi[q][1], aHi[q][2], aHi[q][3], r0, r1);
                MMA_BF16(acc[0][0], acc[0][1], acc[0][2], acc[0][3],
                         aHi[q][0], aHi[q][1], aHi[q][2], aHi[q][3], f0, f1);
                MMA_BF16(acc[0][0], acc[0][1], acc[0][2], acc[0][3],
                         aLo[q][0], aLo[q][1], aLo[q][2], aLo[q][3], r0, r1);
                // b rows 8-15
                MMA_BF16(acc[1][0], acc[1][1], acc[1][2], acc[1][3],
                         aHi[q][0], aHi[q][1], aHi[q][2], aHi[q][3], r2, r3);
                MMA_BF16(acc[1][0], acc[1][1], acc[1][2], acc[1][3],
                         aHi[q][0], aHi[q][1], aHi[q][2], aHi[q][3], f2, f3);
                MMA_BF16(acc[1][0], acc[1][1], acc[1][2], acc[1][3],
                         aLo[q][0], aLo[q][1], aLo[q][2], aLo[q][3], r2, r3);
            }
            // write kw partials
#pragma unroll
            for (int n = 0; n < 2; n++) {
                pp[(n * 8 + bl + 0) * 36 + jl]     = acc[n][0];
                pp[(n * 8 + bl + 1) * 36 + jl]     = acc[n][1];
                pp[(n * 8 + bl + 0) * 36 + jl + 8] = acc[n][2];
                pp[(n * 8 + bl + 1) * 36 + jl + 8] = acc[n][3];
            }
        }
        __syncthreads();

        // ---- owner epilogue: reduce kw partials + tanh + split + store ----
        {
            float v0 = sStg[sr * 36 + sj + 0];
            float v1 = sStg[sr * 36 + sj + 1];
            if (t > 0) {
#pragma unroll
                for (int q = 0; q < 4; q++) {
                    v0 += sPrt[q * 576 + sr * 36 + sj + 0];
                    v1 += sPrt[q * 576 + sr * 36 + sj + 1];
                }
            }
            v0 = tanhf(v0); v1 = tanhf(v1);

            __nv_bfloat16 h0, h1, l0b, l1b;
            split_bf16(v0, h0, l0b);
            split_bf16(v1, h1, l1b);
            const int p1 = (t + 1) & 1;
            const int gidx = (d * NB + b0 + sr) * NH + j0 + sj;
            uint32_t phi = (uint32_t)__bfloat16_as_ushort(h0) |
                           ((uint32_t)__bfloat16_as_ushort(h1) << 16);
            uint32_t plo = (uint32_t)__bfloat16_as_ushort(l0b) |
                           ((uint32_t)__bfloat16_as_ushort(l1b) << 16);
            *(uint32_t*)(g_hhi[p1] + gidx) = phi;
            *(uint32_t*)(g_hlo[p1] + gidx) = plo;
            if (layer == 0) {
                const int li = (td * NB + b0 + sr) * (2 * NH) + d * NH + j0 + sj;
                *(uint32_t*)(g_l0hi + li) = phi;
                *(uint32_t*)(g_l0lo + li) = plo;
            }
            if (t == NT - 1) {
                const int slot = (layer ? 2 : 0) + d;
                const int di = (slot * NB + b0 + sr) * NH + j0 + sj;
                *(uint32_t*)(g_dhhi[0] + di) = phi;
                *(uint32_t*)(g_dhlo[0] + di) = plo;
            }
        }

        if (t < NT - 1)
            group_barrier(grp, 16);
    }
}

// ---------------------------------------------------------------------------
// xs1 via tensor cores (unchanged from R9)
// ---------------------------------------------------------------------------
__global__ void __launch_bounds__(256) xs1_mma(
    const float* __restrict__ bih, const float* __restrict__ bhh)
{
    extern __shared__ char sm[];
    __nv_bfloat16* sAhi = (__nv_bfloat16*)(sm);
    __nv_bfloat16* sBhi = (__nv_bfloat16*)(sm + 2 * X_SA);

    const int d  = blockIdx.z;
    const int j0 = blockIdx.x * 64;
    const int m0 = blockIdx.y * 128;
    const int tid  = threadIdx.x;
    const int lane = tid & 31;
    const int warp = tid >> 5;
    const int wm = warp & 3;
    const int wn = warp >> 2;

    const int ag = lane >> 3, ar = lane & 7;
    const uint32_t aBase = s2u(sAhi) +
        (uint32_t)((wm * 32 + (ag & 1) * 8 + ar) * XAS + (ag >> 1) * 8) * 2;
    const uint32_t bBase = s2u(sBhi) +
        (uint32_t)((wn * 32 + (lane >> 4) * 8 + (lane & 7)) * XAS + ((lane >> 3) & 1) * 8) * 2;

    float acc[2][4][4];
#pragma unroll
    for (int i = 0; i < 2; i++)
#pragma unroll
        for (int n = 0; n < 4; n++)
#pragma unroll
            for (int q = 0; q < 4; q++) acc[i][n][q] = 0.f;

    const int r  = tid >> 3;
    const int c8 = (tid & 7) * 8;

    for (int k0 = 0; k0 < 2 * NH; k0 += 64) {
        if (k0) __syncthreads();
#pragma unroll
        for (int rr = r; rr < 128; rr += 32) {
            const int gi = (m0 + rr) * (2 * NH) + k0 + c8;
            *(uint4*)((char*)sAhi + (rr * XAS + c8) * 2)        = __ldg((const uint4*)(g_l0hi + gi));
            *(uint4*)((char*)sAhi + X_SA + (rr * XAS + c8) * 2) = __ldg((const uint4*)(g_l0lo + gi));
        }
#pragma unroll
        for (int rr = r; rr < 64; rr += 32) {
            const int gi = (d * NH + j0 + rr) * (2 * NH) + k0 + c8;
            *(uint4*)((char*)sBhi + (rr * XAS + c8) * 2)        = __ldg((const uint4*)(g_xWhi + gi));
            *(uint4*)((char*)sBhi + X_SB + (rr * XAS + c8) * 2) = __ldg((const uint4*)(g_xWlo + gi));
        }
        __syncthreads();

#pragma unroll
        for (int kk = 0; kk < 4; kk++) {
            uint32_t ah[2][4], al[2][4];
#pragma unroll
            for (int mt = 0; mt < 2; mt++) {
                const uint32_t addr = aBase + (uint32_t)(mt * 16 * XAS + kk * 16) * 2;
                LDSM_X4(ah[mt][0], ah[mt][1], ah[mt][2], ah[mt][3], addr);
                LDSM_X4(al[mt][0], al[mt][1], al[mt][2], al[mt][3], addr + X_SA);
            }
#pragma unroll
            for (int np = 0; np < 2; np++) {
                const uint32_t addr = bBase + (uint32_t)(np * 16 * XAS + kk * 16) * 2;
                uint32_t bh0, bh1, bh2, bh3, bl0, bl1, bl2, bl3;
                LDSM_X4(bh0, bh1, bh2, bh3, addr);
                LDSM_X4(bl0, bl1, bl2, bl3, addr + X_SB);
#pragma unroll
                for (int mt = 0; mt < 2; mt++) {
                    float* a0 = acc[mt][np * 2 + 0];
                    float* a1 = acc[mt][np * 2 + 1];
                    MMA_BF16(a0[0], a0[1], a0[2], a0[3],
                             ah[mt][0], ah[mt][1], ah[mt][2], ah[mt][3], bh0, bh1);
                    MMA_BF16(a0[0], a0[1], a0[2], a0[3],
                             ah[mt][0], ah[mt][1], ah[mt][2], ah[mt][3], bl0, bl1);
                    MMA_BF16(a0[0], a0[1], a0[2], a0[3],
                             al[mt][0], al[mt][1], al[mt][2], al[mt][3], bh0, bh1);
                    MMA_BF16(a1[0], a1[1], a1[2], a1[3],
                             ah[mt][0], ah[mt][1], ah[mt][2], ah[mt][3], bh2, bh3);
                    MMA_BF16(a1[0], a1[1], a1[2], a1[3],
                             ah[mt][0], ah[mt][1], ah[mt][2], ah[mt][3], bl2, bl3);
                    MMA_BF16(a1[0], a1[1], a1[2], a1[3],
                             al[mt][0], al[mt][1], al[mt][2], al[mt][3], bh2, bh3);
                }
            }
        }
    }

#pragma unroll
    for (int nt = 0; nt < 4; nt++) {
        const int j = j0 + wn * 32 + nt * 8 + (lane & 3) * 2;
        const float bj0 = __ldg(&bih[(2 + d) * NH + j])     + __ldg(&bhh[(2 + d) * NH + j]);
        const float bj1 = __ldg(&bih[(2 + d) * NH + j + 1]) + __ldg(&bhh[(2 + d) * NH + j + 1]);
#pragma unroll
        for (int mt = 0; mt < 2; mt++) {
            const int m = m0 + wm * 32 + mt * 16 + (lane >> 2);
            *(float2*)&g_xs1[(d * NT * NB + m) * NH + j] =
                make_float2(acc[mt][nt][0] + bj0, acc[mt][nt][1] + bj1);
            *(float2*)&g_xs1[(d * NT * NB + m + 8) * NH + j] =
                make_float2(acc[mt][nt][2] + bj0, acc[mt][nt][3] + bj1);
        }
    }
}

// ---------------------------------------------------------------------------
// Decoder W prefetch (cp.async): no dependency on the group barrier.
// ---------------------------------------------------------------------------
__device__ __forceinline__ void dec_prefetch_W(int l, int j0, int tid,
                                               uint32_t swhi, uint32_t swlo)
{
    const int r  = tid >> 3;
    const int c8 = tid & 7;
    const __nv_bfloat16* shi = g_dWhi + l * WMAT + (j0 + r) * NH;
    const __nv_bfloat16* slo = g_dWlo + l * WMAT + (j0 + r) * NH;
#pragma unroll
    for (int c = c8; c < 64; c += 8) {
        CP_ASYNC16(swhi + (uint32_t)(r * DEHS + c * 8) * 2, shi + c * 8);
        CP_ASYNC16(swlo + (uint32_t)(r * DEHS + c * 8) * 2, slo + c * 8);
    }
    if (l > 0) {
        const __nv_bfloat16* shi2 = g_dWhi + WIHR_OFF + (l - 1) * WMAT + (j0 + r) * NH;
        const __nv_bfloat16* slo2 = g_dWlo + WIHR_OFF + (l - 1) * WMAT + (j0 + r) * NH;
#pragma unroll
        for (int c = c8; c < 64; c += 8) {
            CP_ASYNC16(swhi + (uint32_t)(r * DEHS + 512 + c * 8) * 2, shi2 + c * 8);
            CP_ASYNC16(swlo + (uint32_t)(r * DEHS + 512 + c * 8) * 2, slo2 + c * 8);
        }
    }
    CP_COMMIT();
}

// ---------------------------------------------------------------------------
// Persistent decoder via tensor cores (R10 unchanged)
// ---------------------------------------------------------------------------
__global__ void __launch_bounds__(256) dec_persist(
    const float* __restrict__ x,    const float* __restrict__ Wih0,
    const float* __restrict__ Wihr, const float* __restrict__ Whh,
    const float* __restrict__ bih,  const float* __restrict__ bhh,
    const float* __restrict__ linW, const float* __restrict__ linb,
    float* __restrict__ out)
{
    extern __shared__ char sm[];
    __nv_bfloat16* sWhi = (__nv_bfloat16*)(sm + OFF_DWHI);
    __nv_bfloat16* sWlo = (__nv_bfloat16*)(sm + OFF_DWLO);
    __nv_bfloat16* sHhi = (__nv_bfloat16*)(sm + OFF_DHHI);
    __nv_bfloat16* sHlo = (__nv_bfloat16*)(sm + OFF_DHLO);
    float*         sStg = (float*)(sm + OFF_DSTG);
    float*         sPrt = (float*)(sm + OFF_DPRT);

    __shared__ float s_dec[16][3];
    __shared__ float s_o0[16];

    const int jt = blockIdx.x & 15;
    const int bt = blockIdx.x >> 4;
    const int grp = 8 + bt;
    const int j0 = jt * 32;
    const int b0 = bt * 16;
    const int tid  = threadIdx.x;
    const int lane = tid & 31;
    const int warp = tid >> 5;
    const int mj   = warp & 1;
    const int kw   = warp >> 1;

    {
        const int stride4 = DEC_CTAS * 256 * 4;
        const int g4 = (blockIdx.x * 256 + tid) * 4;
        for (int i = g4; i < 4 * WMAT; i += stride4) {
            float4 w = *(const float4*)&Whh[i];
            split_bf16(w.x, g_dWhi[i + 0], g_dWlo[i + 0]);
            split_bf16(w.y, g_dWhi[i + 1], g_dWlo[i + 1]);
            split_bf16(w.z, g_dWhi[i + 2], g_dWlo[i + 2]);
            split_bf16(w.w, g_dWhi[i + 3], g_dWlo[i + 3]);
        }
        for (int i = g4; i < 3 * WMAT; i += stride4) {
            float4 w = *(const float4*)&Wihr[i];
            split_bf16(w.x, g_dWhi[WIHR_OFF + i + 0], g_dWlo[WIHR_OFF + i + 0]);
            split_bf16(w.y, g_dWhi[WIHR_OFF + i + 1], g_dWlo[WIHR_OFF + i + 1]);
            split_bf16(w.z, g_dWhi[WIHR_OFF + i + 2], g_dWlo[WIHR_OFF + i + 2]);
            split_bf16(w.w, g_dWhi[WIHR_OFF + i + 3], g_dWlo[WIHR_OFF + i + 3]);
        }
    }
    if (tid < 16) {
        const float* xr = x + ((b0 + tid) * NT + (NT - 1)) * NIN;
        s_dec[tid][0] = xr[0];
        s_dec[tid][1] = xr[1];
        s_dec[tid][2] = xr[2];
    }
    grid_barrier(DEC_CTAS);

    dec_prefetch_W(0, j0, tid, s2u(sWhi), s2u(sWlo));

    const int ag = lane >> 3, ar = lane & 7;
    const uint32_t aOff = (uint32_t)((mj * 16 + (ag & 1) * 8 + ar) * DEHS
                                     + (ag >> 1) * 8 + kw * 256) * 2;
    const uint32_t aHiBase = s2u(sWhi) + aOff;
    const uint32_t aLoBase = s2u(sWlo) + aOff;
    const uint32_t bOff = (uint32_t)(((lane >> 4) * 8 + (lane & 7)) * DEHS
                                     + ((lane >> 3) & 1) * 8 + kw * 256) * 2;
    const uint32_t bHiBase = s2u(sHhi) + bOff;
    const uint32_t bLoBase = s2u(sHlo) + bOff;

    const int sr = tid >> 4;
    const int sj = (tid & 15) * 2;
    const int jl = mj * 16 + (lane >> 2);
    const int bl = (lane & 3) * 2;

    for (int t = 0; t < NTGT; t++) {
        const int p = t & 1;

        if (t > 0) {
            const float* h3 = g_h3[p];
#pragma unroll
            for (int rr = 0; rr < 2; rr++) {
                const int brow = warp * 2 + rr;
                const float* row = h3 + (b0 + brow) * NH;
                float s = 0.f;
#pragma unroll
                for (int i = lane; i < NH; i += 32)
                    s += __ldcg(&row[i]) * linW[i];
#pragma unroll
                for (int o = 16; o; o >>= 1) s += __shfl_xor_sync(0xffffffffu, s, o);
                if (lane == 0) s_o0[brow] = s;
            }
            __syncthreads();
            if (tid < 16) {
                float o0 = s_o0[tid] + linb[0];
                if (jt == 0) out[(b0 + tid) * NTGT + (t - 1)] = o0;
                float s1 = s_dec[tid][0] - o0;
                float s2 = s_dec[tid][1] - s1;
                s_dec[tid][0] = o0;
                s_dec[tid][1] = s1;
                s_dec[tid][2] = s2;
            }
            __syncthreads();
        }

        for (int l = 0; l < 4; l++) {
            const int nk = (l == 0) ? 2 : 4;

            {
                const int r   = tid >> 4;
                const int c16 = tid & 15;
                const __nv_bfloat16* rhi = g_dhhi[p] + (l * NB + b0 + r) * NH;
                const __nv_bfloat16* rlo = g_dhlo[p] + (l * NB + b0 + r) * NH;
#pragma unroll
                for (int c = c16; c < 64; c += 16) {
                    *(uint4*)(sHhi + r * DEHS + c * 8) = __ldcg((const uint4*)(rhi + c * 8));
                    *(uint4*)(sHlo + r * DEHS + c * 8) = __ldcg((const uint4*)(rlo + c * 8));
                }
                if (l > 0) {
                    const __nv_bfloat16* ihi = g_dhhi[1 - p] + ((l - 1) * NB + b0 + r) * NH;
                    const __nv_bfloat16* ilo = g_dhlo[1 - p] + ((l - 1) * NB + b0 + r) * NH;
#pragma unroll
                    for (int c = c16; c < 64; c += 16) {
                        *(uint4*)(sHhi + r * DEHS + 512 + c * 8) = __ldcg((const uint4*)(ihi + c * 8));
                        *(uint4*)(sHlo + r * DEHS + 512 + c * 8) = __ldcg((const uint4*)(ilo + c * 8));
                    }
                }
            }
            {
                float v0 = bih[l * NH + j0 + sj + 0] + bhh[l * NH + j0 + sj + 0];
                float v1 = bih[l * NH + j0 + sj + 1] + bhh[l * NH + j0 + sj + 1];
                if (l == 0) {
                    const float i0 = s_dec[sr][0], i1 = s_dec[sr][1], i2 = s_dec[sr][2];
                    const float* wp = Wih0 + (j0 + sj) * NIN;
                    v0 += i0 * wp[0] + i1 * wp[1] + i2 * wp[2];
                    v1 += i0 * wp[3] + i1 * wp[4] + i2 * wp[5];
                }
                sStg[sr * 36 + sj + 0] = v0;
                sStg[sr * 36 + sj + 1] = v1;
            }
            CP_WAIT0();
            __syncthreads();

            if (kw < nk) {
                float c00 = 0.f, c01 = 0.f, c02 = 0.f, c03 = 0.f;
                float c10 = 0.f, c11 = 0.f, c12 = 0.f, c13 = 0.f;
                uint32_t aHi = aHiBase, aLo = aLoBase, bHi = bHiBase, bLo = bLoBase;
#pragma unroll 4
                for (int kk = 0; kk < 16; kk++) {
                    uint32_t a0, a1, a2, a3, e0, e1, e2, e3;
                    uint32_t r0, r1, r2, r3, f0, f1, f2, f3;
                    LDSM_X4(a0, a1, a2, a3, aHi);
                    LDSM_X4(e0, e1, e2, e3, aLo);
                    LDSM_X4(r0, r1, r2, r3, bHi);
                    LDSM_X4(f0, f1, f2, f3, bLo);
                    MMA_BF16(c00, c01, c02, c03, a0, a1, a2, a3, r0, r1);
                    MMA_BF16(c00, c01, c02, c03, a0, a1, a2, a3, f0, f1);
                    MMA_BF16(c00, c01, c02, c03, e0, e1, e2, e3, r0, r1);
                    MMA_BF16(c10, c11, c12, c13, a0, a1, a2, a3, r2, r3);
                    MMA_BF16(c10, c11, c12, c13, a0, a1, a2, a3, f2, f3);
                    MMA_BF16(c10, c11, c12, c13, e0, e1, e2, e3, r2, r3);
                    aHi += 32; aLo += 32; bHi += 32; bLo += 32;
                }
                float* pp = sPrt + kw * (16 * 36);
                pp[(bl + 0) * 36 + jl]     = c00;
                pp[(bl + 1) * 36 + jl]     = c01;
                pp[(bl + 0) * 36 + jl + 8] = c02;
                pp[(bl + 1) * 36 + jl + 8] = c03;
                pp[(bl + 8) * 36 + jl]     = c10;
                pp[(bl + 9) * 36 + jl]     = c11;
                pp[(bl + 8) * 36 + jl + 8] = c12;
                pp[(bl + 9) * 36 + jl + 8] = c13;
            }
            __syncthreads();

            if (!(t == NTGT - 1 && l == 3))
                dec_prefetch_W((l == 3) ? 0 : l + 1, j0, tid, s2u(sWhi), s2u(sWlo));

            {
                float v0 = sStg[sr * 36 + sj + 0];
                float v1 = sStg[sr * 36 + sj + 1];
#pragma unroll
                for (int q = 0; q < 4; q++) {
                    if (q < nk) {
                        v0 += sPrt[q * 576 + sr * 36 + sj + 0];
                        v1 += sPrt[q * 576 + sr * 36 + sj + 1];
                    }
                }
                v0 = tanhf(v0); v1 = tanhf(v1);
                __nv_bfloat16 h0, h1, l0b, l1b;
                split_bf16(v0, h0, l0b);
                split_bf16(v1, h1, l1b);
                const int idx = (l * NB + b0 + sr) * NH + j0 + sj;
                uint32_t phi = (uint32_t)__bfloat16_as_ushort(h0) |
                               ((uint32_t)__bfloat16_as_ushort(h1) << 16);
                uint32_t plo = (uint32_t)__bfloat16_as_ushort(l0b) |
                               ((uint32_t)__bfloat16_as_ushort(l1b) << 16);
                *(uint32_t*)(g_dhhi[1 - p] + idx) = phi;
                *(uint32_t*)(g_dhlo[1 - p] + idx) = plo;
                if (l == 3)
                    *(float2*)&g_h3[1 - p][(b0 + sr) * NH + j0 + sj] = make_float2(v0, v1);
            }

            group_barrier(grp, 16);
        }
    }

    {
        const float* h3 = g_h3[NTGT & 1];
#pragma unroll
        for (int rr = 0; rr < 2; rr++) {
            const int brow = warp * 2 + rr;
            const float* row = h3 + (b0 + brow) * NH;
            float s = 0.f;
#pragma unroll
            for (int i = lane; i < NH; i += 32)
                s += __ldcg(&row[i]) * linW[i];
#pragma unroll
            for (int o = 16; o; o >>= 1) s += __shfl_xor_sync(0xffffffffu, s, o);
            if (lane == 0) s_o0[brow] = s;
        }
        __syncthreads();
        if (tid < 16 && jt == 0)
            out[(b0 + tid) * NTGT + (NTGT - 1)] = s_o0[tid] + linb[0];
    }
}

// ---------------------------------------------------------------------------
// Launch sequence (graph-capturable: kernel launches only)
// ---------------------------------------------------------------------------
extern "C" void kernel_launch(void* const* d_in, const int* in_sizes, int n_in,
                              void* d_out, int out_size)
{
    const float* x        = (const float*)d_in[0];
    const float* enc_Wih0 = (const float*)d_in[2];
    const float* enc_Whh0 = (const float*)d_in[3];
    const float* enc_Wih1 = (const float*)d_in[4];
    const float* enc_Whh1 = (const float*)d_in[5];
    const float* enc_bih  = (const float*)d_in[6];
    const float* enc_bhh  = (const float*)d_in[7];
    const float* dec_Wih0 = (const float*)d_in[8];
    const float* dec_Wihr = (const float*)d_in[9];
    const float* dec_Whh  = (const float*)d_in[10];
    const float* dec_bih  = (const float*)d_in[11];
    const float* dec_bhh  = (const float*)d_in[12];
    const float* lin_W    = (const float*)d_in[13];
    const float* lin_b    = (const float*)d_in[14];
    float* out = (float*)d_out;

    cudaFuncSetAttribute(enc_mma, cudaFuncAttributeMaxDynamicSharedMemorySize,
                         ENC_SMEM);
    cudaFuncSetAttribute(dec_persist, cudaFuncAttributeMaxDynamicSharedMemorySize,
                         DEC_SMEM);
    cudaFuncSetAttribute(xs1_mma, cudaFuncAttributeMaxDynamicSharedMemorySize,
                         XS1_SMEM);

    // Pre-split Wih1 (independent of encoder)
    split_wih1<<<1024, 256>>>(enc_Wih1);

    // Encoder layer 0: 256 CTAs, 2 per SM (paired chains hide barrier latency)
    enc_mma<<<ENC_CTAS, 256, ENC_SMEM>>>(x, enc_Wih0, enc_Whh0,
                                         enc_bih, enc_bhh, 0);

    // Layer-1 input terms, tensor cores
    xs1_mma<<<dim3(8, 128, 2), 256, XS1_SMEM>>>(enc_bih, enc_bhh);

    // Encoder layer 1
    enc_mma<<<ENC_CTAS, 256, ENC_SMEM>>>(x, enc_Wih0, enc_Whh1,
                                         enc_bih, enc_bhh, 1);

    // Decoder
    dec_persist<<<DEC_CTAS, 256, DEC_SMEM>>>(x, dec_Wih0, dec_Wihr, dec_Whh,
                                             dec_bih, dec_bhh, lin_W, lin_b, out);
}

// round 12
// speedup vs baseline: 3.7553x; 1.0218x over previous
#include <cuda_runtime.h>
#include <cuda_bf16.h>
#include <cstdint>

// Problem constants
constexpr int NB   = 128;   // batch
constexpr int NT   = 128;   // encoder time steps
constexpr int NIN  = 3;     // input features
constexpr int NH   = 512;   // hidden
constexpr int NTGT = 32;    // decoder steps

constexpr int ENC_CTAS = 256;   // 2 dirs x 8 bt x 16 jt, 2 CTAs/SM
constexpr int DEC_CTAS = 128;

// ---------------- encoder smem layout (R11) ----------------
constexpr int EHS      = 520;                   // bf16 row stride (elements)
constexpr int E_UNION  = 32 * EHS * 2;          // W staging (32 rows) / h tile (16 rows)
constexpr int OFF_ESTG = 2 * E_UNION;           // [16][36] f32 stage
constexpr int OFF_EPRT = OFF_ESTG + 16 * 36 * 4;   // [4][16][36] f32 partials
constexpr int ENC_SMEM = OFF_EPRT + 4 * 16 * 36 * 4;   // 78080 B

// ---------------- decoder smem layout (R8) ----------------
constexpr int DEHS     = 1032;
constexpr int DW_TILE  = 32 * DEHS * 2;
constexpr int DH_TILE  = 16 * DEHS * 2;
constexpr int OFF_DWHI = 0;
constexpr int OFF_DWLO = OFF_DWHI + DW_TILE;
constexpr int OFF_DHHI = OFF_DWLO + DW_TILE;
constexpr int OFF_DHLO = OFF_DHHI + DH_TILE;
constexpr int OFF_DSTG = OFF_DHLO + DH_TILE;
constexpr int OFF_DPRT = OFF_DSTG + 16 * 36 * 4;
constexpr int DEC_SMEM = OFF_DPRT + 4 * 16 * 36 * 4;

constexpr int WMAT     = NH * NH;
constexpr int WIHR_OFF = 4 * WMAT;

// ---------------- xs1 mma smem layout (R12: double-buffered) ----------------
constexpr int XAS     = 72;
constexpr int X_SA    = 128 * XAS * 2;           // 18432 B per A buffer (hi or lo)
constexpr int X_SB    = 64 * XAS * 2;            // 9216 B per B buffer
constexpr int X_STAGE = 2 * X_SA + 2 * X_SB;     // 55296 B one pipeline stage
constexpr int XS1_SMEM = 2 * X_STAGE;            // 110592 B

// ---------------------------------------------------------------------------
// Static device scratch
// ---------------------------------------------------------------------------
__device__ __nv_bfloat16 g_l0hi[NT * NB * (2 * NH)];
__device__ __nv_bfloat16 g_l0lo[NT * NB * (2 * NH)];
__device__ __nv_bfloat16 g_xWhi[2 * NH * (2 * NH)];
__device__ __nv_bfloat16 g_xWlo[2 * NH * (2 * NH)];
__device__ float g_xs1[2 * NT * NB * NH];
__device__ __nv_bfloat16 g_hhi[2][2 * NB * NH];
__device__ __nv_bfloat16 g_hlo[2][2 * NB * NH];
__device__ __nv_bfloat16 g_dWhi[7 * WMAT];
__device__ __nv_bfloat16 g_dWlo[7 * WMAT];
__device__ __nv_bfloat16 g_dhhi[2][4 * NB * NH];
__device__ __nv_bfloat16 g_dhlo[2][4 * NB * NH];
__device__ float g_h3[2][NB * NH];
__device__ unsigned g_cnt;
__device__ unsigned g_gen;
__device__ unsigned g_gcnt[16 * 32];
__device__ unsigned g_ggen[16 * 32];

// ---------------------------------------------------------------------------
// Barriers (generation-based, self-resetting, replay-safe)
// ---------------------------------------------------------------------------
__device__ __forceinline__ void grid_barrier(unsigned nctas)
{
    __threadfence();
    __syncthreads();
    if (threadIdx.x == 0) {
        volatile unsigned* genp = &g_gen;
        unsigned gen = *genp;
        if (atomicAdd(&g_cnt, 1u) == nctas - 1) {
            g_cnt = 0;
            __threadfence();
            *genp = gen + 1;
        } else {
            while (*genp == gen) { }
            __threadfence();
        }
    }
    __syncthreads();
}

__device__ __forceinline__ void group_barrier(int g, unsigned n)
{
    __threadfence();
    __syncthreads();
    if (threadIdx.x == 0) {
        volatile unsigned* genp = &g_ggen[g * 32];
        unsigned gen = *genp;
        if (atomicAdd(&g_gcnt[g * 32], 1u) == n - 1) {
            g_gcnt[g * 32] = 0;
            __threadfence();
            *genp = gen + 1;
        } else {
            while (*genp == gen) { }
            __threadfence();
        }
    }
    __syncthreads();
}

// ---------------------------------------------------------------------------
// mma.sync + cp.async helpers
// ---------------------------------------------------------------------------
__device__ __forceinline__ uint32_t s2u(const void* p)
{
    return (uint32_t)__cvta_generic_to_shared(p);
}

#define LDSM_X4(r0, r1, r2, r3, addr)                                          \
    asm volatile("ldmatrix.sync.aligned.m8n8.x4.shared.b16 {%0,%1,%2,%3}, [%4];" \
                 : "=r"(r0), "=r"(r1), "=r"(r2), "=r"(r3) : "r"(addr))

#define MMA_BF16(c0, c1, c2, c3, a0, a1, a2, a3, b0, b1)                       \
    asm volatile("mma.sync.aligned.m16n8k16.row.col.f32.bf16.bf16.f32 "        \
                 "{%0,%1,%2,%3}, {%4,%5,%6,%7}, {%8,%9}, {%0,%1,%2,%3};"       \
                 : "+f"(c0), "+f"(c1), "+f"(c2), "+f"(c3)                      \
                 : "r"(a0), "r"(a1), "r"(a2), "r"(a3), "r"(b0), "r"(b1))

#define CP_ASYNC16(saddr, gptr)                                                \
    asm volatile("cp.async.cg.shared.global [%0], [%1], 16;"                   \
                 :: "r"(saddr), "l"(gptr))
#define CP_COMMIT()  asm volatile("cp.async.commit_group;")
#define CP_WAIT0()   asm volatile("cp.async.wait_group 0;" ::: "memory")
#define CP_WAIT1()   asm volatile("cp.async.wait_group 1;" ::: "memory")

__device__ __forceinline__ void split_bf16(float v, __nv_bfloat16& hi, __nv_bfloat16& lo)
{
    hi = __float2bfloat16(v);
    lo = __float2bfloat16(v - __bfloat162float(hi));
}

// ---------------------------------------------------------------------------
// Pre-split Wih1 into bf16 hi/lo
// ---------------------------------------------------------------------------
__global__ void __launch_bounds__(256) split_wih1(const float* __restrict__ W)
{
    const int i = (blockIdx.x * 256 + threadIdx.x) * 4;
    if (i < 2 * NH * 2 * NH) {
        float4 w = *(const float4*)&W[i];
        split_bf16(w.x, g_xWhi[i + 0], g_xWlo[i + 0]);
        split_bf16(w.y, g_xWhi[i + 1], g_xWlo[i + 1]);
        split_bf16(w.z, g_xWhi[i + 2], g_xWlo[i + 2]);
        split_bf16(w.w, g_xWhi[i + 3], g_xWlo[i + 3]);
    }
}

// ---------------------------------------------------------------------------
// Persistent encoder layer (R12): R11 + stage-init hoisted pre-barrier.
// ---------------------------------------------------------------------------
__global__ void __launch_bounds__(256, 2) enc_mma(
    const float* __restrict__ x, const float* __restrict__ Wih0,
    const float* __restrict__ Whh_all, const float* __restrict__ bih,
    const float* __restrict__ bhh, int layer)
{
    extern __shared__ char sm[];
    __nv_bfloat16* sHhi = (__nv_bfloat16*)(sm);             // W-hi staging / h-hi tile
    __nv_bfloat16* sHlo = (__nv_bfloat16*)(sm + E_UNION);   // W-lo staging / h-lo tile
    float*         sStg = (float*)(sm + OFF_ESTG);          // [16][36]
    float*         sPrt = (float*)(sm + OFF_EPRT);          // [4][16][36]

    const int blk = blockIdx.x;
    const int d   = blk >> 7;          // direction
    const int rem = blk & 127;
    const int bt  = rem >> 4;          // batch tile (0..7)
    const int jt  = rem & 15;          // j tile
    const int grp = blk >> 4;          // (d, bt) group of 16 CTAs -> 0..15
    const int b0  = bt * 16;
    const int j0  = jt * 32;
    const int tid = threadIdx.x;
    const int lane = tid & 31;
    const int warp = tid >> 5;
    const int kw   = warp & 3;         // K quarter (128 cols)
    const int mj   = warp >> 2;        // j half (16 rows)

    const float* Whh = Whh_all + d * NH * NH;

    // ---- one-time: stage W tile (32j x 512k, bf16 hi/lo) into smem ----
    {
        const int r  = tid >> 3;
        const int c0 = (tid & 7) * 4;
        for (int k0 = 0; k0 < NH; k0 += 32) {
            float4 w = __ldg((const float4*)&Whh[(j0 + r) * NH + k0 + c0]);
            const int o = r * EHS + k0 + c0;
            split_bf16(w.x, sHhi[o + 0], sHlo[o + 0]);
            split_bf16(w.y, sHhi[o + 1], sHlo[o + 1]);
            split_bf16(w.z, sHhi[o + 2], sHlo[o + 2]);
            split_bf16(w.w, sHhi[o + 3], sHlo[o + 3]);
        }
    }
    __syncthreads();

    // ---- preload A fragments (16j x 128K per warp, hi+lo) into registers ----
    uint32_t aHi[8][4], aLo[8][4];
    {
        const int ag = lane >> 3, ar = lane & 7;
        const uint32_t rowOff = (uint32_t)((mj * 16 + (ag & 1) * 8 + ar) * EHS) * 2;
        const uint32_t colSel = (uint32_t)(kw * 128 + (ag >> 1) * 8) * 2;
#pragma unroll
        for (int q = 0; q < 8; q++) {
            const uint32_t off = rowOff + colSel + q * 32;
            LDSM_X4(aHi[q][0], aHi[q][1], aHi[q][2], aHi[q][3], s2u(sHhi) + off);
            LDSM_X4(aLo[q][0], aLo[q][1], aLo[q][2], aLo[q][3], s2u(sHlo) + off);
        }
    }

    // ---- B (h) ldmatrix bases ----
    const uint32_t bOff = (uint32_t)(((lane >> 4) * 8 + (lane & 7)) * EHS
                                     + ((lane >> 3) & 1) * 8 + kw * 128) * 2;
    const uint32_t bHiBase = s2u(sHhi) + bOff;
    const uint32_t bLoBase = s2u(sHlo) + bOff;

    // ---- owner slots (2 j per thread) + layer-0 constants ----
    const int sr = tid >> 4;               // b row 0..15
    const int sj = (tid & 15) * 2;         // j pair
    float bias0 = 0.f, bias1 = 0.f, wi[6];
    if (layer == 0) {
        bias0 = bih[d * NH + j0 + sj + 0] + bhh[d * NH + j0 + sj + 0];
        bias1 = bih[d * NH + j0 + sj + 1] + bhh[d * NH + j0 + sj + 1];
        const float* wp = Wih0 + (d * NH + j0 + sj) * NIN;
#pragma unroll
        for (int i = 0; i < 6; i++) wi[i] = wp[i];
    }

    // ---- stage init for t = 0 (written before the loop) ----
    {
        const int td0 = d ? (NT - 1) : 0;
        float v0, v1;
        if (layer == 0) {
            const float* xr = x + ((b0 + sr) * NT + td0) * NIN;
            const float x0 = xr[0], x1 = xr[1], x2 = xr[2];
            v0 = bias0 + x0 * wi[0] + x1 * wi[1] + x2 * wi[2];
            v1 = bias1 + x0 * wi[3] + x1 * wi[4] + x2 * wi[5];
        } else {
            float2 v = __ldg((const float2*)&g_xs1[((d * NT + td0) * NB + b0 + sr) * NH + j0 + sj]);
            v0 = v.x; v1 = v.y;
        }
        sStg[sr * 36 + sj + 0] = v0;
        sStg[sr * 36 + sj + 1] = v1;
    }
    __syncthreads();   // W smem dead (A frags loaded); reuse region for h

    // c-frag positions for partial writes
    const int jl = mj * 16 + (lane >> 2);
    const int bl = (lane & 3) * 2;
    float* pp = sPrt + kw * (16 * 36);

    for (int t = 0; t < NT; t++) {
        const int td = d ? (NT - 1 - t) : t;

        // ---- stage h tile (16 rows, bf16 hi/lo) ----
        if (t > 0) {
            const int p = t & 1;
            const __nv_bfloat16* srcHi = g_hhi[p] + (d * NB + b0) * NH;
            const __nv_bfloat16* srcLo = g_hlo[p] + (d * NB + b0) * NH;
            const int r  = tid >> 4;            // 0..15
            const int cc = tid & 15;            // 16B-chunk base
#pragma unroll
            for (int it = 0; it < 4; it++) {
                const int c16 = cc + it * 16;   // 0..63
                uint4 vh = __ldcg((const uint4*)(srcHi + r * NH) + c16);
                uint4 vl = __ldcg((const uint4*)(srcLo + r * NH) + c16);
                *(uint4*)((char*)sHhi + r * (EHS * 2) + c16 * 16) = vh;
                *(uint4*)((char*)sHlo + r * (EHS * 2) + c16 * 16) = vl;
            }
        }
        __syncthreads();

        // ---- MMA over this warp's K quarter (A from registers) ----
        if (t > 0) {
            float acc[2][4];
#pragma unroll
            for (int n = 0; n < 2; n++)
#pragma unroll
                for (int q = 0; q < 4; q++) acc[n][q] = 0.f;

#pragma unroll
            for (int q = 0; q < 8; q++) {
                uint32_t r0, r1, r2, r3, f0, f1, f2, f3;
                LDSM_X4(r0, r1, r2, r3, bHiBase + q * 32);
                LDSM_X4(f0, f1, f2, f3, bLoBase + q * 32);
                MMA_BF16(acc[0][0], acc[0][1], acc[0][2], acc[0][3],
                         aHi[q][0], aHi[q][1], aHi[q][2], aHi[q][3], r0, r1);
                MMA_BF16(acc[0][0], acc[0][1], acc[0][2], acc[0][3],
                         aHi[q][0], aHi[q][1], aHi[q][2], aHi[q][3], f0, f1);
                MMA_BF16(acc[0][0], acc[0][1], acc[0][2], acc[0][3],
                         aLo[q][0], aLo[q][1], aLo[q][2], aLo[q][3], r0, r1);
                MMA_BF16(acc[1][0], acc[1][1], acc[1][2], acc[1][3],
                         aHi[q][0], aHi[q][1], aHi[q][2], aHi[q][3], r2, r3);
                MMA_BF16(acc[1][0], acc[1][1], acc[1][2], acc[1][3],
                         aHi[q][0], aHi[q][1], aHi[q][2], aHi[q][3], f2, f3);
                MMA_BF16(acc[1][0], acc[1][1], acc[1][2], acc[1][3],
                         aLo[q][0], aLo[q][1], aLo[q][2], aLo[q][3], r2, r3);
            }
#pragma unroll
            for (int n = 0; n < 2; n++) {
                pp[(n * 8 + bl + 0) * 36 + jl]     = acc[n][0];
                pp[(n * 8 + bl + 1) * 36 + jl]     = acc[n][1];
                pp[(n * 8 + bl + 0) * 36 + jl + 8] = acc[n][2];
                pp[(n * 8 + bl + 1) * 36 + jl + 8] = acc[n][3];
            }
        }
        __syncthreads();

        // ---- owner epilogue: reduce + tanh + split + store + NEXT init ----
        {
            float v0 = sStg[sr * 36 + sj + 0];
            float v1 = sStg[sr * 36 + sj + 1];
            if (t > 0) {
#pragma unroll
                for (int q = 0; q < 4; q++) {
                    v0 += sPrt[q * 576 + sr * 36 + sj + 0];
                    v1 += sPrt[q * 576 + sr * 36 + sj + 1];
                }
            }
            v0 = tanhf(v0); v1 = tanhf(v1);

            __nv_bfloat16 h0, h1, l0b, l1b;
            split_bf16(v0, h0, l0b);
            split_bf16(v1, h1, l1b);
            const int p1 = (t + 1) & 1;
            const int gidx = (d * NB + b0 + sr) * NH + j0 + sj;
            uint32_t phi = (uint32_t)__bfloat16_as_ushort(h0) |
                           ((uint32_t)__bfloat16_as_ushort(h1) << 16);
            uint32_t plo = (uint32_t)__bfloat16_as_ushort(l0b) |
                           ((uint32_t)__bfloat16_as_ushort(l1b) << 16);
            *(uint32_t*)(g_hhi[p1] + gidx) = phi;
            *(uint32_t*)(g_hlo[p1] + gidx) = plo;
            if (layer == 0) {
                const int li = (td * NB + b0 + sr) * (2 * NH) + d * NH + j0 + sj;
                *(uint32_t*)(g_l0hi + li) = phi;
                *(uint32_t*)(g_l0lo + li) = plo;
            }
            if (t == NT - 1) {
                const int slot = (layer ? 2 : 0) + d;
                const int di = (slot * NB + b0 + sr) * NH + j0 + sj;
                *(uint32_t*)(g_dhhi[0] + di) = phi;
                *(uint32_t*)(g_dhlo[0] + di) = plo;
            }

            // next-step init (barrier-independent; overlaps the barrier wait).
            // sStg slot is thread-exclusive: safe without extra sync.
            if (t < NT - 1) {
                const int td2 = d ? (NT - 2 - t) : (t + 1);
                float n0, n1;
                if (layer == 0) {
                    const float* xr = x + ((b0 + sr) * NT + td2) * NIN;
                    const float x0 = xr[0], x1 = xr[1], x2 = xr[2];
                    n0 = bias0 + x0 * wi[0] + x1 * wi[1] + x2 * wi[2];
                    n1 = bias1 + x0 * wi[3] + x1 * wi[4] + x2 * wi[5];
                } else {
                    float2 v = __ldg((const float2*)&g_xs1[((d * NT + td2) * NB + b0 + sr) * NH + j0 + sj]);
                    n0 = v.x; n1 = v.y;
                }
                sStg[sr * 36 + sj + 0] = n0;
                sStg[sr * 36 + sj + 1] = n1;
            }
        }

        if (t < NT - 1)
            group_barrier(grp, 16);
    }
}

// ---------------------------------------------------------------------------
// xs1 via tensor cores (R12): 2-stage cp.async pipelined GEMM.
// Tile 128m x 64n, K chunks of 64 (16 chunks), double-buffered stages.
// ---------------------------------------------------------------------------
__device__ __forceinline__ void xs1_stage(uint32_t sbase, int d, int j0, int m0,
                                          int k0, int tid)
{
    const int r  = tid >> 3;
    const int c8 = (tid & 7) * 8;
#pragma unroll
    for (int rr = r; rr < 128; rr += 32) {
        const int gi = (m0 + rr) * (2 * NH) + k0 + c8;
        CP_ASYNC16(sbase + (uint32_t)((rr * XAS + c8) * 2),        g_l0hi + gi);
        CP_ASYNC16(sbase + (uint32_t)(X_SA + (rr * XAS + c8) * 2), g_l0lo + gi);
    }
#pragma unroll
    for (int rr = r; rr < 64; rr += 32) {
        const int gi = (d * NH + j0 + rr) * (2 * NH) + k0 + c8;
        CP_ASYNC16(sbase + (uint32_t)(2 * X_SA + (rr * XAS + c8) * 2),        g_xWhi + gi);
        CP_ASYNC16(sbase + (uint32_t)(2 * X_SA + X_SB + (rr * XAS + c8) * 2), g_xWlo + gi);
    }
    CP_COMMIT();
}

__global__ void __launch_bounds__(256) xs1_mma(
    const float* __restrict__ bih, const float* __restrict__ bhh)
{
    extern __shared__ char sm[];
    const uint32_t smBase = s2u(sm);

    const int d  = blockIdx.z;
    const int j0 = blockIdx.x * 64;
    const int m0 = blockIdx.y * 128;
    const int tid  = threadIdx.x;
    const int lane = tid & 31;
    const int warp = tid >> 5;
    const int wm = warp & 3;
    const int wn = warp >> 2;

    const int ag = lane >> 3, ar = lane & 7;
    const uint32_t aOff = (uint32_t)((wm * 32 + (ag & 1) * 8 + ar) * XAS + (ag >> 1) * 8) * 2;
    const uint32_t bOff = (uint32_t)(2 * X_SA) +
        (uint32_t)((wn * 32 + (lane >> 4) * 8 + (lane & 7)) * XAS + ((lane >> 3) & 1) * 8) * 2;

    float acc[2][4][4];
#pragma unroll
    for (int i = 0; i < 2; i++)
#pragma unroll
        for (int n = 0; n < 4; n++)
#pragma unroll
            for (int q = 0; q < 4; q++) acc[i][n][q] = 0.f;

    // prologue: stage chunk 0
    xs1_stage(smBase, d, j0, m0, 0, tid);

    for (int c = 0; c < 16; c++) {
        if (c < 15)
            xs1_stage(smBase + ((c + 1) & 1) * X_STAGE, d, j0, m0, (c + 1) * 64, tid);
        if (c < 15) { CP_WAIT1(); } else { CP_WAIT0(); }
        __syncthreads();

        const uint32_t aBase = smBase + (c & 1) * X_STAGE + aOff;
        const uint32_t bBase = smBase + (c & 1) * X_STAGE + bOff;

#pragma unroll
        for (int kk = 0; kk < 4; kk++) {
            uint32_t ah[2][4], al[2][4];
#pragma unroll
            for (int mt = 0; mt < 2; mt++) {
                const uint32_t addr = aBase + (uint32_t)(mt * 16 * XAS + kk * 16) * 2;
                LDSM_X4(ah[mt][0], ah[mt][1], ah[mt][2], ah[mt][3], addr);
                LDSM_X4(al[mt][0], al[mt][1], al[mt][2], al[mt][3], addr + X_SA);
            }
#pragma unroll
            for (int np = 0; np < 2; np++) {
                const uint32_t addr = bBase + (uint32_t)(np * 16 * XAS + kk * 16) * 2;
                uint32_t bh0, bh1, bh2, bh3, bl0, bl1, bl2, bl3;
                LDSM_X4(bh0, bh1, bh2, bh3, addr);
                LDSM_X4(bl0, bl1, bl2, bl3, addr + X_SB);
#pragma unroll
                for (int mt = 0; mt < 2; mt++) {
                    float* a0 = acc[mt][np * 2 + 0];
                    float* a1 = acc[mt][np * 2 + 1];
                    MMA_BF16(a0[0], a0[1], a0[2], a0[3],
                             ah[mt][0], ah[mt][1], ah[mt][2], ah[mt][3], bh0, bh1);
                    MMA_BF16(a0[0], a0[1], a0[2], a0[3],
                             ah[mt][0], ah[mt][1], ah[mt][2], ah[mt][3], bl0, bl1);
                    MMA_BF16(a0[0], a0[1], a0[2], a0[3],
                             al[mt][0], al[mt][1], al[mt][2], al[mt][3], bh0, bh1);
                    MMA_BF16(a1[0], a1[1], a1[2], a1[3],
                             ah[mt][0], ah[mt][1], ah[mt][2], ah[mt][3], bh2, bh3);
                    MMA_BF16(a1[0], a1[1], a1[2], a1[3],
                             ah[mt][0], ah[mt][1], ah[mt][2], ah[mt][3], bl2, bl3);
                    MMA_BF16(a1[0], a1[1], a1[2], a1[3],
                             al[mt][0], al[mt][1], al[mt][2], al[mt][3], bh2, bh3);
                }
            }
        }
        __syncthreads();   // buffer (c&1) free for reuse at c+2
    }

#pragma unroll
    for (int nt = 0; nt < 4; nt++) {
        const int j = j0 + wn * 32 + nt * 8 + (lane & 3) * 2;
        const float bj0 = __ldg(&bih[(2 + d) * NH + j])     + __ldg(&bhh[(2 + d) * NH + j]);
        const float bj1 = __ldg(&bih[(2 + d) * NH + j + 1]) + __ldg(&bhh[(2 + d) * NH + j + 1]);
#pragma unroll
        for (int mt = 0; mt < 2; mt++) {
            const int m = m0 + wm * 32 + mt * 16 + (lane >> 2);
            *(float2*)&g_xs1[(d * NT * NB + m) * NH + j] =
                make_float2(acc[mt][nt][0] + bj0, acc[mt][nt][1] + bj1);
            *(float2*)&g_xs1[(d * NT * NB + m + 8) * NH + j] =
                make_float2(acc[mt][nt][2] + bj0, acc[mt][nt][3] + bj1);
        }
    }
}

// ---------------------------------------------------------------------------
// Decoder W prefetch (cp.async): no dependency on the group barrier.
// ---------------------------------------------------------------------------
__device__ __forceinline__ void dec_prefetch_W(int l, int j0, int tid,
                                               uint32_t swhi, uint32_t swlo)
{
    const int r  = tid >> 3;
    const int c8 = tid & 7;
    const __nv_bfloat16* shi = g_dWhi + l * WMAT + (j0 + r) * NH;
    const __nv_bfloat16* slo = g_dWlo + l * WMAT + (j0 + r) * NH;
#pragma unroll
    for (int c = c8; c < 64; c += 8) {
        CP_ASYNC16(swhi + (uint32_t)(r * DEHS + c * 8) * 2, shi + c * 8);
        CP_ASYNC16(swlo + (uint32_t)(r * DEHS + c * 8) * 2, slo + c * 8);
    }
    if (l > 0) {
        const __nv_bfloat16* shi2 = g_dWhi + WIHR_OFF + (l - 1) * WMAT + (j0 + r) * NH;
        const __nv_bfloat16* slo2 = g_dWlo + WIHR_OFF + (l - 1) * WMAT + (j0 + r) * NH;
#pragma unroll
        for (int c = c8; c < 64; c += 8) {
            CP_ASYNC16(swhi + (uint32_t)(r * DEHS + 512 + c * 8) * 2, shi2 + c * 8);
            CP_ASYNC16(swlo + (uint32_t)(r * DEHS + 512 + c * 8) * 2, slo2 + c * 8);
        }
    }
    CP_COMMIT();
}

// ---------------------------------------------------------------------------
// Persistent decoder via tensor cores (R12: h staged via cp.async)
// ---------------------------------------------------------------------------
__global__ void __launch_bounds__(256) dec_persist(
    const float* __restrict__ x,    const float* __restrict__ Wih0,
    const float* __restrict__ Wihr, const float* __restrict__ Whh,
    const float* __restrict__ bih,  const float* __restrict__ bhh,
    const float* __restrict__ linW, const float* __restrict__ linb,
    float* __restrict__ out)
{
    extern __shared__ char sm[];
    __nv_bfloat16* sWhi = (__nv_bfloat16*)(sm + OFF_DWHI);
    __nv_bfloat16* sWlo = (__nv_bfloat16*)(sm + OFF_DWLO);
    __nv_bfloat16* sHhi = (__nv_bfloat16*)(sm + OFF_DHHI);
    __nv_bfloat16* sHlo = (__nv_bfloat16*)(sm + OFF_DHLO);
    float*         sStg = (float*)(sm + OFF_DSTG);
    float*         sPrt = (float*)(sm + OFF_DPRT);

    __shared__ float s_dec[16][3];
    __shared__ float s_o0[16];

    const int jt = blockIdx.x & 15;
    const int bt = blockIdx.x >> 4;
    const int grp = 8 + bt;
    const int j0 = jt * 32;
    const int b0 = bt * 16;
    const int tid  = threadIdx.x;
    const int lane = tid & 31;
    const int warp = tid >> 5;
    const int mj   = warp & 1;
    const int kw   = warp >> 1;

    {
        const int stride4 = DEC_CTAS * 256 * 4;
        const int g4 = (blockIdx.x * 256 + tid) * 4;
        for (int i = g4; i < 4 * WMAT; i += stride4) {
            float4 w = *(const float4*)&Whh[i];
            split_bf16(w.x, g_dWhi[i + 0], g_dWlo[i + 0]);
            split_bf16(w.y, g_dWhi[i + 1], g_dWlo[i + 1]);
            split_bf16(w.z, g_dWhi[i + 2], g_dWlo[i + 2]);
            split_bf16(w.w, g_dWhi[i + 3], g_dWlo[i + 3]);
        }
        for (int i = g4; i < 3 * WMAT; i += stride4) {
            float4 w = *(const float4*)&Wihr[i];
            split_bf16(w.x, g_dWhi[WIHR_OFF + i + 0], g_dWlo[WIHR_OFF + i + 0]);
            split_bf16(w.y, g_dWhi[WIHR_OFF + i + 1], g_dWlo[WIHR_OFF + i + 1]);
            split_bf16(w.z, g_dWhi[WIHR_OFF + i + 2], g_dWlo[WIHR_OFF + i + 2]);
            split_bf16(w.w, g_dWhi[WIHR_OFF + i + 3], g_dWlo[WIHR_OFF + i + 3]);
        }
    }
    if (tid < 16) {
        const float* xr = x + ((b0 + tid) * NT + (NT - 1)) * NIN;
        s_dec[tid][0] = xr[0];
        s_dec[tid][1] = xr[1];
        s_dec[tid][2] = xr[2];
    }
    grid_barrier(DEC_CTAS);

    dec_prefetch_W(0, j0, tid, s2u(sWhi), s2u(sWlo));

    const int ag = lane >> 3, ar = lane & 7;
    const uint32_t aOff = (uint32_t)((mj * 16 + (ag & 1) * 8 + ar) * DEHS
                                     + (ag >> 1) * 8 + kw * 256) * 2;
    const uint32_t aHiBase = s2u(sWhi) + aOff;
    const uint32_t aLoBase = s2u(sWlo) + aOff;
    const uint32_t bOff = (uint32_t)(((lane >> 4) * 8 + (lane & 7)) * DEHS
                                     + ((lane >> 3) & 1) * 8 + kw * 256) * 2;
    const uint32_t bHiBase = s2u(sHhi) + bOff;
    const uint32_t bLoBase = s2u(sHlo) + bOff;

    const int sr = tid >> 4;
    const int sj = (tid & 15) * 2;
    const int jl = mj * 16 + (lane >> 2);
    const int bl = (lane & 3) * 2;

    for (int t = 0; t < NTGT; t++) {
        const int p = t & 1;

        if (t > 0) {
            const float* h3 = g_h3[p];
#pragma unroll
            for (int rr = 0; rr < 2; rr++) {
                const int brow = warp * 2 + rr;
                const float* row = h3 + (b0 + brow) * NH;
                float s = 0.f;
#pragma unroll
                for (int i = lane; i < NH; i += 32)
                    s += __ldcg(&row[i]) * linW[i];
#pragma unroll
                for (int o = 16; o; o >>= 1) s += __shfl_xor_sync(0xffffffffu, s, o);
                if (lane == 0) s_o0[brow] = s;
            }
            __syncthreads();
            if (tid < 16) {
                float o0 = s_o0[tid] + linb[0];
                if (jt == 0) out[(b0 + tid) * NTGT + (t - 1)] = o0;
                float s1 = s_dec[tid][0] - o0;
                float s2 = s_dec[tid][1] - s1;
                s_dec[tid][0] = o0;
                s_dec[tid][1] = s1;
                s_dec[tid][2] = s2;
            }
            __syncthreads();
        }

        for (int l = 0; l < 4; l++) {
            const int nk = (l == 0) ? 2 : 4;

            // ---- stage h tiles via cp.async (joins W prefetch wait) ----
            {
                const int r   = tid >> 4;
                const int c16 = tid & 15;
                const __nv_bfloat16* rhi = g_dhhi[p] + (l * NB + b0 + r) * NH;
                const __nv_bfloat16* rlo = g_dhlo[p] + (l * NB + b0 + r) * NH;
#pragma unroll
                for (int c = c16; c < 64; c += 16) {
                    CP_ASYNC16(s2u(sHhi) + (uint32_t)(r * DEHS + c * 8) * 2, rhi + c * 8);
                    CP_ASYNC16(s2u(sHlo) + (uint32_t)(r * DEHS + c * 8) * 2, rlo + c * 8);
                }
                if (l > 0) {
                    const __nv_bfloat16* ihi = g_dhhi[1 - p] + ((l - 1) * NB + b0 + r) * NH;
                    const __nv_bfloat16* ilo = g_dhlo[1 - p] + ((l - 1) * NB + b0 + r) * NH;
#pragma unroll
                    for (int c = c16; c < 64; c += 16) {
                        CP_ASYNC16(s2u(sHhi) + (uint32_t)(r * DEHS + 512 + c * 8) * 2, ihi + c * 8);
                        CP_ASYNC16(s2u(sHlo) + (uint32_t)(r * DEHS + 512 + c * 8) * 2, ilo + c * 8);
                    }
                }
                CP_COMMIT();
            }
            // ---- stage init ----
            {
                float v0 = bih[l * NH + j0 + sj + 0] + bhh[l * NH + j0 + sj + 0];
                float v1 = bih[l * NH + j0 + sj + 1] + bhh[l * NH + j0 + sj + 1];
                if (l == 0) {
                    const float i0 = s_dec[sr][0], i1 = s_dec[sr][1], i2 = s_dec[sr][2];
                    const float* wp = Wih0 + (j0 + sj) * NIN;
                    v0 += i0 * wp[0] + i1 * wp[1] + i2 * wp[2];
                    v1 += i0 * wp[3] + i1 * wp[4] + i2 * wp[5];
                }
                sStg[sr * 36 + sj + 0] = v0;
                sStg[sr * 36 + sj + 1] = v1;
            }
            CP_WAIT0();         // W prefetch + h stage complete
            __syncthreads();

            if (kw < nk) {
                float c00 = 0.f, c01 = 0.f, c02 = 0.f, c03 = 0.f;
                float c10 = 0.f, c11 = 0.f, c12 = 0.f, c13 = 0.f;
                uint32_t aHi = aHiBase, aLo = aLoBase, bHi = bHiBase, bLo = bLoBase;
#pragma unroll 4
                for (int kk = 0; kk < 16; kk++) {
                    uint32_t a0, a1, a2, a3, e0, e1, e2, e3;
                    uint32_t r0, r1, r2, r3, f0, f1, f2, f3;
                    LDSM_X4(a0, a1, a2, a3, aHi);
                    LDSM_X4(e0, e1, e2, e3, aLo);
                    LDSM_X4(r0, r1, r2, r3, bHi);
                    LDSM_X4(f0, f1, f2, f3, bLo);
                    MMA_BF16(c00, c01, c02, c03, a0, a1, a2, a3, r0, r1);
                    MMA_BF16(c00, c01, c02, c03, a0, a1, a2, a3, f0, f1);
                    MMA_BF16(c00, c01, c02, c03, e0, e1, e2, e3, r0, r1);
                    MMA_BF16(c10, c11, c12, c13, a0, a1, a2, a3, r2, r3);
                    MMA_BF16(c10, c11, c12, c13, a0, a1, a2, a3, f2, f3);
                    MMA_BF16(c10, c11, c12, c13, e0, e1, e2, e3, r2, r3);
                    aHi += 32; aLo += 32; bHi += 32; bLo += 32;
                }
                float* pp = sPrt + kw * (16 * 36);
                pp[(bl + 0) * 36 + jl]     = c00;
                pp[(bl + 1) * 36 + jl]     = c01;
                pp[(bl + 0) * 36 + jl + 8] = c02;
                pp[(bl + 1) * 36 + jl + 8] = c03;
                pp[(bl + 8) * 36 + jl]     = c10;
                pp[(bl + 9) * 36 + jl]     = c11;
                pp[(bl + 8) * 36 + jl + 8] = c12;
                pp[(bl + 9) * 36 + jl + 8] = c13;
            }
            __syncthreads();    // all LDSM on sW done -> safe to prefetch next W

            if (!(t == NTGT - 1 && l == 3))
                dec_prefetch_W((l == 3) ? 0 : l + 1, j0, tid, s2u(sWhi), s2u(sWlo));

            {
                float v0 = sStg[sr * 36 + sj + 0];
                float v1 = sStg[sr * 36 + sj + 1];
#pragma unroll
                for (int q = 0; q < 4; q++) {
                    if (q < nk) {
                        v0 += sPrt[q * 576 + sr * 36 + sj + 0];
                        v1 += sPrt[q * 576 + sr * 36 + sj + 1];
                    }
                }
                v0 = tanhf(v0); v1 = tanhf(v1);
                __nv_bfloat16 h0, h1, l0b, l1b;
                split_bf16(v0, h0, l0b);
                split_bf16(v1, h1, l1b);
                const int idx = (l * NB + b0 + sr) * NH + j0 + sj;
                uint32_t phi = (uint32_t)__bfloat16_as_ushort(h0) |
                               ((uint32_t)__bfloat16_as_ushort(h1) << 16);
                uint32_t plo = (uint32_t)__bfloat16_as_ushort(l0b) |
                               ((uint32_t)__bfloat16_as_ushort(l1b) << 16);
                *(uint32_t*)(g_dhhi[1 - p] + idx) = phi;
                *(uint32_t*)(g_dhlo[1 - p] + idx) = plo;
                if (l == 3)
                    *(float2*)&g_h3[1 - p][(b0 + sr) * NH + j0 + sj] = make_float2(v0, v1);
            }

            group_barrier(grp, 16);
        }
    }

    {
        const float* h3 = g_h3[NTGT & 1];
#pragma unroll
        for (int rr = 0; rr < 2; rr++) {
            const int brow = warp * 2 + rr;
            const float* row = h3 + (b0 + brow) * NH;
            float s = 0.f;
#pragma unroll
            for (int i = lane; i < NH; i += 32)
                s += __ldcg(&row[i]) * linW[i];
#pragma unroll
            for (int o = 16; o; o >>= 1) s += __shfl_xor_sync(0xffffffffu, s, o);
            if (lane == 0) s_o0[brow] = s;
        }
        __syncthreads();
        if (tid < 16 && jt == 0)
            out[(b0 + tid) * NTGT + (NTGT - 1)] = s_o0[tid] + linb[0];
    }
}

// ---------------------------------------------------------------------------
// Launch sequence (graph-capturable: kernel launches only)
// ---------------------------------------------------------------------------
extern "C" void kernel_launch(void* const* d_in, const int* in_sizes, int n_in,
                              void* d_out, int out_size)
{
    const float* x        = (const float*)d_in[0];
    const float* enc_Wih0 = (const float*)d_in[2];
    const float* enc_Whh0 = (const float*)d_in[3];
    const float* enc_Wih1 = (const float*)d_in[4];
    const float* enc_Whh1 = (const float*)d_in[5];
    const float* enc_bih  = (const float*)d_in[6];
    const float* enc_bhh  = (const float*)d_in[7];
    const float* dec_Wih0 = (const float*)d_in[8];
    const float* dec_Wihr = (const float*)d_in[9];
    const float* dec_Whh  = (const float*)d_in[10];
    const float* dec_bih  = (const float*)d_in[11];
    const float* dec_bhh  = (const float*)d_in[12];
    const float* lin_W    = (const float*)d_in[13];
    const float* lin_b    = (const float*)d_in[14];
    float* out = (float*)d_out;

    cudaFuncSetAttribute(enc_mma, cudaFuncAttributeMaxDynamicSharedMemorySize,
                         ENC_SMEM);
    cudaFuncSetAttribute(dec_persist, cudaFuncAttributeMaxDynamicSharedMemorySize,
                         DEC_SMEM);
    cudaFuncSetAttribute(xs1_mma, cudaFuncAttributeMaxDynamicSharedMemorySize,
                         XS1_SMEM);

    // Pre-split Wih1 (independent of encoder)
    split_wih1<<<1024, 256>>>(enc_Wih1);

    // Encoder layer 0: 256 CTAs, 2 per SM (paired chains hide barrier latency)
    enc_mma<<<ENC_CTAS, 256, ENC_SMEM>>>(x, enc_Wih0, enc_Whh0,
                                         enc_bih, enc_bhh, 0);

    // Layer-1 input terms, pipelined tensor-core GEMM
    xs1_mma<<<dim3(8, 128, 2), 256, XS1_SMEM>>>(enc_bih, enc_bhh);

    // Encoder layer 1
    enc_mma<<<ENC_CTAS, 256, ENC_SMEM>>>(x, enc_Wih0, enc_Whh1,
                                         enc_bih, enc_bhh, 1);

    // Decoder
    dec_persist<<<DEC_CTAS, 256, DEC_SMEM>>>(x, dec_Wih0, dec_Wihr, dec_Whh,
                                             dec_bih, dec_bhh, lin_W, lin_b, out);
}

// round 13
// speedup vs baseline: 3.8395x; 1.0224x over previous
#include <cuda_runtime.h>
#include <cuda_bf16.h>
#include <cstdint>

// Problem constants
constexpr int NB   = 128;   // batch
constexpr int NT   = 128;   // encoder time steps
constexpr int NIN  = 3;     // input features
constexpr int NH   = 512;   // hidden
constexpr int NTGT = 32;    // decoder steps

constexpr int ENC_CTAS = 256;   // 2 dirs x 8 bt x 16 jt, 2 CTAs/SM
constexpr int DEC_CTAS = 128;

// ---------------- encoder smem layout (R11) ----------------
constexpr int EHS      = 520;                   // bf16 row stride (elements)
constexpr int E_UNION  = 32 * EHS * 2;          // W staging (32 rows) / h tile (16 rows)
constexpr int OFF_ESTG = 2 * E_UNION;           // [16][36] f32 stage
constexpr int OFF_EPRT = OFF_ESTG + 16 * 36 * 4;   // [4][16][36] f32 partials
constexpr int ENC_SMEM = OFF_EPRT + 4 * 16 * 36 * 4;   // 78080 B

// ---------------- decoder smem layout (R8) ----------------
constexpr int DEHS     = 1032;
constexpr int DW_TILE  = 32 * DEHS * 2;
constexpr int DH_TILE  = 16 * DEHS * 2;
constexpr int OFF_DWHI = 0;
constexpr int OFF_DWLO = OFF_DWHI + DW_TILE;
constexpr int OFF_DHHI = OFF_DWLO + DW_TILE;
constexpr int OFF_DHLO = OFF_DHHI + DH_TILE;
constexpr int OFF_DSTG = OFF_DHLO + DH_TILE;
constexpr int OFF_DPRT = OFF_DSTG + 16 * 36 * 4;
constexpr int DEC_SMEM = OFF_DPRT + 4 * 16 * 36 * 4;

constexpr int WMAT     = NH * NH;
constexpr int WIHR_OFF = 4 * WMAT;

// ---------------- xs1 mma smem layout (R12: double-buffered) ----------------
constexpr int XAS     = 72;
constexpr int X_SA    = 128 * XAS * 2;
constexpr int X_SB    = 64 * XAS * 2;
constexpr int X_STAGE = 2 * X_SA + 2 * X_SB;
constexpr int XS1_SMEM = 2 * X_STAGE;

// ---------------------------------------------------------------------------
// Static device scratch
// ---------------------------------------------------------------------------
__device__ __nv_bfloat16 g_l0hi[NT * NB * (2 * NH)];
__device__ __nv_bfloat16 g_l0lo[NT * NB * (2 * NH)];
__device__ __nv_bfloat16 g_xWhi[2 * NH * (2 * NH)];
__device__ __nv_bfloat16 g_xWlo[2 * NH * (2 * NH)];
__device__ float g_xs1[2 * NT * NB * NH];
__device__ __nv_bfloat16 g_hhi[2][2 * NB * NH];
__device__ __nv_bfloat16 g_hlo[2][2 * NB * NH];
__device__ __nv_bfloat16 g_dWhi[7 * WMAT];
__device__ __nv_bfloat16 g_dWlo[7 * WMAT];
__device__ __nv_bfloat16 g_dhhi[2][4 * NB * NH];
__device__ __nv_bfloat16 g_dhlo[2][4 * NB * NH];
__device__ float g_o0p[2][16 * NB];          // per-jt partial output dots [parity][jt*NB + b]
__device__ unsigned g_cnt;
__device__ unsigned g_gen;
__device__ unsigned g_gcnt[16 * 32];
__device__ unsigned g_ggen[16 * 32];

// ---------------------------------------------------------------------------
// Barriers: generation-based, self-resetting, replay-safe.
// Leader-only cumulative fence: __syncthreads() orders all CTA threads'
// writes before the leader; the leader's fence.gpu then makes them visible
// chip-wide (PTX cumulativity). Acquire side mirrored.
// ---------------------------------------------------------------------------
__device__ __forceinline__ void grid_barrier(unsigned nctas)
{
    __syncthreads();
    if (threadIdx.x == 0) {
        __threadfence();
        volatile unsigned* genp = &g_gen;
        unsigned gen = *genp;
        if (atomicAdd(&g_cnt, 1u) == nctas - 1) {
            g_cnt = 0;
            __threadfence();
            *genp = gen + 1;
        } else {
            while (*genp == gen) { }
            __threadfence();
        }
    }
    __syncthreads();
}

__device__ __forceinline__ void group_barrier(int g, unsigned n)
{
    __syncthreads();
    if (threadIdx.x == 0) {
        __threadfence();
        volatile unsigned* genp = &g_ggen[g * 32];
        unsigned gen = *genp;
        if (atomicAdd(&g_gcnt[g * 32], 1u) == n - 1) {
            g_gcnt[g * 32] = 0;
            __threadfence();
            *genp = gen + 1;
        } else {
            while (*genp == gen) { }
            __threadfence();
        }
    }
    __syncthreads();
}

// ---------------------------------------------------------------------------
// mma.sync + cp.async helpers
// ---------------------------------------------------------------------------
__device__ __forceinline__ uint32_t s2u(const void* p)
{
    return (uint32_t)__cvta_generic_to_shared(p);
}

#define LDSM_X4(r0, r1, r2, r3, addr)                                          \
    asm volatile("ldmatrix.sync.aligned.m8n8.x4.shared.b16 {%0,%1,%2,%3}, [%4];" \
                 : "=r"(r0), "=r"(r1), "=r"(r2), "=r"(r3) : "r"(addr))

#define MMA_BF16(c0, c1, c2, c3, a0, a1, a2, a3, b0, b1)                       \
    asm volatile("mma.sync.aligned.m16n8k16.row.col.f32.bf16.bf16.f32 "        \
                 "{%0,%1,%2,%3}, {%4,%5,%6,%7}, {%8,%9}, {%0,%1,%2,%3};"       \
                 : "+f"(c0), "+f"(c1), "+f"(c2), "+f"(c3)                      \
                 : "r"(a0), "r"(a1), "r"(a2), "r"(a3), "r"(b0), "r"(b1))

#define CP_ASYNC16(saddr, gptr)                                                \
    asm volatile("cp.async.cg.shared.global [%0], [%1], 16;"                   \
                 :: "r"(saddr), "l"(gptr))
#define CP_COMMIT()  asm volatile("cp.async.commit_group;")
#define CP_WAIT0()   asm volatile("cp.async.wait_group 0;" ::: "memory")
#define CP_WAIT1()   asm volatile("cp.async.wait_group 1;" ::: "memory")

__device__ __forceinline__ void split_bf16(float v, __nv_bfloat16& hi, __nv_bfloat16& lo)
{
    hi = __float2bfloat16(v);
    lo = __float2bfloat16(v - __bfloat162float(hi));
}

// ---------------------------------------------------------------------------
// Pre-split Wih1 into bf16 hi/lo
// ---------------------------------------------------------------------------
__global__ void __launch_bounds__(256) split_wih1(const float* __restrict__ W)
{
    const int i = (blockIdx.x * 256 + threadIdx.x) * 4;
    if (i < 2 * NH * 2 * NH) {
        float4 w = *(const float4*)&W[i];
        split_bf16(w.x, g_xWhi[i + 0], g_xWlo[i + 0]);
        split_bf16(w.y, g_xWhi[i + 1], g_xWlo[i + 1]);
        split_bf16(w.z, g_xWhi[i + 2], g_xWlo[i + 2]);
        split_bf16(w.w, g_xWhi[i + 3], g_xWlo[i + 3]);
    }
}

// ---------------------------------------------------------------------------
// Persistent encoder layer (R13): R12 + cp.async h staging + light barrier.
// ---------------------------------------------------------------------------
__global__ void __launch_bounds__(256, 2) enc_mma(
    const float* __restrict__ x, const float* __restrict__ Wih0,
    const float* __restrict__ Whh_all, const float* __restrict__ bih,
    const float* __restrict__ bhh, int layer)
{
    extern __shared__ char sm[];
    __nv_bfloat16* sHhi = (__nv_bfloat16*)(sm);             // W-hi staging / h-hi tile
    __nv_bfloat16* sHlo = (__nv_bfloat16*)(sm + E_UNION);   // W-lo staging / h-lo tile
    float*         sStg = (float*)(sm + OFF_ESTG);          // [16][36]
    float*         sPrt = (float*)(sm + OFF_EPRT);          // [4][16][36]

    const int blk = blockIdx.x;
    const int d   = blk >> 7;
    const int rem = blk & 127;
    const int bt  = rem >> 4;
    const int jt  = rem & 15;
    const int grp = blk >> 4;
    const int b0  = bt * 16;
    const int j0  = jt * 32;
    const int tid = threadIdx.x;
    const int lane = tid & 31;
    const int warp = tid >> 5;
    const int kw   = warp & 3;
    const int mj   = warp >> 2;

    const float* Whh = Whh_all + d * NH * NH;

    // ---- one-time: stage W tile (bf16 hi/lo) into smem ----
    {
        const int r  = tid >> 3;
        const int c0 = (tid & 7) * 4;
        for (int k0 = 0; k0 < NH; k0 += 32) {
            float4 w = __ldg((const float4*)&Whh[(j0 + r) * NH + k0 + c0]);
            const int o = r * EHS + k0 + c0;
            split_bf16(w.x, sHhi[o + 0], sHlo[o + 0]);
            split_bf16(w.y, sHhi[o + 1], sHlo[o + 1]);
            split_bf16(w.z, sHhi[o + 2], sHlo[o + 2]);
            split_bf16(w.w, sHhi[o + 3], sHlo[o + 3]);
        }
    }
    __syncthreads();

    // ---- preload A fragments into registers ----
    uint32_t aHi[8][4], aLo[8][4];
    {
        const int ag = lane >> 3, ar = lane & 7;
        const uint32_t rowOff = (uint32_t)((mj * 16 + (ag & 1) * 8 + ar) * EHS) * 2;
        const uint32_t colSel = (uint32_t)(kw * 128 + (ag >> 1) * 8) * 2;
#pragma unroll
        for (int q = 0; q < 8; q++) {
            const uint32_t off = rowOff + colSel + q * 32;
            LDSM_X4(aHi[q][0], aHi[q][1], aHi[q][2], aHi[q][3], s2u(sHhi) + off);
            LDSM_X4(aLo[q][0], aLo[q][1], aLo[q][2], aLo[q][3], s2u(sHlo) + off);
        }
    }

    // ---- B (h) ldmatrix bases ----
    const uint32_t bOff = (uint32_t)(((lane >> 4) * 8 + (lane & 7)) * EHS
                                     + ((lane >> 3) & 1) * 8 + kw * 128) * 2;
    const uint32_t bHiBase = s2u(sHhi) + bOff;
    const uint32_t bLoBase = s2u(sHlo) + bOff;

    // ---- owner slots + layer-0 constants ----
    const int sr = tid >> 4;
    const int sj = (tid & 15) * 2;
    float bias0 = 0.f, bias1 = 0.f, wi[6];
    if (layer == 0) {
        bias0 = bih[d * NH + j0 + sj + 0] + bhh[d * NH + j0 + sj + 0];
        bias1 = bih[d * NH + j0 + sj + 1] + bhh[d * NH + j0 + sj + 1];
        const float* wp = Wih0 + (d * NH + j0 + sj) * NIN;
#pragma unroll
        for (int i = 0; i < 6; i++) wi[i] = wp[i];
    }

    // ---- stage init for t = 0 ----
    {
        const int td0 = d ? (NT - 1) : 0;
        float v0, v1;
        if (layer == 0) {
            const float* xr = x + ((b0 + sr) * NT + td0) * NIN;
            const float x0 = xr[0], x1 = xr[1], x2 = xr[2];
            v0 = bias0 + x0 * wi[0] + x1 * wi[1] + x2 * wi[2];
            v1 = bias1 + x0 * wi[3] + x1 * wi[4] + x2 * wi[5];
        } else {
            float2 v = __ldg((const float2*)&g_xs1[((d * NT + td0) * NB + b0 + sr) * NH + j0 + sj]);
            v0 = v.x; v1 = v.y;
        }
        sStg[sr * 36 + sj + 0] = v0;
        sStg[sr * 36 + sj + 1] = v1;
    }
    __syncthreads();   // W smem dead; region reused for h

    const int jl = mj * 16 + (lane >> 2);
    const int bl = (lane & 3) * 2;
    float* pp = sPrt + kw * (16 * 36);

    for (int t = 0; t < NT; t++) {
        const int td = d ? (NT - 1 - t) : t;

        // ---- stage h tile via cp.async (no register round-trip) ----
        if (t > 0) {
            const int p = t & 1;
            const __nv_bfloat16* srcHi = g_hhi[p] + (d * NB + b0) * NH;
            const __nv_bfloat16* srcLo = g_hlo[p] + (d * NB + b0) * NH;
            const int r  = tid >> 4;            // 0..15
            const int cc = tid & 15;
#pragma unroll
            for (int it = 0; it < 4; it++) {
                const int c16 = cc + it * 16;   // 0..63
                CP_ASYNC16(s2u(sHhi) + (uint32_t)(r * (EHS * 2) + c16 * 16), (const uint4*)(srcHi + r * NH) + c16);
                CP_ASYNC16(s2u(sHlo) + (uint32_t)(r * (EHS * 2) + c16 * 16), (const uint4*)(srcLo + r * NH) + c16);
            }
            CP_COMMIT();
            CP_WAIT0();
        }
        __syncthreads();

        // ---- MMA over this warp's K quarter (A from registers) ----
        if (t > 0) {
            float acc[2][4];
#pragma unroll
            for (int n = 0; n < 2; n++)
#pragma unroll
                for (int q = 0; q < 4; q++) acc[n][q] = 0.f;

#pragma unroll
            for (int q = 0; q < 8; q++) {
                uint32_t r0, r1, r2, r3, f0, f1, f2, f3;
                LDSM_X4(r0, r1, r2, r3, bHiBase + q * 32);
                LDSM_X4(f0, f1, f2, f3, bLoBase + q * 32);
                MMA_BF16(acc[0][0], acc[0][1], acc[0][2], acc[0][3],
                         aHi[q][0], aHi[q][1], aHi[q][2], aHi[q][3], r0, r1);
                MMA_BF16(acc[0][0], acc[0][1], acc[0][2], acc[0][3],
                         aHi[q][0], aHi[q][1], aHi[q][2], aHi[q][3], f0, f1);
                MMA_BF16(acc[0][0], acc[0][1], acc[0][2], acc[0][3],
                         aLo[q][0], aLo[q][1], aLo[q][2], aLo[q][3], r0, r1);
                MMA_BF16(acc[1][0], acc[1][1], acc[1][2], acc[1][3],
                         aHi[q][0], aHi[q][1], aHi[q][2], aHi[q][3], r2, r3);
                MMA_BF16(acc[1][0], acc[1][1], acc[1][2], acc[1][3],
                         aHi[q][0], aHi[q][1], aHi[q][2], aHi[q][3], f2, f3);
                MMA_BF16(acc[1][0], acc[1][1], acc[1][2], acc[1][3],
                         aLo[q][0], aLo[q][1], aLo[q][2], aLo[q][3], r2, r3);
            }
#pragma unroll
            for (int n = 0; n < 2; n++) {
                pp[(n * 8 + bl + 0) * 36 + jl]     = acc[n][0];
                pp[(n * 8 + bl + 1) * 36 + jl]     = acc[n][1];
                pp[(n * 8 + bl + 0) * 36 + jl + 8] = acc[n][2];
                pp[(n * 8 + bl + 1) * 36 + jl + 8] = acc[n][3];
            }
        }
        __syncthreads();

        // ---- owner epilogue: reduce + tanh + split + store + next init ----
        {
            float v0 = sStg[sr * 36 + sj + 0];
            float v1 = sStg[sr * 36 + sj + 1];
            if (t > 0) {
#pragma unroll
                for (int q = 0; q < 4; q++) {
                    v0 += sPrt[q * 576 + sr * 36 + sj + 0];
                    v1 += sPrt[q * 576 + sr * 36 + sj + 1];
                }
            }
            v0 = tanhf(v0); v1 = tanhf(v1);

            __nv_bfloat16 h0, h1, l0b, l1b;
            split_bf16(v0, h0, l0b);
            split_bf16(v1, h1, l1b);
            const int p1 = (t + 1) & 1;
            const int gidx = (d * NB + b0 + sr) * NH + j0 + sj;
            uint32_t phi = (uint32_t)__bfloat16_as_ushort(h0) |
                           ((uint32_t)__bfloat16_as_ushort(h1) << 16);
            uint32_t plo = (uint32_t)__bfloat16_as_ushort(l0b) |
                           ((uint32_t)__bfloat16_as_ushort(l1b) << 16);
            *(uint32_t*)(g_hhi[p1] + gidx) = phi;
            *(uint32_t*)(g_hlo[p1] + gidx) = plo;
            if (layer == 0) {
                const int li = (td * NB + b0 + sr) * (2 * NH) + d * NH + j0 + sj;
                *(uint32_t*)(g_l0hi + li) = phi;
                *(uint32_t*)(g_l0lo + li) = plo;
            }
            if (t == NT - 1) {
                const int slot = (layer ? 2 : 0) + d;
                const int di = (slot * NB + b0 + sr) * NH + j0 + sj;
                *(uint32_t*)(g_dhhi[0] + di) = phi;
                *(uint32_t*)(g_dhlo[0] + di) = plo;
            }

            // next-step init (barrier-independent; overlaps barrier wait)
            if (t < NT - 1) {
                const int td2 = d ? (NT - 2 - t) : (t + 1);
                float n0, n1;
                if (layer == 0) {
                    const float* xr = x + ((b0 + sr) * NT + td2) * NIN;
                    const float x0 = xr[0], x1 = xr[1], x2 = xr[2];
                    n0 = bias0 + x0 * wi[0] + x1 * wi[1] + x2 * wi[2];
                    n1 = bias1 + x0 * wi[3] + x1 * wi[4] + x2 * wi[5];
                } else {
                    float2 v = __ldg((const float2*)&g_xs1[((d * NT + td2) * NB + b0 + sr) * NH + j0 + sj]);
                    n0 = v.x; n1 = v.y;
                }
                sStg[sr * 36 + sj + 0] = n0;
                sStg[sr * 36 + sj + 1] = n1;
            }
        }

        if (t < NT - 1)
            group_barrier(grp, 16);
    }
}

// ---------------------------------------------------------------------------
// xs1 via tensor cores (R12): 2-stage cp.async pipelined GEMM.
// ---------------------------------------------------------------------------
__device__ __forceinline__ void xs1_stage(uint32_t sbase, int d, int j0, int m0,
                                          int k0, int tid)
{
    const int r  = tid >> 3;
    const int c8 = (tid & 7) * 8;
#pragma unroll
    for (int rr = r; rr < 128; rr += 32) {
        const int gi = (m0 + rr) * (2 * NH) + k0 + c8;
        CP_ASYNC16(sbase + (uint32_t)((rr * XAS + c8) * 2),        g_l0hi + gi);
        CP_ASYNC16(sbase + (uint32_t)(X_SA + (rr * XAS + c8) * 2), g_l0lo + gi);
    }
#pragma unroll
    for (int rr = r; rr < 64; rr += 32) {
        const int gi = (d * NH + j0 + rr) * (2 * NH) + k0 + c8;
        CP_ASYNC16(sbase + (uint32_t)(2 * X_SA + (rr * XAS + c8) * 2),        g_xWhi + gi);
        CP_ASYNC16(sbase + (uint32_t)(2 * X_SA + X_SB + (rr * XAS + c8) * 2), g_xWlo + gi);
    }
    CP_COMMIT();
}

__global__ void __launch_bounds__(256) xs1_mma(
    const float* __restrict__ bih, const float* __restrict__ bhh)
{
    extern __shared__ char sm[];
    const uint32_t smBase = s2u(sm);

    const int d  = blockIdx.z;
    const int j0 = blockIdx.x * 64;
    const int m0 = blockIdx.y * 128;
    const int tid  = threadIdx.x;
    const int lane = tid & 31;
    const int warp = tid >> 5;
    const int wm = warp & 3;
    const int wn = warp >> 2;

    const int ag = lane >> 3, ar = lane & 7;
    const uint32_t aOff = (uint32_t)((wm * 32 + (ag & 1) * 8 + ar) * XAS + (ag >> 1) * 8) * 2;
    const uint32_t bOff = (uint32_t)(2 * X_SA) +
        (uint32_t)((wn * 32 + (lane >> 4) * 8 + (lane & 7)) * XAS + ((lane >> 3) & 1) * 8) * 2;

    float acc[2][4][4];
#pragma unroll
    for (int i = 0; i < 2; i++)
#pragma unroll
        for (int n = 0; n < 4; n++)
#pragma unroll
            for (int q = 0; q < 4; q++) acc[i][n][q] = 0.f;

    xs1_stage(smBase, d, j0, m0, 0, tid);

    for (int c = 0; c < 16; c++) {
        if (c < 15)
            xs1_stage(smBase + ((c + 1) & 1) * X_STAGE, d, j0, m0, (c + 1) * 64, tid);
        if (c < 15) { CP_WAIT1(); } else { CP_WAIT0(); }
        __syncthreads();

        const uint32_t aBase = smBase + (c & 1) * X_STAGE + aOff;
        const uint32_t bBase = smBase + (c & 1) * X_STAGE + bOff;

#pragma unroll
        for (int kk = 0; kk < 4; kk++) {
            uint32_t ah[2][4], al[2][4];
#pragma unroll
            for (int mt = 0; mt < 2; mt++) {
                const uint32_t addr = aBase + (uint32_t)(mt * 16 * XAS + kk * 16) * 2;
                LDSM_X4(ah[mt][0], ah[mt][1], ah[mt][2], ah[mt][3], addr);
                LDSM_X4(al[mt][0], al[mt][1], al[mt][2], al[mt][3], addr + X_SA);
            }
#pragma unroll
            for (int np = 0; np < 2; np++) {
                const uint32_t addr = bBase + (uint32_t)(np * 16 * XAS + kk * 16) * 2;
                uint32_t bh0, bh1, bh2, bh3, bl0, bl1, bl2, bl3;
                LDSM_X4(bh0, bh1, bh2, bh3, addr);
                LDSM_X4(bl0, bl1, bl2, bl3, addr + X_SB);
#pragma unroll
                for (int mt = 0; mt < 2; mt++) {
                    float* a0 = acc[mt][np * 2 + 0];
                    float* a1 = acc[mt][np * 2 + 1];
                    MMA_BF16(a0[0], a0[1], a0[2], a0[3],
                             ah[mt][0], ah[mt][1], ah[mt][2], ah[mt][3], bh0, bh1);
                    MMA_BF16(a0[0], a0[1], a0[2], a0[3],
                             ah[mt][0], ah[mt][1], ah[mt][2], ah[mt][3], bl0, bl1);
                    MMA_BF16(a0[0], a0[1], a0[2], a0[3],
                             al[mt][0], al[mt][1], al[mt][2], al[mt][3], bh0, bh1);
                    MMA_BF16(a1[0], a1[1], a1[2], a1[3],
                             ah[mt][0], ah[mt][1], ah[mt][2], ah[mt][3], bh2, bh3);
                    MMA_BF16(a1[0], a1[1], a1[2], a1[3],
                             ah[mt][0], ah[mt][1], ah[mt][2], ah[mt][3], bl2, bl3);
                    MMA_BF16(a1[0], a1[1], a1[2], a1[3],
                             al[mt][0], al[mt][1], al[mt][2], al[mt][3], bh2, bh3);
                }
            }
        }
        __syncthreads();
    }

#pragma unroll
    for (int nt = 0; nt < 4; nt++) {
        const int j = j0 + wn * 32 + nt * 8 + (lane & 3) * 2;
        const float bj0 = __ldg(&bih[(2 + d) * NH + j])     + __ldg(&bhh[(2 + d) * NH + j]);
        const float bj1 = __ldg(&bih[(2 + d) * NH + j + 1]) + __ldg(&bhh[(2 + d) * NH + j + 1]);
#pragma unroll
        for (int mt = 0; mt < 2; mt++) {
            const int m = m0 + wm * 32 + mt * 16 + (lane >> 2);
            *(float2*)&g_xs1[(d * NT * NB + m) * NH + j] =
                make_float2(acc[mt][nt][0] + bj0, acc[mt][nt][1] + bj1);
            *(float2*)&g_xs1[(d * NT * NB + m + 8) * NH + j] =
                make_float2(acc[mt][nt][2] + bj0, acc[mt][nt][3] + bj1);
        }
    }
}

// ---------------------------------------------------------------------------
// Decoder W prefetch (cp.async)
// ---------------------------------------------------------------------------
__device__ __forceinline__ void dec_prefetch_W(int l, int j0, int tid,
                                               uint32_t swhi, uint32_t swlo)
{
    const int r  = tid >> 3;
    const int c8 = tid & 7;
    const __nv_bfloat16* shi = g_dWhi + l * WMAT + (j0 + r) * NH;
    const __nv_bfloat16* slo = g_dWlo + l * WMAT + (j0 + r) * NH;
#pragma unroll
    for (int c = c8; c < 64; c += 8) {
        CP_ASYNC16(swhi + (uint32_t)(r * DEHS + c * 8) * 2, shi + c * 8);
        CP_ASYNC16(swlo + (uint32_t)(r * DEHS + c * 8) * 2, slo + c * 8);
    }
    if (l > 0) {
        const __nv_bfloat16* shi2 = g_dWhi + WIHR_OFF + (l - 1) * WMAT + (j0 + r) * NH;
        const __nv_bfloat16* slo2 = g_dWlo + WIHR_OFF + (l - 1) * WMAT + (j0 + r) * NH;
#pragma unroll
        for (int c = c8; c < 64; c += 8) {
            CP_ASYNC16(swhi + (uint32_t)(r * DEHS + 512 + c * 8) * 2, shi2 + c * 8);
            CP_ASYNC16(swlo + (uint32_t)(r * DEHS + 512 + c * 8) * 2, slo2 + c * 8);
        }
    }
    CP_COMMIT();
}

// ---------------------------------------------------------------------------
// Persistent decoder (R13): out-dot folded into l3 epilogue as per-jt
// partials; feedback sums 16 partials (deterministic). g_h3 eliminated.
// ---------------------------------------------------------------------------
__global__ void __launch_bounds__(256) dec_persist(
    const float* __restrict__ x,    const float* __restrict__ Wih0,
    const float* __restrict__ Wihr, const float* __restrict__ Whh,
    const float* __restrict__ bih,  const float* __restrict__ bhh,
    const float* __restrict__ linW, const float* __restrict__ linb,
    float* __restrict__ out)
{
    extern __shared__ char sm[];
    __nv_bfloat16* sWhi = (__nv_bfloat16*)(sm + OFF_DWHI);
    __nv_bfloat16* sWlo = (__nv_bfloat16*)(sm + OFF_DWLO);
    __nv_bfloat16* sHhi = (__nv_bfloat16*)(sm + OFF_DHHI);
    __nv_bfloat16* sHlo = (__nv_bfloat16*)(sm + OFF_DHLO);
    float*         sStg = (float*)(sm + OFF_DSTG);
    float*         sPrt = (float*)(sm + OFF_DPRT);

    __shared__ float s_dec[16][3];

    const int jt = blockIdx.x & 15;
    const int bt = blockIdx.x >> 4;
    const int grp = 8 + bt;
    const int j0 = jt * 32;
    const int b0 = bt * 16;
    const int tid  = threadIdx.x;
    const int lane = tid & 31;
    const int warp = tid >> 5;
    const int mj   = warp & 1;
    const int kw   = warp >> 1;

    // one-time: convert decoder weights to bf16 hi/lo (grid-strided)
    {
        const int stride4 = DEC_CTAS * 256 * 4;
        const int g4 = (blockIdx.x * 256 + tid) * 4;
        for (int i = g4; i < 4 * WMAT; i += stride4) {
            float4 w = *(const float4*)&Whh[i];
            split_bf16(w.x, g_dWhi[i + 0], g_dWlo[i + 0]);
            split_bf16(w.y, g_dWhi[i + 1], g_dWlo[i + 1]);
            split_bf16(w.z, g_dWhi[i + 2], g_dWlo[i + 2]);
            split_bf16(w.w, g_dWhi[i + 3], g_dWlo[i + 3]);
        }
        for (int i = g4; i < 3 * WMAT; i += stride4) {
            float4 w = *(const float4*)&Wihr[i];
            split_bf16(w.x, g_dWhi[WIHR_OFF + i + 0], g_dWlo[WIHR_OFF + i + 0]);
            split_bf16(w.y, g_dWhi[WIHR_OFF + i + 1], g_dWlo[WIHR_OFF + i + 1]);
            split_bf16(w.z, g_dWhi[WIHR_OFF + i + 2], g_dWlo[WIHR_OFF + i + 2]);
            split_bf16(w.w, g_dWhi[WIHR_OFF + i + 3], g_dWlo[WIHR_OFF + i + 3]);
        }
    }
    if (tid < 16) {
        const float* xr = x + ((b0 + tid) * NT + (NT - 1)) * NIN;
        s_dec[tid][0] = xr[0];
        s_dec[tid][1] = xr[1];
        s_dec[tid][2] = xr[2];
    }
    grid_barrier(DEC_CTAS);

    dec_prefetch_W(0, j0, tid, s2u(sWhi), s2u(sWlo));

    const int ag = lane >> 3, ar = lane & 7;
    const uint32_t aOff = (uint32_t)((mj * 16 + (ag & 1) * 8 + ar) * DEHS
                                     + (ag >> 1) * 8 + kw * 256) * 2;
    const uint32_t aHiBase = s2u(sWhi) + aOff;
    const uint32_t aLoBase = s2u(sWlo) + aOff;
    const uint32_t bOff = (uint32_t)(((lane >> 4) * 8 + (lane & 7)) * DEHS
                                     + ((lane >> 3) & 1) * 8 + kw * 256) * 2;
    const uint32_t bHiBase = s2u(sHhi) + bOff;
    const uint32_t bLoBase = s2u(sHlo) + bOff;

    const int sr = tid >> 4;
    const int sj = (tid & 15) * 2;
    const int jl = mj * 16 + (lane >> 2);
    const int bl = (lane & 3) * 2;

    // per-thread linW values for the partial output dot (constant)
    const float linw0 = __ldg(&linW[j0 + sj + 0]);
    const float linw1 = __ldg(&linW[j0 + sj + 1]);
    const float lb0   = __ldg(&linb[0]);

    for (int t = 0; t < NTGT; t++) {
        const int p = t & 1;

        // ---- feedback from step t-1: sum 16 per-jt partials ----
        if (t > 0) {
            if (tid < 16) {
                float o0 = lb0;
#pragma unroll
                for (int q = 0; q < 16; q++)
                    o0 += __ldcg(&g_o0p[p][q * NB + b0 + tid]);
                if (jt == 0) out[(b0 + tid) * NTGT + (t - 1)] = o0;
                float s1 = s_dec[tid][0] - o0;
                float s2 = s_dec[tid][1] - s1;
                s_dec[tid][0] = o0;
                s_dec[tid][1] = s1;
                s_dec[tid][2] = s2;
            }
            __syncthreads();
        }

        for (int l = 0; l < 4; l++) {
            const int nk = (l == 0) ? 2 : 4;

            // ---- stage h tiles via cp.async (joins W prefetch wait) ----
            {
                const int r   = tid >> 4;
                const int c16 = tid & 15;
                const __nv_bfloat16* rhi = g_dhhi[p] + (l * NB + b0 + r) * NH;
                const __nv_bfloat16* rlo = g_dhlo[p] + (l * NB + b0 + r) * NH;
#pragma unroll
                for (int c = c16; c < 64; c += 16) {
                    CP_ASYNC16(s2u(sHhi) + (uint32_t)(r * DEHS + c * 8) * 2, rhi + c * 8);
                    CP_ASYNC16(s2u(sHlo) + (uint32_t)(r * DEHS + c * 8) * 2, rlo + c * 8);
                }
                if (l > 0) {
                    const __nv_bfloat16* ihi = g_dhhi[1 - p] + ((l - 1) * NB + b0 + r) * NH;
                    const __nv_bfloat16* ilo = g_dhlo[1 - p] + ((l - 1) * NB + b0 + r) * NH;
#pragma unroll
                    for (int c = c16; c < 64; c += 16) {
                        CP_ASYNC16(s2u(sHhi) + (uint32_t)(r * DEHS + 512 + c * 8) * 2, ihi + c * 8);
                        CP_ASYNC16(s2u(sHlo) + (uint32_t)(r * DEHS + 512 + c * 8) * 2, ilo + c * 8);
                    }
                }
                CP_COMMIT();
            }
            // ---- stage init ----
            {
                float v0 = bih[l * NH + j0 + sj + 0] + bhh[l * NH + j0 + sj + 0];
                float v1 = bih[l * NH + j0 + sj + 1] + bhh[l * NH + j0 + sj + 1];
                if (l == 0) {
                    const float i0 = s_dec[sr][0], i1 = s_dec[sr][1], i2 = s_dec[sr][2];
                    const float* wp = Wih0 + (j0 + sj) * NIN;
                    v0 += i0 * wp[0] + i1 * wp[1] + i2 * wp[2];
                    v1 += i0 * wp[3] + i1 * wp[4] + i2 * wp[5];
                }
                sStg[sr * 36 + sj + 0] = v0;
                sStg[sr * 36 + sj + 1] = v1;
            }
            CP_WAIT0();
            __syncthreads();

            if (kw < nk) {
                float c00 = 0.f, c01 = 0.f, c02 = 0.f, c03 = 0.f;
                float c10 = 0.f, c11 = 0.f, c12 = 0.f, c13 = 0.f;
                uint32_t aHi = aHiBase, aLo = aLoBase, bHi = bHiBase, bLo = bLoBase;
#pragma unroll 4
                for (int kk = 0; kk < 16; kk++) {
                    uint32_t a0, a1, a2, a3, e0, e1, e2, e3;
                    uint32_t r0, r1, r2, r3, f0, f1, f2, f3;
                    LDSM_X4(a0, a1, a2, a3, aHi);
                    LDSM_X4(e0, e1, e2, e3, aLo);
                    LDSM_X4(r0, r1, r2, r3, bHi);
                    LDSM_X4(f0, f1, f2, f3, bLo);
                    MMA_BF16(c00, c01, c02, c03, a0, a1, a2, a3, r0, r1);
                    MMA_BF16(c00, c01, c02, c03, a0, a1, a2, a3, f0, f1);
                    MMA_BF16(c00, c01, c02, c03, e0, e1, e2, e3, r0, r1);
                    MMA_BF16(c10, c11, c12, c13, a0, a1, a2, a3, r2, r3);
                    MMA_BF16(c10, c11, c12, c13, a0, a1, a2, a3, f2, f3);
                    MMA_BF16(c10, c11, c12, c13, e0, e1, e2, e3, r2, r3);
                    aHi += 32; aLo += 32; bHi += 32; bLo += 32;
                }
                float* pp = sPrt + kw * (16 * 36);
                pp[(bl + 0) * 36 + jl]     = c00;
                pp[(bl + 1) * 36 + jl]     = c01;
                pp[(bl + 0) * 36 + jl + 8] = c02;
                pp[(bl + 1) * 36 + jl + 8] = c03;
                pp[(bl + 8) * 36 + jl]     = c10;
                pp[(bl + 9) * 36 + jl]     = c11;
                pp[(bl + 8) * 36 + jl + 8] = c12;
                pp[(bl + 9) * 36 + jl + 8] = c13;
            }
            __syncthreads();

            if (!(t == NTGT - 1 && l == 3))
                dec_prefetch_W((l == 3) ? 0 : l + 1, j0, tid, s2u(sWhi), s2u(sWlo));

            {
                float v0 = sStg[sr * 36 + sj + 0];
                float v1 = sStg[sr * 36 + sj + 1];
#pragma unroll
                for (int q = 0; q < 4; q++) {
                    if (q < nk) {
                        v0 += sPrt[q * 576 + sr * 36 + sj + 0];
                        v1 += sPrt[q * 576 + sr * 36 + sj + 1];
                    }
                }
                v0 = tanhf(v0); v1 = tanhf(v1);
                __nv_bfloat16 h0, h1, l0b, l1b;
                split_bf16(v0, h0, l0b);
                split_bf16(v1, h1, l1b);
                const int idx = (l * NB + b0 + sr) * NH + j0 + sj;
                uint32_t phi = (uint32_t)__bfloat16_as_ushort(h0) |
                               ((uint32_t)__bfloat16_as_ushort(h1) << 16);
                uint32_t plo = (uint32_t)__bfloat16_as_ushort(l0b) |
                               ((uint32_t)__bfloat16_as_ushort(l1b) << 16);
                *(uint32_t*)(g_dhhi[1 - p] + idx) = phi;
                *(uint32_t*)(g_dhlo[1 - p] + idx) = plo;

                // l3: fold output-dot partial (fp32 h3 values, pre-split)
                if (l == 3) {
                    float part = v0 * linw0 + v1 * linw1;
                    // reduce over the 16 owner threads of row sr (a half-warp)
#pragma unroll
                    for (int o = 8; o; o >>= 1)
                        part += __shfl_down_sync(0xffffffffu, part, o, 16);
                    if ((lane & 15) == 0)
                        g_o0p[1 - p][jt * NB + b0 + sr] = part;
                }
            }

            group_barrier(grp, 16);
        }
    }

    // ---- final output (t = NTGT-1): partials live in g_o0p[0] ----
    if (tid < 16 && jt == 0) {
        float o0 = lb0;
#pragma unroll
        for (int q = 0; q < 16; q++)
            o0 += __ldcg(&g_o0p[NTGT & 1][q * NB + b0 + tid]);
        out[(b0 + tid) * NTGT + (NTGT - 1)] = o0;
    }
}

// ---------------------------------------------------------------------------
// Launch sequence (graph-capturable: kernel launches only)
// ---------------------------------------------------------------------------
extern "C" void kernel_launch(void* const* d_in, const int* in_sizes, int n_in,
                              void* d_out, int out_size)
{
    const float* x        = (const float*)d_in[0];
    const float* enc_Wih0 = (const float*)d_in[2];
    const float* enc_Whh0 = (const float*)d_in[3];
    const float* enc_Wih1 = (const float*)d_in[4];
    const float* enc_Whh1 = (const float*)d_in[5];
    const float* enc_bih  = (const float*)d_in[6];
    const float* enc_bhh  = (const float*)d_in[7];
    const float* dec_Wih0 = (const float*)d_in[8];
    const float* dec_Wihr = (const float*)d_in[9];
    const float* dec_Whh  = (const float*)d_in[10];
    const float* dec_bih  = (const float*)d_in[11];
    const float* dec_bhh  = (const float*)d_in[12];
    const float* lin_W    = (const float*)d_in[13];
    const float* lin_b    = (const float*)d_in[14];
    float* out = (float*)d_out;

    cudaFuncSetAttribute(enc_mma, cudaFuncAttributeMaxDynamicSharedMemorySize,
                         ENC_SMEM);
    cudaFuncSetAttribute(dec_persist, cudaFuncAttributeMaxDynamicSharedMemorySize,
                         DEC_SMEM);
    cudaFuncSetAttribute(xs1_mma, cudaFuncAttributeMaxDynamicSharedMemorySize,
                         XS1_SMEM);

    // Pre-split Wih1 (independent of encoder)
    split_wih1<<<1024, 256>>>(enc_Wih1);

    // Encoder layer 0
    enc_mma<<<ENC_CTAS, 256, ENC_SMEM>>>(x, enc_Wih0, enc_Whh0,
                                         enc_bih, enc_bhh, 0);

    // Layer-1 input terms, pipelined tensor-core GEMM
    xs1_mma<<<dim3(8, 128, 2), 256, XS1_SMEM>>>(enc_bih, enc_bhh);

    // Encoder layer 1
    enc_mma<<<ENC_CTAS, 256, ENC_SMEM>>>(x, enc_Wih0, enc_Whh1,
                                         enc_bih, enc_bhh, 1);

    // Decoder
    dec_persist<<<DEC_CTAS, 256, DEC_SMEM>>>(x, dec_Wih0, dec_Wihr, dec_Whh,
                                             dec_bih, dec_bhh, lin_W, lin_b, out);
}

// round 15
// speedup vs baseline: 3.9058x; 1.0173x over previous
#include <cuda_runtime.h>
#include <cuda_bf16.h>
#include <cstdint>

// Problem constants
constexpr int NB   = 128;   // batch
constexpr int NT   = 128;   // encoder time steps
constexpr int NIN  = 3;     // input features
constexpr int NH   = 512;   // hidden
constexpr int NTGT = 32;    // decoder steps

constexpr int ENC_CTAS = 256;   // 2 dirs x 8 bt x 16 jt, 2 CTAs/SM
constexpr int DEC_CTAS = 128;

// ---------------- encoder smem layout (R11/R12) ----------------
constexpr int EHS      = 520;                   // bf16 row stride (elements)
constexpr int E_UNION  = 32 * EHS * 2;          // W staging (32 rows) / h tile (16 rows)
constexpr int OFF_ESTG = 2 * E_UNION;           // [16][36] f32 stage
constexpr int OFF_EPRT = OFF_ESTG + 16 * 36 * 4;   // [4][16][36] f32 partials
constexpr int ENC_SMEM = OFF_EPRT + 4 * 16 * 36 * 4;   // 78080 B

// ---------------- decoder smem layout (R14: split W regions + sRec) --------
constexpr int DEHS     = 1032;                  // W row stride (1024 cols + pad)
constexpr int DHS      = 520;                   // h row stride (512 cols + pad)
constexpr int DW_TILE  = 32 * DEHS * 2;         // 66048 B per precision
constexpr int DH_TILE  = 16 * DHS * 2;          // 16640 B per precision
constexpr int OFF_DWHI = 0;
constexpr int OFF_DWLO = OFF_DWHI + DW_TILE;    // 66048
constexpr int OFF_DHHI = OFF_DWLO + DW_TILE;    // 132096
constexpr int OFF_DHLO = OFF_DHHI + DH_TILE;    // 148736
constexpr int OFF_DSTG = OFF_DHLO + DH_TILE;    // 165376  [16][36] f32
constexpr int OFF_DPRT = OFF_DSTG + 16 * 36 * 4;   // 167680 [2][16][36] f32 (B partials)
constexpr int OFF_DREC = OFF_DPRT + 2 * 16 * 36 * 4; // 172288 [4][2][16][36] f32
constexpr int DEC_SMEM = OFF_DREC + 4 * 2 * 16 * 36 * 4;  // 190720 B

constexpr int WMAT     = NH * NH;
constexpr int WIHR_OFF = 4 * WMAT;

// ---------------- xs1 mma smem layout (R12: double-buffered) ----------------
constexpr int XAS     = 72;
constexpr int X_SA    = 128 * XAS * 2;
constexpr int X_SB    = 64 * XAS * 2;
constexpr int X_STAGE = 2 * X_SA + 2 * X_SB;
constexpr int XS1_SMEM = 2 * X_STAGE;

// ---------------------------------------------------------------------------
// Static device scratch
// ---------------------------------------------------------------------------
__device__ __nv_bfloat16 g_l0hi[NT * NB * (2 * NH)];
__device__ __nv_bfloat16 g_l0lo[NT * NB * (2 * NH)];
__device__ __nv_bfloat16 g_xWhi[2 * NH * (2 * NH)];
__device__ __nv_bfloat16 g_xWlo[2 * NH * (2 * NH)];
__device__ float g_xs1[2 * NT * NB * NH];
__device__ __nv_bfloat16 g_hhi[2][2 * NB * NH];
__device__ __nv_bfloat16 g_hlo[2][2 * NB * NH];
__device__ __nv_bfloat16 g_dWhi[7 * WMAT];
__device__ __nv_bfloat16 g_dWlo[7 * WMAT];
__device__ __nv_bfloat16 g_dhhi[2][4 * NB * NH];
__device__ __nv_bfloat16 g_dhlo[2][4 * NB * NH];
__device__ float g_o0p[2][16 * NB];          // per-jt partial output dots
__device__ unsigned g_cnt;
__device__ unsigned g_gen;
__device__ unsigned g_gcnt[16 * 32];
__device__ unsigned g_ggen[16 * 32];

// ---------------------------------------------------------------------------
// Barriers (generation-based, self-resetting, replay-safe, leader fence)
// ---------------------------------------------------------------------------
__device__ __forceinline__ void grid_barrier(unsigned nctas)
{
    __syncthreads();
    if (threadIdx.x == 0) {
        __threadfence();
        volatile unsigned* genp = &g_gen;
        unsigned gen = *genp;
        if (atomicAdd(&g_cnt, 1u) == nctas - 1) {
            g_cnt = 0;
            __threadfence();
            *genp = gen + 1;
        } else {
            while (*genp == gen) { }
            __threadfence();
        }
    }
    __syncthreads();
}

__device__ __forceinline__ void group_barrier(int g, unsigned n)
{
    __syncthreads();
    if (threadIdx.x == 0) {
        __threadfence();
        volatile unsigned* genp = &g_ggen[g * 32];
        unsigned gen = *genp;
        if (atomicAdd(&g_gcnt[g * 32], 1u) == n - 1) {
            g_gcnt[g * 32] = 0;
            __threadfence();
            *genp = gen + 1;
        } else {
            while (*genp == gen) { }
            __threadfence();
        }
    }
    __syncthreads();
}

// ---------------------------------------------------------------------------
// mma.sync + cp.async helpers
// ---------------------------------------------------------------------------
__device__ __forceinline__ uint32_t s2u(const void* p)
{
    return (uint32_t)__cvta_generic_to_shared(p);
}

#define LDSM_X4(r0, r1, r2, r3, addr)                                          \
    asm volatile("ldmatrix.sync.aligned.m8n8.x4.shared.b16 {%0,%1,%2,%3}, [%4];" \
                 : "=r"(r0), "=r"(r1), "=r"(r2), "=r"(r3) : "r"(addr))

#define MMA_BF16(c0, c1, c2, c3, a0, a1, a2, a3, b0, b1)                       \
    asm volatile("mma.sync.aligned.m16n8k16.row.col.f32.bf16.bf16.f32 "        \
                 "{%0,%1,%2,%3}, {%4,%5,%6,%7}, {%8,%9}, {%0,%1,%2,%3};"       \
                 : "+f"(c0), "+f"(c1), "+f"(c2), "+f"(c3)                      \
                 : "r"(a0), "r"(a1), "r"(a2), "r"(a3), "r"(b0), "r"(b1))

#define CP_ASYNC16(saddr, gptr)                                                \
    asm volatile("cp.async.cg.shared.global [%0], [%1], 16;"                   \
                 :: "r"(saddr), "l"(gptr))
#define CP_COMMIT()  asm volatile("cp.async.commit_group;")
#define CP_WAIT0()   asm volatile("cp.async.wait_group 0;" ::: "memory")
#define CP_WAIT1()   asm volatile("cp.async.wait_group 1;" ::: "memory")

__device__ __forceinline__ void split_bf16(float v, __nv_bfloat16& hi, __nv_bfloat16& lo)
{
    hi = __float2bfloat16(v);
    lo = __float2bfloat16(v - __bfloat162float(hi));
}

// ---------------------------------------------------------------------------
// Pre-split Wih1 into bf16 hi/lo
// ---------------------------------------------------------------------------
__global__ void __launch_bounds__(256) split_wih1(const float* __restrict__ W)
{
    const int i = (blockIdx.x * 256 + threadIdx.x) * 4;
    if (i < 2 * NH * 2 * NH) {
        float4 w = *(const float4*)&W[i];
        split_bf16(w.x, g_xWhi[i + 0], g_xWlo[i + 0]);
        split_bf16(w.y, g_xWhi[i + 1], g_xWlo[i + 1]);
        split_bf16(w.z, g_xWhi[i + 2], g_xWlo[i + 2]);
        split_bf16(w.w, g_xWhi[i + 3], g_xWlo[i + 3]);
    }
}

// ---------------------------------------------------------------------------
// Persistent encoder layer (R14 = R12 h-staging + light barrier + init hoist)
// ---------------------------------------------------------------------------
__global__ void __launch_bounds__(256, 2) enc_mma(
    const float* __restrict__ x, const float* __restrict__ Wih0,
    const float* __restrict__ Whh_all, const float* __restrict__ bih,
    const float* __restrict__ bhh, int layer)
{
    extern __shared__ char sm[];
    __nv_bfloat16* sHhi = (__nv_bfloat16*)(sm);
    __nv_bfloat16* sHlo = (__nv_bfloat16*)(sm + E_UNION);
    float*         sStg = (float*)(sm + OFF_ESTG);
    float*         sPrt = (float*)(sm + OFF_EPRT);

    const int blk = blockIdx.x;
    const int d   = blk >> 7;
    const int rem = blk & 127;
    const int bt  = rem >> 4;
    const int jt  = rem & 15;
    const int grp = blk >> 4;
    const int b0  = bt * 16;
    const int j0  = jt * 32;
    const int tid = threadIdx.x;
    const int lane = tid & 31;
    const int warp = tid >> 5;
    const int kw   = warp & 3;
    const int mj   = warp >> 2;

    const float* Whh = Whh_all + d * NH * NH;

    // ---- one-time: stage W tile (bf16 hi/lo) into smem ----
    {
        const int r  = tid >> 3;
        const int c0 = (tid & 7) * 4;
        for (int k0 = 0; k0 < NH; k0 += 32) {
            float4 w = __ldg((const float4*)&Whh[(j0 + r) * NH + k0 + c0]);
            const int o = r * EHS + k0 + c0;
            split_bf16(w.x, sHhi[o + 0], sHlo[o + 0]);
            split_bf16(w.y, sHhi[o + 1], sHlo[o + 1]);
            split_bf16(w.z, sHhi[o + 2], sHlo[o + 2]);
            split_bf16(w.w, sHhi[o + 3], sHlo[o + 3]);
        }
    }
    __syncthreads();

    // ---- preload A fragments into registers ----
    uint32_t aHi[8][4], aLo[8][4];
    {
        const int ag = lane >> 3, ar = lane & 7;
        const uint32_t rowOff = (uint32_t)((mj * 16 + (ag & 1) * 8 + ar) * EHS) * 2;
        const uint32_t colSel = (uint32_t)(kw * 128 + (ag >> 1) * 8) * 2;
#pragma unroll
        for (int q = 0; q < 8; q++) {
            const uint32_t off = rowOff + colSel + q * 32;
            LDSM_X4(aHi[q][0], aHi[q][1], aHi[q][2], aHi[q][3], s2u(sHhi) + off);
            LDSM_X4(aLo[q][0], aLo[q][1], aLo[q][2], aLo[q][3], s2u(sHlo) + off);
        }
    }

    // ---- B (h) ldmatrix bases ----
    const uint32_t bOff = (uint32_t)(((lane >> 4) * 8 + (lane & 7)) * EHS
                                     + ((lane >> 3) & 1) * 8 + kw * 128) * 2;
    const uint32_t bHiBase = s2u(sHhi) + bOff;
    const uint32_t bLoBase = s2u(sHlo) + bOff;

    // ---- owner slots + layer-0 constants ----
    const int sr = tid >> 4;
    const int sj = (tid & 15) * 2;
    float bias0 = 0.f, bias1 = 0.f, wi[6];
    if (layer == 0) {
        bias0 = bih[d * NH + j0 + sj + 0] + bhh[d * NH + j0 + sj + 0];
        bias1 = bih[d * NH + j0 + sj + 1] + bhh[d * NH + j0 + sj + 1];
        const float* wp = Wih0 + (d * NH + j0 + sj) * NIN;
#pragma unroll
        for (int i = 0; i < 6; i++) wi[i] = wp[i];
    }

    // ---- stage init for t = 0 ----
    {
        const int td0 = d ? (NT - 1) : 0;
        float v0, v1;
        if (layer == 0) {
            const float* xr = x + ((b0 + sr) * NT + td0) * NIN;
            const float x0 = xr[0], x1 = xr[1], x2 = xr[2];
            v0 = bias0 + x0 * wi[0] + x1 * wi[1] + x2 * wi[2];
            v1 = bias1 + x0 * wi[3] + x1 * wi[4] + x2 * wi[5];
        } else {
            float2 v = __ldg((const float2*)&g_xs1[((d * NT + td0) * NB + b0 + sr) * NH + j0 + sj]);
            v0 = v.x; v1 = v.y;
        }
        sStg[sr * 36 + sj + 0] = v0;
        sStg[sr * 36 + sj + 1] = v1;
    }
    __syncthreads();   // W smem dead; region reused for h

    const int jl = mj * 16 + (lane >> 2);
    const int bl = (lane & 3) * 2;
    float* pp = sPrt + kw * (16 * 36);

    for (int t = 0; t < NT; t++) {
        const int td = d ? (NT - 1 - t) : t;

        // ---- stage h tile (16 rows, __ldcg batch, proven R12) ----
        if (t > 0) {
            const int p = t & 1;
            const __nv_bfloat16* srcHi = g_hhi[p] + (d * NB + b0) * NH;
            const __nv_bfloat16* srcLo = g_hlo[p] + (d * NB + b0) * NH;
            const int r  = tid >> 4;
            const int cc = tid & 15;
#pragma unroll
            for (int it = 0; it < 4; it++) {
                const int c16 = cc + it * 16;
                uint4 vh = __ldcg((const uint4*)(srcHi + r * NH) + c16);
                uint4 vl = __ldcg((const uint4*)(srcLo + r * NH) + c16);
                *(uint4*)((char*)sHhi + r * (EHS * 2) + c16 * 16) = vh;
                *(uint4*)((char*)sHlo + r * (EHS * 2) + c16 * 16) = vl;
            }
        }
        __syncthreads();

        // ---- MMA over this warp's K quarter (A from registers) ----
        if (t > 0) {
            float acc[2][4];
#pragma unroll
            for (int n = 0; n < 2; n++)
#pragma unroll
                for (int q = 0; q < 4; q++) acc[n][q] = 0.f;

#pragma unroll
            for (int q = 0; q < 8; q++) {
                uint32_t r0, r1, r2, r3, f0, f1, f2, f3;
                LDSM_X4(r0, r1, r2, r3, bHiBase + q * 32);
                LDSM_X4(f0, f1, f2, f3, bLoBase + q * 32);
                MMA_BF16(acc[0][0], acc[0][1], acc[0][2], acc[0][3],
                         aHi[q][0], aHi[q][1], aHi[q][2], aHi[q][3], r0, r1);
                MMA_BF16(acc[0][0], acc[0][1], acc[0][2], acc[0][3],
                         aHi[q][0], aHi[q][1], aHi[q][2], aHi[q][3], f0, f1);
                MMA_BF16(acc[0][0], acc[0][1], acc[0][2], acc[0][3],
                         aLo[q][0], aLo[q][1], aLo[q][2], aLo[q][3], r0, r1);
                MMA_BF16(acc[1][0], acc[1][1], acc[1][2], acc[1][3],
                         aHi[q][0], aHi[q][1], aHi[q][2], aHi[q][3], r2, r3);
                MMA_BF16(acc[1][0], acc[1][1], acc[1][2], acc[1][3],
                         aHi[q][0], aHi[q][1], aHi[q][2], aHi[q][3], f2, f3);
                MMA_BF16(acc[1][0], acc[1][1], acc[1][2], acc[1][3],
                         aLo[q][0], aLo[q][1], aLo[q][2], aLo[q][3], r2, r3);
            }
#pragma unroll
            for (int n = 0; n < 2; n++) {
                pp[(n * 8 + bl + 0) * 36 + jl]     = acc[n][0];
                pp[(n * 8 + bl + 1) * 36 + jl]     = acc[n][1];
                pp[(n * 8 + bl + 0) * 36 + jl + 8] = acc[n][2];
                pp[(n * 8 + bl + 1) * 36 + jl + 8] = acc[n][3];
            }
        }
        __syncthreads();

        // ---- owner epilogue: reduce + tanh + split + store + next init ----
        {
            float v0 = sStg[sr * 36 + sj + 0];
            float v1 = sStg[sr * 36 + sj + 1];
            if (t > 0) {
#pragma unroll
                for (int q = 0; q < 4; q++) {
                    v0 += sPrt[q * 576 + sr * 36 + sj + 0];
                    v1 += sPrt[q * 576 + sr * 36 + sj + 1];
                }
            }
            v0 = tanhf(v0); v1 = tanhf(v1);

            __nv_bfloat16 h0, h1, l0b, l1b;
            split_bf16(v0, h0, l0b);
            split_bf16(v1, h1, l1b);
            const int p1 = (t + 1) & 1;
            const int gidx = (d * NB + b0 + sr) * NH + j0 + sj;
            uint32_t phi = (uint32_t)__bfloat16_as_ushort(h0) |
                           ((uint32_t)__bfloat16_as_ushort(h1) << 16);
            uint32_t plo = (uint32_t)__bfloat16_as_ushort(l0b) |
                           ((uint32_t)__bfloat16_as_ushort(l1b) << 16);
            *(uint32_t*)(g_hhi[p1] + gidx) = phi;
            *(uint32_t*)(g_hlo[p1] + gidx) = plo;
            if (layer == 0) {
                const int li = (td * NB + b0 + sr) * (2 * NH) + d * NH + j0 + sj;
                *(uint32_t*)(g_l0hi + li) = phi;
                *(uint32_t*)(g_l0lo + li) = plo;
            }
            if (t == NT - 1) {
                const int slot = (layer ? 2 : 0) + d;
                const int di = (slot * NB + b0 + sr) * NH + j0 + sj;
                *(uint32_t*)(g_dhhi[0] + di) = phi;
                *(uint32_t*)(g_dhlo[0] + di) = plo;
            }

            if (t < NT - 1) {
                const int td2 = d ? (NT - 2 - t) : (t + 1);
                float n0, n1;
                if (layer == 0) {
                    const float* xr = x + ((b0 + sr) * NT + td2) * NIN;
                    const float x0 = xr[0], x1 = xr[1], x2 = xr[2];
                    n0 = bias0 + x0 * wi[0] + x1 * wi[1] + x2 * wi[2];
                    n1 = bias1 + x0 * wi[3] + x1 * wi[4] + x2 * wi[5];
                } else {
                    float2 v = __ldg((const float2*)&g_xs1[((d * NT + td2) * NB + b0 + sr) * NH + j0 + sj]);
                    n0 = v.x; n1 = v.y;
                }
                sStg[sr * 36 + sj + 0] = n0;
                sStg[sr * 36 + sj + 1] = n1;
            }
        }

        if (t < NT - 1)
            group_barrier(grp, 16);
    }
}

// ---------------------------------------------------------------------------
// xs1 via tensor cores (R12, unchanged): 2-stage cp.async pipelined GEMM.
// ---------------------------------------------------------------------------
__device__ __forceinline__ void xs1_stage(uint32_t sbase, int d, int j0, int m0,
                                          int k0, int tid)
{
    const int r  = tid >> 3;
    const int c8 = (tid & 7) * 8;
#pragma unroll
    for (int rr = r; rr < 128; rr += 32) {
        const int gi = (m0 + rr) * (2 * NH) + k0 + c8;
        CP_ASYNC16(sbase + (uint32_t)((rr * XAS + c8) * 2),        g_l0hi + gi);
        CP_ASYNC16(sbase + (uint32_t)(X_SA + (rr * XAS + c8) * 2), g_l0lo + gi);
    }
#pragma unroll
    for (int rr = r; rr < 64; rr += 32) {
        const int gi = (d * NH + j0 + rr) * (2 * NH) + k0 + c8;
        CP_ASYNC16(sbase + (uint32_t)(2 * X_SA + (rr * XAS + c8) * 2),        g_xWhi + gi);
        CP_ASYNC16(sbase + (uint32_t)(2 * X_SA + X_SB + (rr * XAS + c8) * 2), g_xWlo + gi);
    }
    CP_COMMIT();
}

__global__ void __launch_bounds__(256) xs1_mma(
    const float* __restrict__ bih, const float* __restrict__ bhh)
{
    extern __shared__ char sm[];
    const uint32_t smBase = s2u(sm);

    const int d  = blockIdx.z;
    const int j0 = blockIdx.x * 64;
    const int m0 = blockIdx.y * 128;
    const int tid  = threadIdx.x;
    const int lane = tid & 31;
    const int warp = tid >> 5;
    const int wm = warp & 3;
    const int wn = warp >> 2;

    const int ag = lane >> 3, ar = lane & 7;
    const uint32_t aOff = (uint32_t)((wm * 32 + (ag & 1) * 8 + ar) * XAS + (ag >> 1) * 8) * 2;
    const uint32_t bOff = (uint32_t)(2 * X_SA) +
        (uint32_t)((wn * 32 + (lane >> 4) * 8 + (lane & 7)) * XAS + ((lane >> 3) & 1) * 8) * 2;

    float acc[2][4][4];
#pragma unroll
    for (int i = 0; i < 2; i++)
#pragma unroll
        for (int n = 0; n < 4; n++)
#pragma unroll
            for (int q = 0; q < 4; q++) acc[i][n][q] = 0.f;

    xs1_stage(smBase, d, j0, m0, 0, tid);

    for (int c = 0; c < 16; c++) {
        if (c < 15)
            xs1_stage(smBase + ((c + 1) & 1) * X_STAGE, d, j0, m0, (c + 1) * 64, tid);
        if (c < 15) { CP_WAIT1(); } else { CP_WAIT0(); }
        __syncthreads();

        const uint32_t aBase = smBase + (c & 1) * X_STAGE + aOff;
        const uint32_t bBase = smBase + (c & 1) * X_STAGE + bOff;

#pragma unroll
        for (int kk = 0; kk < 4; kk++) {
            uint32_t ah[2][4], al[2][4];
#pragma unroll
            for (int mt = 0; mt < 2; mt++) {
                const uint32_t addr = aBase + (uint32_t)(mt * 16 * XAS + kk * 16) * 2;
                LDSM_X4(ah[mt][0], ah[mt][1], ah[mt][2], ah[mt][3], addr);
                LDSM_X4(al[mt][0], al[mt][1], al[mt][2], al[mt][3], addr + X_SA);
            }
#pragma unroll
            for (int np = 0; np < 2; np++) {
                const uint32_t addr = bBase + (uint32_t)(np * 16 * XAS + kk * 16) * 2;
                uint32_t bh0, bh1, bh2, bh3, bl0, bl1, bl2, bl3;
                LDSM_X4(bh0, bh1, bh2, bh3, addr);
                LDSM_X4(bl0, bl1, bl2, bl3, addr + X_SB);
#pragma unroll
                for (int mt = 0; mt < 2; mt++) {
                    float* a0 = acc[mt][np * 2 + 0];
                    float* a1 = acc[mt][np * 2 + 1];
                    MMA_BF16(a0[0], a0[1], a0[2], a0[3],
                             ah[mt][0], ah[mt][1], ah[mt][2], ah[mt][3], bh0, bh1);
                    MMA_BF16(a0[0], a0[1], a0[2], a0[3],
                             ah[mt][0], ah[mt][1], ah[mt][2], ah[mt][3], bl0, bl1);
                    MMA_BF16(a0[0], a0[1], a0[2], a0[3],
                             al[mt][0], al[mt][1], al[mt][2], al[mt][3], bh0, bh1);
                    MMA_BF16(a1[0], a1[1], a1[2], a1[3],
                             ah[mt][0], ah[mt][1], ah[mt][2], ah[mt][3], bh2, bh3);
                    MMA_BF16(a1[0], a1[1], a1[2], a1[3],
                             ah[mt][0], ah[mt][1], ah[mt][2], ah[mt][3], bl2, bl3);
                    MMA_BF16(a1[0], a1[1], a1[2], a1[3],
                             al[mt][0], al[mt][1], al[mt][2], al[mt][3], bh2, bh3);
                }
            }
        }
        __syncthreads();
    }

#pragma unroll
    for (int nt = 0; nt < 4; nt++) {
        const int j = j0 + wn * 32 + nt * 8 + (lane & 3) * 2;
        const float bj0 = __ldg(&bih[(2 + d) * NH + j])     + __ldg(&bhh[(2 + d) * NH + j]);
        const float bj1 = __ldg(&bih[(2 + d) * NH + j + 1]) + __ldg(&bhh[(2 + d) * NH + j + 1]);
#pragma unroll
        for (int mt = 0; mt < 2; mt++) {
            const int m = m0 + wm * 32 + mt * 16 + (lane >> 2);
            *(float2*)&g_xs1[(d * NT * NB + m) * NH + j] =
                make_float2(acc[mt][nt][0] + bj0, acc[mt][nt][1] + bj1);
            *(float2*)&g_xs1[(d * NT * NB + m + 8) * NH + j] =
                make_float2(acc[mt][nt][2] + bj0, acc[mt][nt][3] + bj1);
        }
    }
}

// ---------------------------------------------------------------------------
// Decoder W prefetch: Wihr[lB-1] -> cols 0-511 (if lB>=1), Whh[lR] -> cols 512+
// ---------------------------------------------------------------------------
__device__ __forceinline__ void dec_prefetch_W(int lB, int lR, int j0, int tid,
                                               uint32_t swhi, uint32_t swlo)
{
    const int r  = tid >> 3;
    const int c8 = tid & 7;
    if (lB >= 1) {
        const __nv_bfloat16* shi = g_dWhi + WIHR_OFF + (lB - 1) * WMAT + (j0 + r) * NH;
        const __nv_bfloat16* slo = g_dWlo + WIHR_OFF + (lB - 1) * WMAT + (j0 + r) * NH;
#pragma unroll
        for (int c = c8; c < 64; c += 8) {
            CP_ASYNC16(swhi + (uint32_t)(r * DEHS + c * 8) * 2, shi + c * 8);
            CP_ASYNC16(swlo + (uint32_t)(r * DEHS + c * 8) * 2, slo + c * 8);
        }
    }
    {
        const __nv_bfloat16* rhi = g_dWhi + lR * WMAT + (j0 + r) * NH;
        const __nv_bfloat16* rlo = g_dWlo + lR * WMAT + (j0 + r) * NH;
#pragma unroll
        for (int c = c8; c < 64; c += 8) {
            CP_ASYNC16(swhi + (uint32_t)(r * DEHS + 512 + c * 8) * 2, rhi + c * 8);
            CP_ASYNC16(swlo + (uint32_t)(r * DEHS + 512 + c * 8) * 2, rlo + c * 8);
        }
    }
    CP_COMMIT();
}

// ---------------------------------------------------------------------------
// Persistent decoder (R14): warp-specialized. Warps 0-3 (role 0) run the
// critical input-GEMM chain; warps 4-7 (role 1) compute next-step recurrent
// GEMMs (Whh_l . h_l) off the critical path, sharing the same staged h tile.
// Schedule: phase P_l(t) -> role1 computes R_{(l+3)%4} for its consumer phase;
// prologue seeds R_0..R_2(0) from hn.
// ---------------------------------------------------------------------------
__global__ void __launch_bounds__(256) dec_persist(
    const float* __restrict__ x,    const float* __restrict__ Wih0,
    const float* __restrict__ Wihr, const float* __restrict__ Whh,
    const float* __restrict__ bih,  const float* __restrict__ bhh,
    const float* __restrict__ linW, const float* __restrict__ linb,
    float* __restrict__ out)
{
    extern __shared__ char sm[];
    __nv_bfloat16* sWhi = (__nv_bfloat16*)(sm + OFF_DWHI);
    __nv_bfloat16* sWlo = (__nv_bfloat16*)(sm + OFF_DWLO);
    __nv_bfloat16* sHhi = (__nv_bfloat16*)(sm + OFF_DHHI);
    __nv_bfloat16* sHlo = (__nv_bfloat16*)(sm + OFF_DHLO);
    float*         sStg = (float*)(sm + OFF_DSTG);   // [16][36]
    float*         sPrt = (float*)(sm + OFF_DPRT);   // [2][16][36] (B partials)
    float*         sRec = (float*)(sm + OFF_DREC);   // [4][2][16][36]

    __shared__ float s_dec[16][3];

    const int jt = blockIdx.x & 15;
    const int bt = blockIdx.x >> 4;
    const int grp = 8 + bt;
    const int j0 = jt * 32;
    const int b0 = bt * 16;
    const int tid  = threadIdx.x;
    const int lane = tid & 31;
    const int warp = tid >> 5;
    const int mj   = warp & 1;          // j half (16 rows)
    const int kh   = (warp >> 1) & 1;   // k half (256 cols)
    const int role = warp >> 2;         // 0 = input chain, 1 = recurrent

    // one-time: convert decoder weights to bf16 hi/lo (grid-strided)
    {
        const int stride4 = DEC_CTAS * 256 * 4;
        const int g4 = (blockIdx.x * 256 + tid) * 4;
        for (int i = g4; i < 4 * WMAT; i += stride4) {
            float4 w = *(const float4*)&Whh[i];
            split_bf16(w.x, g_dWhi[i + 0], g_dWlo[i + 0]);
            split_bf16(w.y, g_dWhi[i + 1], g_dWlo[i + 1]);
            split_bf16(w.z, g_dWhi[i + 2], g_dWlo[i + 2]);
            split_bf16(w.w, g_dWhi[i + 3], g_dWlo[i + 3]);
        }
        for (int i = g4; i < 3 * WMAT; i += stride4) {
            float4 w = *(const float4*)&Wihr[i];
            split_bf16(w.x, g_dWhi[WIHR_OFF + i + 0], g_dWlo[WIHR_OFF + i + 0]);
            split_bf16(w.y, g_dWhi[WIHR_OFF + i + 1], g_dWlo[WIHR_OFF + i + 1]);
            split_bf16(w.z, g_dWhi[WIHR_OFF + i + 2], g_dWlo[WIHR_OFF + i + 2]);
            split_bf16(w.w, g_dWhi[WIHR_OFF + i + 3], g_dWlo[WIHR_OFF + i + 3]);
        }
    }
    if (tid < 16) {
        const float* xr = x + ((b0 + tid) * NT + (NT - 1)) * NIN;
        s_dec[tid][0] = xr[0];
        s_dec[tid][1] = xr[1];
        s_dec[tid][2] = xr[2];
    }
    grid_barrier(DEC_CTAS);

    // ---- ldmatrix bases ----
    const int ag = lane >> 3, ar = lane & 7;
    const uint32_t aOff = (uint32_t)((mj * 16 + (ag & 1) * 8 + ar) * DEHS
                                     + (ag >> 1) * 8 + role * 512 + kh * 256) * 2;
    const uint32_t aHiBase = s2u(sWhi) + aOff;
    const uint32_t aLoBase = s2u(sWlo) + aOff;
    const uint32_t bOff = (uint32_t)(((lane >> 4) * 8 + (lane & 7)) * DHS
                                     + ((lane >> 3) & 1) * 8 + kh * 256) * 2;
    const uint32_t bHiBase = s2u(sHhi) + bOff;
    const uint32_t bLoBase = s2u(sHlo) + bOff;

    const int sr = tid >> 4;
    const int sj = (tid & 15) * 2;
    const int jl = mj * 16 + (lane >> 2);
    const int bl = (lane & 3) * 2;

    const float linw0 = __ldg(&linW[j0 + sj + 0]);
    const float linw1 = __ldg(&linW[j0 + sj + 1]);
    const float lb0   = __ldg(&linb[0]);

    // ---- stage-h helper captured by lambda-ish macro (inline each use) ----
    // ---- prologue: seed sRec[0..2] = Whh_l . hn_l (local, no barriers) ----
    for (int l = 0; l < 3; l++) {
        {   // stage hn_l + Whh_l (R region)
            const int r   = tid >> 4;
            const int c16 = tid & 15;
            const __nv_bfloat16* rhi = g_dhhi[0] + (l * NB + b0 + r) * NH;
            const __nv_bfloat16* rlo = g_dhlo[0] + (l * NB + b0 + r) * NH;
#pragma unroll
            for (int c = c16; c < 64; c += 16) {
                CP_ASYNC16(s2u(sHhi) + (uint32_t)(r * DHS + c * 8) * 2, rhi + c * 8);
                CP_ASYNC16(s2u(sHlo) + (uint32_t)(r * DHS + c * 8) * 2, rlo + c * 8);
            }
            const int wr = tid >> 3, wc = tid & 7;
            const __nv_bfloat16* whi = g_dWhi + l * WMAT + (j0 + wr) * NH;
            const __nv_bfloat16* wlo = g_dWlo + l * WMAT + (j0 + wr) * NH;
#pragma unroll
            for (int c = wc; c < 64; c += 8) {
                CP_ASYNC16(s2u(sWhi) + (uint32_t)(wr * DEHS + 512 + c * 8) * 2, whi + c * 8);
                CP_ASYNC16(s2u(sWlo) + (uint32_t)(wr * DEHS + 512 + c * 8) * 2, wlo + c * 8);
            }
            CP_COMMIT();
        }
        CP_WAIT0();
        __syncthreads();
        if (role == 1) {
            float c00 = 0.f, c01 = 0.f, c02 = 0.f, c03 = 0.f;
            float c10 = 0.f, c11 = 0.f, c12 = 0.f, c13 = 0.f;
            uint32_t aHi = aHiBase, aLo = aLoBase, bHi = bHiBase, bLo = bLoBase;
#pragma unroll 4
            for (int kk = 0; kk < 16; kk++) {
                uint32_t a0, a1, a2, a3, e0, e1, e2, e3;
                uint32_t r0, r1, r2, r3, f0, f1, f2, f3;
                LDSM_X4(a0, a1, a2, a3, aHi);
                LDSM_X4(e0, e1, e2, e3, aLo);
                LDSM_X4(r0, r1, r2, r3, bHi);
                LDSM_X4(f0, f1, f2, f3, bLo);
                MMA_BF16(c00, c01, c02, c03, a0, a1, a2, a3, r0, r1);
                MMA_BF16(c00, c01, c02, c03, a0, a1, a2, a3, f0, f1);
                MMA_BF16(c00, c01, c02, c03, e0, e1, e2, e3, r0, r1);
                MMA_BF16(c10, c11, c12, c13, a0, a1, a2, a3, r2, r3);
                MMA_BF16(c10, c11, c12, c13, a0, a1, a2, a3, f2, f3);
                MMA_BF16(c10, c11, c12, c13, e0, e1, e2, e3, r2, r3);
                aHi += 32; aLo += 32; bHi += 32; bLo += 32;
            }
            float* pp = sRec + (l * 2 + kh) * 576;
            pp[(bl + 0) * 36 + jl]     = c00;
            pp[(bl + 1) * 36 + jl]     = c01;
            pp[(bl + 0) * 36 + jl + 8] = c02;
            pp[(bl + 1) * 36 + jl + 8] = c03;
            pp[(bl + 8) * 36 + jl]     = c10;
            pp[(bl + 9) * 36 + jl]     = c11;
            pp[(bl + 8) * 36 + jl + 8] = c12;
            pp[(bl + 9) * 36 + jl + 8] = c13;
        }
        __syncthreads();
    }
    // prefetch for P0(0): Whh_3 only
    dec_prefetch_W(0, 3, j0, tid, s2u(sWhi), s2u(sWlo));

    for (int t = 0; t < NTGT; t++) {
        const int p = t & 1;

        // ---- feedback from step t-1: sum 16 per-jt partials ----
        if (t > 0) {
            if (tid < 16) {
                float o0 = lb0;
#pragma unroll
                for (int q = 0; q < 16; q++)
                    o0 += __ldcg(&g_o0p[p][q * NB + b0 + tid]);
                if (jt == 0) out[(b0 + tid) * NTGT + (t - 1)] = o0;
                float s1 = s_dec[tid][0] - o0;
                float s2 = s_dec[tid][1] - s1;
                s_dec[tid][0] = o0;
                s_dec[tid][1] = s1;
                s_dec[tid][2] = s2;
            }
            __syncthreads();
        }

        for (int l = 0; l < 4; l++) {
            // ---- stage h tile: l==0 -> h_3(t-1) [g_dh(p)]; else h_{l-1}(t) ----
            {
                const int r   = tid >> 4;
                const int c16 = tid & 15;
                const __nv_bfloat16* rhi;
                const __nv_bfloat16* rlo;
                if (l == 0) {
                    rhi = g_dhhi[p] + (3 * NB + b0 + r) * NH;
                    rlo = g_dhlo[p] + (3 * NB + b0 + r) * NH;
                } else {
                    rhi = g_dhhi[1 - p] + ((l - 1) * NB + b0 + r) * NH;
                    rlo = g_dhlo[1 - p] + ((l - 1) * NB + b0 + r) * NH;
                }
#pragma unroll
                for (int c = c16; c < 64; c += 16) {
                    CP_ASYNC16(s2u(sHhi) + (uint32_t)(r * DHS + c * 8) * 2, rhi + c * 8);
                    CP_ASYNC16(s2u(sHlo) + (uint32_t)(r * DHS + c * 8) * 2, rlo + c * 8);
                }
                CP_COMMIT();
            }
            // ---- stage init ----
            {
                float v0 = bih[l * NH + j0 + sj + 0] + bhh[l * NH + j0 + sj + 0];
                float v1 = bih[l * NH + j0 + sj + 1] + bhh[l * NH + j0 + sj + 1];
                if (l == 0) {
                    const float i0 = s_dec[sr][0], i1 = s_dec[sr][1], i2 = s_dec[sr][2];
                    const float* wp = Wih0 + (j0 + sj) * NIN;
                    v0 += i0 * wp[0] + i1 * wp[1] + i2 * wp[2];
                    v1 += i0 * wp[3] + i1 * wp[4] + i2 * wp[5];
                }
                sStg[sr * 36 + sj + 0] = v0;
                sStg[sr * 36 + sj + 1] = v1;
            }
            CP_WAIT0();     // h (this phase) + W (prefetched last phase)
            __syncthreads();

            // ---- MMA: role0 = input gemm (l>=1); role1 = recurrent prefill ----
            if (role == 1 || l >= 1) {
                float c00 = 0.f, c01 = 0.f, c02 = 0.f, c03 = 0.f;
                float c10 = 0.f, c11 = 0.f, c12 = 0.f, c13 = 0.f;
                uint32_t aHi = aHiBase, aLo = aLoBase, bHi = bHiBase, bLo = bLoBase;
#pragma unroll 4
                for (int kk = 0; kk < 16; kk++) {
                    uint32_t a0, a1, a2, a3, e0, e1, e2, e3;
                    uint32_t r0, r1, r2, r3, f0, f1, f2, f3;
                    LDSM_X4(a0, a1, a2, a3, aHi);
                    LDSM_X4(e0, e1, e2, e3, aLo);
                    LDSM_X4(r0, r1, r2, r3, bHi);
                    LDSM_X4(f0, f1, f2, f3, bLo);
                    MMA_BF16(c00, c01, c02, c03, a0, a1, a2, a3, r0, r1);
                    MMA_BF16(c00, c01, c02, c03, a0, a1, a2, a3, f0, f1);
                    MMA_BF16(c00, c01, c02, c03, e0, e1, e2, e3, r0, r1);
                    MMA_BF16(c10, c11, c12, c13, a0, a1, a2, a3, r2, r3);
                    MMA_BF16(c10, c11, c12, c13, a0, a1, a2, a3, f2, f3);
                    MMA_BF16(c10, c11, c12, c13, e0, e1, e2, e3, r2, r3);
                    aHi += 32; aLo += 32; bHi += 32; bLo += 32;
                }
                float* pp = (role == 0) ? (sPrt + kh * 576)
                                        : (sRec + (((l + 3) & 3) * 2 + kh) * 576);
                pp[(bl + 0) * 36 + jl]     = c00;
                pp[(bl + 1) * 36 + jl]     = c01;
                pp[(bl + 0) * 36 + jl + 8] = c02;
                pp[(bl + 1) * 36 + jl + 8] = c03;
                pp[(bl + 8) * 36 + jl]     = c10;
                pp[(bl + 9) * 36 + jl]     = c11;
                pp[(bl + 8) * 36 + jl + 8] = c12;
                pp[(bl + 9) * 36 + jl + 8] = c13;
            }
            __syncthreads();

            // ---- prefetch next phase's W (overlaps epilogue + barrier) ----
            if (!(t == NTGT - 1 && l == 3)) {
                const int ln = (l + 1) & 3;
                dec_prefetch_W(ln, (ln + 3) & 3, j0, tid, s2u(sWhi), s2u(sWlo));
            }

            // ---- owner epilogue: init + B partials + sRec[l], tanh, store ----
            {
                float v0 = sStg[sr * 36 + sj + 0];
                float v1 = sStg[sr * 36 + sj + 1];
                if (l >= 1) {
#pragma unroll
                    for (int q = 0; q < 2; q++) {
                        v0 += sPrt[q * 576 + sr * 36 + sj + 0];
                        v1 += sPrt[q * 576 + sr * 36 + sj + 1];
                    }
                }
#pragma unroll
                for (int q = 0; q < 2; q++) {
                    v0 += sRec[(l * 2 + q) * 576 + sr * 36 + sj + 0];
                    v1 += sRec[(l * 2 + q) * 576 + sr * 36 + sj + 1];
                }
                v0 = tanhf(v0); v1 = tanhf(v1);
                __nv_bfloat16 h0, h1, l0b, l1b;
                split_bf16(v0, h0, l0b);
                split_bf16(v1, h1, l1b);
                const int idx = (l * NB + b0 + sr) * NH + j0 + sj;
                uint32_t phi = (uint32_t)__bfloat16_as_ushort(h0) |
                               ((uint32_t)__bfloat16_as_ushort(h1) << 16);
                uint32_t plo = (uint32_t)__bfloat16_as_ushort(l0b) |
                               ((uint32_t)__bfloat16_as_ushort(l1b) << 16);
                *(uint32_t*)(g_dhhi[1 - p] + idx) = phi;
                *(uint32_t*)(g_dhlo[1 - p] + idx) = plo;

                if (l == 3) {
                    float part = v0 * linw0 + v1 * linw1;
#pragma unroll
                    for (int o = 8; o; o >>= 1)
                        part += __shfl_down_sync(0xffffffffu, part, o, 16);
                    if ((lane & 15) == 0)
                        g_o0p[1 - p][jt * NB + b0 + sr] = part;
                }
            }

            group_barrier(grp, 16);
        }
    }

    // ---- final output (t = NTGT-1) ----
    if (tid < 16 && jt == 0) {
        float o0 = lb0;
#pragma unroll
        for (int q = 0; q < 16; q++)
            o0 += __ldcg(&g_o0p[NTGT & 1][q * NB + b0 + tid]);
        out[(b0 + tid) * NTGT + (NTGT - 1)] = o0;
    }
}

// ---------------------------------------------------------------------------
// Launch sequence (graph-capturable: kernel launches only)
// ---------------------------------------------------------------------------
extern "C" void kernel_launch(void* const* d_in, const int* in_sizes, int n_in,
                              void* d_out, int out_size)
{
    const float* x        = (const float*)d_in[0];
    const float* enc_Wih0 = (const float*)d_in[2];
    const float* enc_Whh0 = (const float*)d_in[3];
    const float* enc_Wih1 = (const float*)d_in[4];
    const float* enc_Whh1 = (const float*)d_in[5];
    const float* enc_bih  = (const float*)d_in[6];
    const float* enc_bhh  = (const float*)d_in[7];
    const float* dec_Wih0 = (const float*)d_in[8];
    const float* dec_Wihr = (const float*)d_in[9];
    const float* dec_Whh  = (const float*)d_in[10];
    const float* dec_bih  = (const float*)d_in[11];
    const float* dec_bhh  = (const float*)d_in[12];
    const float* lin_W    = (const float*)d_in[13];
    const float* lin_b    = (const float*)d_in[14];
    float* out = (float*)d_out;

    cudaFuncSetAttribute(enc_mma, cudaFuncAttributeMaxDynamicSharedMemorySize,
                         ENC_SMEM);
    cudaFuncSetAttribute(dec_persist, cudaFuncAttributeMaxDynamicSharedMemorySize,
                         DEC_SMEM);
    cudaFuncSetAttribute(xs1_mma, cudaFuncAttributeMaxDynamicSharedMemorySize,
                         XS1_SMEM);

    // Pre-split Wih1 (independent of encoder)
    split_wih1<<<1024, 256>>>(enc_Wih1);

    // Encoder layer 0
    enc_mma<<<ENC_CTAS, 256, ENC_SMEM>>>(x, enc_Wih0, enc_Whh0,
                                         enc_bih, enc_bhh, 0);

    // Layer-1 input terms, pipelined tensor-core GEMM
    xs1_mma<<<dim3(8, 128, 2), 256, XS1_SMEM>>>(enc_bih, enc_bhh);

    // Encoder layer 1
    enc_mma<<<ENC_CTAS, 256, ENC_SMEM>>>(x, enc_Wih0, enc_Whh1,
                                         enc_bih, enc_bhh, 1);

    // Decoder (warp-specialized recurrent prefill)
    dec_persist<<<DEC_CTAS, 256, DEC_SMEM>>>(x, dec_Wih0, dec_Wihr, dec_Whh,
                                             dec_bih, dec_bhh, lin_W, lin_b, out);
}

// round 16
// speedup vs baseline: 3.9248x; 1.0049x over previous
#include <cuda_runtime.h>
#include <cuda_bf16.h>
#include <cstdint>

// Problem constants
constexpr int NB   = 128;   // batch
constexpr int NT   = 128;   // encoder time steps
constexpr int NIN  = 3;     // input features
constexpr int NH   = 512;   // hidden
constexpr int NTGT = 32;    // decoder steps

constexpr int ENC_CTAS = 256;   // 2 dirs x 8 bt x 16 jt, 2 CTAs/SM
constexpr int DEC_CTAS = 128;

// ---------------- encoder smem layout (R11/R12) ----------------
constexpr int EHS      = 520;                   // bf16 row stride (elements)
constexpr int E_UNION  = 32 * EHS * 2;          // W staging (32 rows) / h tile (16 rows)
constexpr int OFF_ESTG = 2 * E_UNION;           // [16][36] f32 stage
constexpr int OFF_EPRT = OFF_ESTG + 16 * 36 * 4;   // [4][16][36] f32 partials
constexpr int ENC_SMEM = OFF_EPRT + 4 * 16 * 36 * 4;   // 78080 B

// ---------------- decoder smem layout (R14: split W regions + sRec) --------
constexpr int DEHS     = 1032;                  // W row stride (1024 cols + pad)
constexpr int DHS      = 520;                   // h row stride (512 cols + pad)
constexpr int DW_TILE  = 32 * DEHS * 2;         // 66048 B per precision
constexpr int DH_TILE  = 16 * DHS * 2;          // 16640 B per precision
constexpr int OFF_DWHI = 0;
constexpr int OFF_DWLO = OFF_DWHI + DW_TILE;    // 66048
constexpr int OFF_DHHI = OFF_DWLO + DW_TILE;    // 132096
constexpr int OFF_DHLO = OFF_DHHI + DH_TILE;    // 148736
constexpr int OFF_DSTG = OFF_DHLO + DH_TILE;    // 165376  [16][36] f32
constexpr int OFF_DPRT = OFF_DSTG + 16 * 36 * 4;   // 167680 [2][16][36] f32 (B partials)
constexpr int OFF_DREC = OFF_DPRT + 2 * 16 * 36 * 4; // 172288 [4][2][16][36] f32
constexpr int DEC_SMEM = OFF_DREC + 4 * 2 * 16 * 36 * 4;  // 190720 B

constexpr int WMAT     = NH * NH;
constexpr int WIHR_OFF = 4 * WMAT;

// ---------------- xs1 mma smem layout (R12: double-buffered) ----------------
constexpr int XAS     = 72;
constexpr int X_SA    = 128 * XAS * 2;
constexpr int X_SB    = 64 * XAS * 2;
constexpr int X_STAGE = 2 * X_SA + 2 * X_SB;
constexpr int XS1_SMEM = 2 * X_STAGE;

// ---------------------------------------------------------------------------
// Static device scratch
// ---------------------------------------------------------------------------
__device__ __nv_bfloat16 g_l0hi[NT * NB * (2 * NH)];
__device__ __nv_bfloat16 g_l0lo[NT * NB * (2 * NH)];
__device__ __nv_bfloat16 g_xWhi[2 * NH * (2 * NH)];
__device__ __nv_bfloat16 g_xWlo[2 * NH * (2 * NH)];
__device__ float g_xs1[2 * NT * NB * NH];
__device__ __nv_bfloat16 g_hhi[2][2 * NB * NH];
__device__ __nv_bfloat16 g_hlo[2][2 * NB * NH];
__device__ __nv_bfloat16 g_dWhi[7 * WMAT];
__device__ __nv_bfloat16 g_dWlo[7 * WMAT];
__device__ __nv_bfloat16 g_dhhi[2][4 * NB * NH];
__device__ __nv_bfloat16 g_dhlo[2][4 * NB * NH];
__device__ float g_o0p[2][16 * NB];          // per-jt partial output dots
__device__ unsigned g_cnt;
__device__ unsigned g_gen;
__device__ unsigned g_gcnt[16 * 32];
__device__ unsigned g_ggen[16 * 32];

// ---------------------------------------------------------------------------
// Barriers (generation-based, self-resetting, replay-safe, leader fence)
// ---------------------------------------------------------------------------
__device__ __forceinline__ void grid_barrier(unsigned nctas)
{
    __syncthreads();
    if (threadIdx.x == 0) {
        __threadfence();
        volatile unsigned* genp = &g_gen;
        unsigned gen = *genp;
        if (atomicAdd(&g_cnt, 1u) == nctas - 1) {
            g_cnt = 0;
            __threadfence();
            *genp = gen + 1;
        } else {
            while (*genp == gen) { }
            __threadfence();
        }
    }
    __syncthreads();
}

__device__ __forceinline__ void group_barrier(int g, unsigned n)
{
    __syncthreads();
    if (threadIdx.x == 0) {
        __threadfence();
        volatile unsigned* genp = &g_ggen[g * 32];
        unsigned gen = *genp;
        if (atomicAdd(&g_gcnt[g * 32], 1u) == n - 1) {
            g_gcnt[g * 32] = 0;
            __threadfence();
            *genp = gen + 1;
        } else {
            while (*genp == gen) { }
            __threadfence();
        }
    }
    __syncthreads();
}

// ---------------------------------------------------------------------------
// mma.sync + cp.async helpers
// ---------------------------------------------------------------------------
__device__ __forceinline__ uint32_t s2u(const void* p)
{
    return (uint32_t)__cvta_generic_to_shared(p);
}

#define LDSM_X4(r0, r1, r2, r3, addr)                                          \
    asm volatile("ldmatrix.sync.aligned.m8n8.x4.shared.b16 {%0,%1,%2,%3}, [%4];" \
                 : "=r"(r0), "=r"(r1), "=r"(r2), "=r"(r3) : "r"(addr))

#define MMA_BF16(c0, c1, c2, c3, a0, a1, a2, a3, b0, b1)                       \
    asm volatile("mma.sync.aligned.m16n8k16.row.col.f32.bf16.bf16.f32 "        \
                 "{%0,%1,%2,%3}, {%4,%5,%6,%7}, {%8,%9}, {%0,%1,%2,%3};"       \
                 : "+f"(c0), "+f"(c1), "+f"(c2), "+f"(c3)                      \
                 : "r"(a0), "r"(a1), "r"(a2), "r"(a3), "r"(b0), "r"(b1))

#define CP_ASYNC16(saddr, gptr)                                                \
    asm volatile("cp.async.cg.shared.global [%0], [%1], 16;"                   \
                 :: "r"(saddr), "l"(gptr))
#define CP_COMMIT()  asm volatile("cp.async.commit_group;")
#define CP_WAIT0()   asm volatile("cp.async.wait_group 0;" ::: "memory")
#define CP_WAIT1()   asm volatile("cp.async.wait_group 1;" ::: "memory")

__device__ __forceinline__ void split_bf16(float v, __nv_bfloat16& hi, __nv_bfloat16& lo)
{
    hi = __float2bfloat16(v);
    lo = __float2bfloat16(v - __bfloat162float(hi));
}

// ---------------------------------------------------------------------------
// Pre-split Wih1 into bf16 hi/lo
// ---------------------------------------------------------------------------
__global__ void __launch_bounds__(256) split_wih1(const float* __restrict__ W)
{
    const int i = (blockIdx.x * 256 + threadIdx.x) * 4;
    if (i < 2 * NH * 2 * NH) {
        float4 w = *(const float4*)&W[i];
        split_bf16(w.x, g_xWhi[i + 0], g_xWlo[i + 0]);
        split_bf16(w.y, g_xWhi[i + 1], g_xWlo[i + 1]);
        split_bf16(w.z, g_xWhi[i + 2], g_xWlo[i + 2]);
        split_bf16(w.w, g_xWhi[i + 3], g_xWlo[i + 3]);
    }
}

// ---------------------------------------------------------------------------
// Persistent encoder layer (R14 = R12 h-staging + light barrier + init hoist)
// ---------------------------------------------------------------------------
__global__ void __launch_bounds__(256, 2) enc_mma(
    const float* __restrict__ x, const float* __restrict__ Wih0,
    const float* __restrict__ Whh_all, const float* __restrict__ bih,
    const float* __restrict__ bhh, int layer)
{
    extern __shared__ char sm[];
    __nv_bfloat16* sHhi = (__nv_bfloat16*)(sm);
    __nv_bfloat16* sHlo = (__nv_bfloat16*)(sm + E_UNION);
    float*         sStg = (float*)(sm + OFF_ESTG);
    float*         sPrt = (float*)(sm + OFF_EPRT);

    const int blk = blockIdx.x;
    const int d   = blk >> 7;
    const int rem = blk & 127;
    const int bt  = rem >> 4;
    const int jt  = rem & 15;
    const int grp = blk >> 4;
    const int b0  = bt * 16;
    const int j0  = jt * 32;
    const int tid = threadIdx.x;
    const int lane = tid & 31;
    const int warp = tid >> 5;
    const int kw   = warp & 3;
    const int mj   = warp >> 2;

    const float* Whh = Whh_all + d * NH * NH;

    // ---- one-time: stage W tile (bf16 hi/lo) into smem ----
    {
        const int r  = tid >> 3;
        const int c0 = (tid & 7) * 4;
        for (int k0 = 0; k0 < NH; k0 += 32) {
            float4 w = __ldg((const float4*)&Whh[(j0 + r) * NH + k0 + c0]);
            const int o = r * EHS + k0 + c0;
            split_bf16(w.x, sHhi[o + 0], sHlo[o + 0]);
            split_bf16(w.y, sHhi[o + 1], sHlo[o + 1]);
            split_bf16(w.z, sHhi[o + 2], sHlo[o + 2]);
            split_bf16(w.w, sHhi[o + 3], sHlo[o + 3]);
        }
    }
    __syncthreads();

    // ---- preload A fragments into registers ----
    uint32_t aHi[8][4], aLo[8][4];
    {
        const int ag = lane >> 3, ar = lane & 7;
        const uint32_t rowOff = (uint32_t)((mj * 16 + (ag & 1) * 8 + ar) * EHS) * 2;
        const uint32_t colSel = (uint32_t)(kw * 128 + (ag >> 1) * 8) * 2;
#pragma unroll
        for (int q = 0; q < 8; q++) {
            const uint32_t off = rowOff + colSel + q * 32;
            LDSM_X4(aHi[q][0], aHi[q][1], aHi[q][2], aHi[q][3], s2u(sHhi) + off);
            LDSM_X4(aLo[q][0], aLo[q][1], aLo[q][2], aLo[q][3], s2u(sHlo) + off);
        }
    }

    // ---- B (h) ldmatrix bases ----
    const uint32_t bOff = (uint32_t)(((lane >> 4) * 8 + (lane & 7)) * EHS
                                     + ((lane >> 3) & 1) * 8 + kw * 128) * 2;
    const uint32_t bHiBase = s2u(sHhi) + bOff;
    const uint32_t bLoBase = s2u(sHlo) + bOff;

    // ---- owner slots + layer-0 constants ----
    const int sr = tid >> 4;
    const int sj = (tid & 15) * 2;
    float bias0 = 0.f, bias1 = 0.f, wi[6];
    if (layer == 0) {
        bias0 = bih[d * NH + j0 + sj + 0] + bhh[d * NH + j0 + sj + 0];
        bias1 = bih[d * NH + j0 + sj + 1] + bhh[d * NH + j0 + sj + 1];
        const float* wp = Wih0 + (d * NH + j0 + sj) * NIN;
#pragma unroll
        for (int i = 0; i < 6; i++) wi[i] = wp[i];
    }

    // ---- stage init for t = 0 ----
    {
        const int td0 = d ? (NT - 1) : 0;
        float v0, v1;
        if (layer == 0) {
            const float* xr = x + ((b0 + sr) * NT + td0) * NIN;
            const float x0 = xr[0], x1 = xr[1], x2 = xr[2];
            v0 = bias0 + x0 * wi[0] + x1 * wi[1] + x2 * wi[2];
            v1 = bias1 + x0 * wi[3] + x1 * wi[4] + x2 * wi[5];
        } else {
            float2 v = __ldg((const float2*)&g_xs1[((d * NT + td0) * NB + b0 + sr) * NH + j0 + sj]);
            v0 = v.x; v1 = v.y;
        }
        sStg[sr * 36 + sj + 0] = v0;
        sStg[sr * 36 + sj + 1] = v1;
    }
    __syncthreads();   // W smem dead; region reused for h

    const int jl = mj * 16 + (lane >> 2);
    const int bl = (lane & 3) * 2;
    float* pp = sPrt + kw * (16 * 36);

    for (int t = 0; t < NT; t++) {
        const int td = d ? (NT - 1 - t) : t;

        // ---- stage h tile (16 rows, __ldcg batch, proven R12) ----
        if (t > 0) {
            const int p = t & 1;
            const __nv_bfloat16* srcHi = g_hhi[p] + (d * NB + b0) * NH;
            const __nv_bfloat16* srcLo = g_hlo[p] + (d * NB + b0) * NH;
            const int r  = tid >> 4;
            const int cc = tid & 15;
#pragma unroll
            for (int it = 0; it < 4; it++) {
                const int c16 = cc + it * 16;
                uint4 vh = __ldcg((const uint4*)(srcHi + r * NH) + c16);
                uint4 vl = __ldcg((const uint4*)(srcLo + r * NH) + c16);
                *(uint4*)((char*)sHhi + r * (EHS * 2) + c16 * 16) = vh;
                *(uint4*)((char*)sHlo + r * (EHS * 2) + c16 * 16) = vl;
            }
        }
        __syncthreads();

        // ---- MMA over this warp's K quarter (A from registers) ----
        if (t > 0) {
            float acc[2][4];
#pragma unroll
            for (int n = 0; n < 2; n++)
#pragma unroll
                for (int q = 0; q < 4; q++) acc[n][q] = 0.f;

#pragma unroll
            for (int q = 0; q < 8; q++) {
                uint32_t r0, r1, r2, r3, f0, f1, f2, f3;
                LDSM_X4(r0, r1, r2, r3, bHiBase + q * 32);
                LDSM_X4(f0, f1, f2, f3, bLoBase + q * 32);
                MMA_BF16(acc[0][0], acc[0][1], acc[0][2], acc[0][3],
                         aHi[q][0], aHi[q][1], aHi[q][2], aHi[q][3], r0, r1);
                MMA_BF16(acc[0][0], acc[0][1], acc[0][2], acc[0][3],
                         aHi[q][0], aHi[q][1], aHi[q][2], aHi[q][3], f0, f1);
                MMA_BF16(acc[0][0], acc[0][1], acc[0][2], acc[0][3],
                         aLo[q][0], aLo[q][1], aLo[q][2], aLo[q][3], r0, r1);
                MMA_BF16(acc[1][0], acc[1][1], acc[1][2], acc[1][3],
                         aHi[q][0], aHi[q][1], aHi[q][2], aHi[q][3], r2, r3);
                MMA_BF16(acc[1][0], acc[1][1], acc[1][2], acc[1][3],
                         aHi[q][0], aHi[q][1], aHi[q][2], aHi[q][3], f2, f3);
                MMA_BF16(acc[1][0], acc[1][1], acc[1][2], acc[1][3],
                         aLo[q][0], aLo[q][1], aLo[q][2], aLo[q][3], r2, r3);
            }
#pragma unroll
            for (int n = 0; n < 2; n++) {
                pp[(n * 8 + bl + 0) * 36 + jl]     = acc[n][0];
                pp[(n * 8 + bl + 1) * 36 + jl]     = acc[n][1];
                pp[(n * 8 + bl + 0) * 36 + jl + 8] = acc[n][2];
                pp[(n * 8 + bl + 1) * 36 + jl + 8] = acc[n][3];
            }
        }
        __syncthreads();

        // ---- owner epilogue: reduce + tanh + split + store + next init ----
        {
            float v0 = sStg[sr * 36 + sj + 0];
            float v1 = sStg[sr * 36 + sj + 1];
            if (t > 0) {
#pragma unroll
                for (int q = 0; q < 4; q++) {
                    v0 += sPrt[q * 576 + sr * 36 + sj + 0];
                    v1 += sPrt[q * 576 + sr * 36 + sj + 1];
                }
            }
            v0 = tanhf(v0); v1 = tanhf(v1);

            __nv_bfloat16 h0, h1, l0b, l1b;
            split_bf16(v0, h0, l0b);
            split_bf16(v1, h1, l1b);
            const int p1 = (t + 1) & 1;
            const int gidx = (d * NB + b0 + sr) * NH + j0 + sj;
            uint32_t phi = (uint32_t)__bfloat16_as_ushort(h0) |
                           ((uint32_t)__bfloat16_as_ushort(h1) << 16);
            uint32_t plo = (uint32_t)__bfloat16_as_ushort(l0b) |
                           ((uint32_t)__bfloat16_as_ushort(l1b) << 16);
            *(uint32_t*)(g_hhi[p1] + gidx) = phi;
            *(uint32_t*)(g_hlo[p1] + gidx) = plo;
            if (layer == 0) {
                const int li = (td * NB + b0 + sr) * (2 * NH) + d * NH + j0 + sj;
                *(uint32_t*)(g_l0hi + li) = phi;
                *(uint32_t*)(g_l0lo + li) = plo;
            }
            if (t == NT - 1) {
                const int slot = (layer ? 2 : 0) + d;
                const int di = (slot * NB + b0 + sr) * NH + j0 + sj;
                *(uint32_t*)(g_dhhi[0] + di) = phi;
                *(uint32_t*)(g_dhlo[0] + di) = plo;
            }

            if (t < NT - 1) {
                const int td2 = d ? (NT - 2 - t) : (t + 1);
                float n0, n1;
                if (layer == 0) {
                    const float* xr = x + ((b0 + sr) * NT + td2) * NIN;
                    const float x0 = xr[0], x1 = xr[1], x2 = xr[2];
                    n0 = bias0 + x0 * wi[0] + x1 * wi[1] + x2 * wi[2];
                    n1 = bias1 + x0 * wi[3] + x1 * wi[4] + x2 * wi[5];
                } else {
                    float2 v = __ldg((const float2*)&g_xs1[((d * NT + td2) * NB + b0 + sr) * NH + j0 + sj]);
                    n0 = v.x; n1 = v.y;
                }
                sStg[sr * 36 + sj + 0] = n0;
                sStg[sr * 36 + sj + 1] = n1;
            }
        }

        if (t < NT - 1)
            group_barrier(grp, 16);
    }
}

// ---------------------------------------------------------------------------
// xs1 via tensor cores (R12, unchanged): 2-stage cp.async pipelined GEMM.
// ---------------------------------------------------------------------------
__device__ __forceinline__ void xs1_stage(uint32_t sbase, int d, int j0, int m0,
                                          int k0, int tid)
{
    const int r  = tid >> 3;
    const int c8 = (tid & 7) * 8;
#pragma unroll
    for (int rr = r; rr < 128; rr += 32) {
        const int gi = (m0 + rr) * (2 * NH) + k0 + c8;
        CP_ASYNC16(sbase + (uint32_t)((rr * XAS + c8) * 2),        g_l0hi + gi);
        CP_ASYNC16(sbase + (uint32_t)(X_SA + (rr * XAS + c8) * 2), g_l0lo + gi);
    }
#pragma unroll
    for (int rr = r; rr < 64; rr += 32) {
        const int gi = (d * NH + j0 + rr) * (2 * NH) + k0 + c8;
        CP_ASYNC16(sbase + (uint32_t)(2 * X_SA + (rr * XAS + c8) * 2),        g_xWhi + gi);
        CP_ASYNC16(sbase + (uint32_t)(2 * X_SA + X_SB + (rr * XAS + c8) * 2), g_xWlo + gi);
    }
    CP_COMMIT();
}

__global__ void __launch_bounds__(256) xs1_mma(
    const float* __restrict__ bih, const float* __restrict__ bhh)
{
    extern __shared__ char sm[];
    const uint32_t smBase = s2u(sm);

    const int d  = blockIdx.z;
    const int j0 = blockIdx.x * 64;
    const int m0 = blockIdx.y * 128;
    const int tid  = threadIdx.x;
    const int lane = tid & 31;
    const int warp = tid >> 5;
    const int wm = warp & 3;
    const int wn = warp >> 2;

    const int ag = lane >> 3, ar = lane & 7;
    const uint32_t aOff = (uint32_t)((wm * 32 + (ag & 1) * 8 + ar) * XAS + (ag >> 1) * 8) * 2;
    const uint32_t bOff = (uint32_t)(2 * X_SA) +
        (uint32_t)((wn * 32 + (lane >> 4) * 8 + (lane & 7)) * XAS + ((lane >> 3) & 1) * 8) * 2;

    float acc[2][4][4];
#pragma unroll
    for (int i = 0; i < 2; i++)
#pragma unroll
        for (int n = 0; n < 4; n++)
#pragma unroll
            for (int q = 0; q < 4; q++) acc[i][n][q] = 0.f;

    xs1_stage(smBase, d, j0, m0, 0, tid);

    for (int c = 0; c < 16; c++) {
        if (c < 15)
            xs1_stage(smBase + ((c + 1) & 1) * X_STAGE, d, j0, m0, (c + 1) * 64, tid);
        if (c < 15) { CP_WAIT1(); } else { CP_WAIT0(); }
        __syncthreads();

        const uint32_t aBase = smBase + (c & 1) * X_STAGE + aOff;
        const uint32_t bBase = smBase + (c & 1) * X_STAGE + bOff;

#pragma unroll
        for (int kk = 0; kk < 4; kk++) {
            uint32_t ah[2][4], al[2][4];
#pragma unroll
            for (int mt = 0; mt < 2; mt++) {
                const uint32_t addr = aBase + (uint32_t)(mt * 16 * XAS + kk * 16) * 2;
                LDSM_X4(ah[mt][0], ah[mt][1], ah[mt][2], ah[mt][3], addr);
                LDSM_X4(al[mt][0], al[mt][1], al[mt][2], al[mt][3], addr + X_SA);
            }
#pragma unroll
            for (int np = 0; np < 2; np++) {
                const uint32_t addr = bBase + (uint32_t)(np * 16 * XAS + kk * 16) * 2;
                uint32_t bh0, bh1, bh2, bh3, bl0, bl1, bl2, bl3;
                LDSM_X4(bh0, bh1, bh2, bh3, addr);
                LDSM_X4(bl0, bl1, bl2, bl3, addr + X_SB);
#pragma unroll
                for (int mt = 0; mt < 2; mt++) {
                    float* a0 = acc[mt][np * 2 + 0];
                    float* a1 = acc[mt][np * 2 + 1];
                    MMA_BF16(a0[0], a0[1], a0[2], a0[3],
                             ah[mt][0], ah[mt][1], ah[mt][2], ah[mt][3], bh0, bh1);
                    MMA_BF16(a0[0], a0[1], a0[2], a0[3],
                             ah[mt][0], ah[mt][1], ah[mt][2], ah[mt][3], bl0, bl1);
                    MMA_BF16(a0[0], a0[1], a0[2], a0[3],
                             al[mt][0], al[mt][1], al[mt][2], al[mt][3], bh0, bh1);
                    MMA_BF16(a1[0], a1[1], a1[2], a1[3],
                             ah[mt][0], ah[mt][1], ah[mt][2], ah[mt][3], bh2, bh3);
                    MMA_BF16(a1[0], a1[1], a1[2], a1[3],
                             ah[mt][0], ah[mt][1], ah[mt][2], ah[mt][3], bl2, bl3);
                    MMA_BF16(a1[0], a1[1], a1[2], a1[3],
                             al[mt][0], al[mt][1], al[mt][2], al[mt][3], bh2, bh3);
                }
            }
        }
        __syncthreads();
    }

#pragma unroll
    for (int nt = 0; nt < 4; nt++) {
        const int j = j0 + wn * 32 + nt * 8 + (lane & 3) * 2;
        const float bj0 = __ldg(&bih[(2 + d) * NH + j])     + __ldg(&bhh[(2 + d) * NH + j]);
        const float bj1 = __ldg(&bih[(2 + d) * NH + j + 1]) + __ldg(&bhh[(2 + d) * NH + j + 1]);
#pragma unroll
        for (int mt = 0; mt < 2; mt++) {
            const int m = m0 + wm * 32 + mt * 16 + (lane >> 2);
            *(float2*)&g_xs1[(d * NT * NB + m) * NH + j] =
                make_float2(acc[mt][nt][0] + bj0, acc[mt][nt][1] + bj1);
            *(float2*)&g_xs1[(d * NT * NB + m + 8) * NH + j] =
                make_float2(acc[mt][nt][2] + bj0, acc[mt][nt][3] + bj1);
        }
    }
}

// ---------------------------------------------------------------------------
// Decoder W prefetch: Wihr[lB-1] -> cols 0-511 (if lB>=1), Whh[lR] -> cols 512+
// ---------------------------------------------------------------------------
__device__ __forceinline__ void dec_prefetch_W(int lB, int lR, int j0, int tid,
                                               uint32_t swhi, uint32_t swlo)
{
    const int r  = tid >> 3;
    const int c8 = tid & 7;
    if (lB >= 1) {
        const __nv_bfloat16* shi = g_dWhi + WIHR_OFF + (lB - 1) * WMAT + (j0 + r) * NH;
        const __nv_bfloat16* slo = g_dWlo + WIHR_OFF + (lB - 1) * WMAT + (j0 + r) * NH;
#pragma unroll
        for (int c = c8; c < 64; c += 8) {
            CP_ASYNC16(swhi + (uint32_t)(r * DEHS + c * 8) * 2, shi + c * 8);
            CP_ASYNC16(swlo + (uint32_t)(r * DEHS + c * 8) * 2, slo + c * 8);
        }
    }
    {
        const __nv_bfloat16* rhi = g_dWhi + lR * WMAT + (j0 + r) * NH;
        const __nv_bfloat16* rlo = g_dWlo + lR * WMAT + (j0 + r) * NH;
#pragma unroll
        for (int c = c8; c < 64; c += 8) {
            CP_ASYNC16(swhi + (uint32_t)(r * DEHS + 512 + c * 8) * 2, rhi + c * 8);
            CP_ASYNC16(swlo + (uint32_t)(r * DEHS + 512 + c * 8) * 2, rlo + c * 8);
        }
    }
    CP_COMMIT();
}

// ---------------------------------------------------------------------------
// Persistent decoder (R14): warp-specialized. Warps 0-3 (role 0) run the
// critical input-GEMM chain; warps 4-7 (role 1) compute next-step recurrent
// GEMMs (Whh_l . h_l) off the critical path, sharing the same staged h tile.
// Schedule: phase P_l(t) -> role1 computes R_{(l+3)%4} for its consumer phase;
// prologue seeds R_0..R_2(0) from hn.
// ---------------------------------------------------------------------------
__global__ void __launch_bounds__(256) dec_persist(
    const float* __restrict__ x,    const float* __restrict__ Wih0,
    const float* __restrict__ Wihr, const float* __restrict__ Whh,
    const float* __restrict__ bih,  const float* __restrict__ bhh,
    const float* __restrict__ linW, const float* __restrict__ linb,
    float* __restrict__ out)
{
    extern __shared__ char sm[];
    __nv_bfloat16* sWhi = (__nv_bfloat16*)(sm + OFF_DWHI);
    __nv_bfloat16* sWlo = (__nv_bfloat16*)(sm + OFF_DWLO);
    __nv_bfloat16* sHhi = (__nv_bfloat16*)(sm + OFF_DHHI);
    __nv_bfloat16* sHlo = (__nv_bfloat16*)(sm + OFF_DHLO);
    float*         sStg = (float*)(sm + OFF_DSTG);   // [16][36]
    float*         sPrt = (float*)(sm + OFF_DPRT);   // [2][16][36] (B partials)
    float*         sRec = (float*)(sm + OFF_DREC);   // [4][2][16][36]

    __shared__ float s_dec[16][3];

    const int jt = blockIdx.x & 15;
    const int bt = blockIdx.x >> 4;
    const int grp = 8 + bt;
    const int j0 = jt * 32;
    const int b0 = bt * 16;
    const int tid  = threadIdx.x;
    const int lane = tid & 31;
    const int warp = tid >> 5;
    const int mj   = warp & 1;          // j half (16 rows)
    const int kh   = (warp >> 1) & 1;   // k half (256 cols)
    const int role = warp >> 2;         // 0 = input chain, 1 = recurrent

    // one-time: convert decoder weights to bf16 hi/lo (grid-strided)
    {
        const int stride4 = DEC_CTAS * 256 * 4;
        const int g4 = (blockIdx.x * 256 + tid) * 4;
        for (int i = g4; i < 4 * WMAT; i += stride4) {
            float4 w = *(const float4*)&Whh[i];
            split_bf16(w.x, g_dWhi[i + 0], g_dWlo[i + 0]);
            split_bf16(w.y, g_dWhi[i + 1], g_dWlo[i + 1]);
            split_bf16(w.z, g_dWhi[i + 2], g_dWlo[i + 2]);
            split_bf16(w.w, g_dWhi[i + 3], g_dWlo[i + 3]);
        }
        for (int i = g4; i < 3 * WMAT; i += stride4) {
            float4 w = *(const float4*)&Wihr[i];
            split_bf16(w.x, g_dWhi[WIHR_OFF + i + 0], g_dWlo[WIHR_OFF + i + 0]);
            split_bf16(w.y, g_dWhi[WIHR_OFF + i + 1], g_dWlo[WIHR_OFF + i + 1]);
            split_bf16(w.z, g_dWhi[WIHR_OFF + i + 2], g_dWlo[WIHR_OFF + i + 2]);
            split_bf16(w.w, g_dWhi[WIHR_OFF + i + 3], g_dWlo[WIHR_OFF + i + 3]);
        }
    }
    if (tid < 16) {
        const float* xr = x + ((b0 + tid) * NT + (NT - 1)) * NIN;
        s_dec[tid][0] = xr[0];
        s_dec[tid][1] = xr[1];
        s_dec[tid][2] = xr[2];
    }
    grid_barrier(DEC_CTAS);

    // ---- ldmatrix bases ----
    const int ag = lane >> 3, ar = lane & 7;
    const uint32_t aOff = (uint32_t)((mj * 16 + (ag & 1) * 8 + ar) * DEHS
                                     + (ag >> 1) * 8 + role * 512 + kh * 256) * 2;
    const uint32_t aHiBase = s2u(sWhi) + aOff;
    const uint32_t aLoBase = s2u(sWlo) + aOff;
    const uint32_t bOff = (uint32_t)(((lane >> 4) * 8 + (lane & 7)) * DHS
                                     + ((lane >> 3) & 1) * 8 + kh * 256) * 2;
    const uint32_t bHiBase = s2u(sHhi) + bOff;
    const uint32_t bLoBase = s2u(sHlo) + bOff;

    const int sr = tid >> 4;
    const int sj = (tid & 15) * 2;
    const int jl = mj * 16 + (lane >> 2);
    const int bl = (lane & 3) * 2;

    const float linw0 = __ldg(&linW[j0 + sj + 0]);
    const float linw1 = __ldg(&linW[j0 + sj + 1]);
    const float lb0   = __ldg(&linb[0]);

    // ---- stage-h helper captured by lambda-ish macro (inline each use) ----
    // ---- prologue: seed sRec[0..2] = Whh_l . hn_l (local, no barriers) ----
    for (int l = 0; l < 3; l++) {
        {   // stage hn_l + Whh_l (R region)
            const int r   = tid >> 4;
            const int c16 = tid & 15;
            const __nv_bfloat16* rhi = g_dhhi[0] + (l * NB + b0 + r) * NH;
            const __nv_bfloat16* rlo = g_dhlo[0] + (l * NB + b0 + r) * NH;
#pragma unroll
            for (int c = c16; c < 64; c += 16) {
                CP_ASYNC16(s2u(sHhi) + (uint32_t)(r * DHS + c * 8) * 2, rhi + c * 8);
                CP_ASYNC16(s2u(sHlo) + (uint32_t)(r * DHS + c * 8) * 2, rlo + c * 8);
            }
            const int wr = tid >> 3, wc = tid & 7;
            const __nv_bfloat16* whi = g_dWhi + l * WMAT + (j0 + wr) * NH;
            const __nv_bfloat16* wlo = g_dWlo + l * WMAT + (j0 + wr) * NH;
#pragma unroll
            for (int c = wc; c < 64; c += 8) {
                CP_ASYNC16(s2u(sWhi) + (uint32_t)(wr * DEHS + 512 + c * 8) * 2, whi + c * 8);
                CP_ASYNC16(s2u(sWlo) + (uint32_t)(wr * DEHS + 512 + c * 8) * 2, wlo + c * 8);
            }
            CP_COMMIT();
        }
        CP_WAIT0();
        __syncthreads();
        if (role == 1) {
            float c00 = 0.f, c01 = 0.f, c02 = 0.f, c03 = 0.f;
            float c10 = 0.f, c11 = 0.f, c12 = 0.f, c13 = 0.f;
            uint32_t aHi = aHiBase, aLo = aLoBase, bHi = bHiBase, bLo = bLoBase;
#pragma unroll 4
            for (int kk = 0; kk < 16; kk++) {
                uint32_t a0, a1, a2, a3, e0, e1, e2, e3;
                uint32_t r0, r1, r2, r3, f0, f1, f2, f3;
                LDSM_X4(a0, a1, a2, a3, aHi);
                LDSM_X4(e0, e1, e2, e3, aLo);
                LDSM_X4(r0, r1, r2, r3, bHi);
                LDSM_X4(f0, f1, f2, f3, bLo);
                MMA_BF16(c00, c01, c02, c03, a0, a1, a2, a3, r0, r1);
                MMA_BF16(c00, c01, c02, c03, a0, a1, a2, a3, f0, f1);
                MMA_BF16(c00, c01, c02, c03, e0, e1, e2, e3, r0, r1);
                MMA_BF16(c10, c11, c12, c13, a0, a1, a2, a3, r2, r3);
                MMA_BF16(c10, c11, c12, c13, a0, a1, a2, a3, f2, f3);
                MMA_BF16(c10, c11, c12, c13, e0, e1, e2, e3, r2, r3);
                aHi += 32; aLo += 32; bHi += 32; bLo += 32;
            }
            float* pp = sRec + (l * 2 + kh) * 576;
            pp[(bl + 0) * 36 + jl]     = c00;
            pp[(bl + 1) * 36 + jl]     = c01;
            pp[(bl + 0) * 36 + jl + 8] = c02;
            pp[(bl + 1) * 36 + jl + 8] = c03;
            pp[(bl + 8) * 36 + jl]     = c10;
            pp[(bl + 9) * 36 + jl]     = c11;
            pp[(bl + 8) * 36 + jl + 8] = c12;
            pp[(bl + 9) * 36 + jl + 8] = c13;
        }
        __syncthreads();
    }
    // prefetch for P0(0): Whh_3 only
    dec_prefetch_W(0, 3, j0, tid, s2u(sWhi), s2u(sWlo));

    for (int t = 0; t < NTGT; t++) {
        const int p = t & 1;

        // ---- feedback from step t-1: sum 16 per-jt partials ----
        if (t > 0) {
            if (tid < 16) {
                float o0 = lb0;
#pragma unroll
                for (int q = 0; q < 16; q++)
                    o0 += __ldcg(&g_o0p[p][q * NB + b0 + tid]);
                if (jt == 0) out[(b0 + tid) * NTGT + (t - 1)] = o0;
                float s1 = s_dec[tid][0] - o0;
                float s2 = s_dec[tid][1] - s1;
                s_dec[tid][0] = o0;
                s_dec[tid][1] = s1;
                s_dec[tid][2] = s2;
            }
            __syncthreads();
        }

        for (int l = 0; l < 4; l++) {
            // ---- stage h tile: l==0 -> h_3(t-1) [g_dh(p)]; else h_{l-1}(t) ----
            {
                const int r   = tid >> 4;
                const int c16 = tid & 15;
                const __nv_bfloat16* rhi;
                const __nv_bfloat16* rlo;
                if (l == 0) {
                    rhi = g_dhhi[p] + (3 * NB + b0 + r) * NH;
                    rlo = g_dhlo[p] + (3 * NB + b0 + r) * NH;
                } else {
                    rhi = g_dhhi[1 - p] + ((l - 1) * NB + b0 + r) * NH;
                    rlo = g_dhlo[1 - p] + ((l - 1) * NB + b0 + r) * NH;
                }
#pragma unroll
                for (int c = c16; c < 64; c += 16) {
                    CP_ASYNC16(s2u(sHhi) + (uint32_t)(r * DHS + c * 8) * 2, rhi + c * 8);
                    CP_ASYNC16(s2u(sHlo) + (uint32_t)(r * DHS + c * 8) * 2, rlo + c * 8);
                }
                CP_COMMIT();
            }
            // ---- stage init ----
            {
                float v0 = bih[l * NH + j0 + sj + 0] + bhh[l * NH + j0 + sj + 0];
                float v1 = bih[l * NH + j0 + sj + 1] + bhh[l * NH + j0 + sj + 1];
                if (l == 0) {
                    const float i0 = s_dec[sr][0], i1 = s_dec[sr][1], i2 = s_dec[sr][2];
                    const float* wp = Wih0 + (j0 + sj) * NIN;
                    v0 += i0 * wp[0] + i1 * wp[1] + i2 * wp[2];
                    v1 += i0 * wp[3] + i1 * wp[4] + i2 * wp[5];
                }
                sStg[sr * 36 + sj + 0] = v0;
                sStg[sr * 36 + sj + 1] = v1;
            }
            CP_WAIT0();     // h (this phase) + W (prefetched last phase)
            __syncthreads();

            // ---- MMA: role0 = input gemm (l>=1); role1 = recurrent prefill ----
            if (role == 1 || l >= 1) {
                float c00 = 0.f, c01 = 0.f, c02 = 0.f, c03 = 0.f;
                float c10 = 0.f, c11 = 0.f, c12 = 0.f, c13 = 0.f;
                uint32_t aHi = aHiBase, aLo = aLoBase, bHi = bHiBase, bLo = bLoBase;
#pragma unroll 4
                for (int kk = 0; kk < 16; kk++) {
                    uint32_t a0, a1, a2, a3, e0, e1, e2, e3;
                    uint32_t r0, r1, r2, r3, f0, f1, f2, f3;
                    LDSM_X4(a0, a1, a2, a3, aHi);
                    LDSM_X4(e0, e1, e2, e3, aLo);
                    LDSM_X4(r0, r1, r2, r3, bHi);
                    LDSM_X4(f0, f1, f2, f3, bLo);
                    MMA_BF16(c00, c01, c02, c03, a0, a1, a2, a3, r0, r1);
                    MMA_BF16(c00, c01, c02, c03, a0, a1, a2, a3, f0, f1);
                    MMA_BF16(c00, c01, c02, c03, e0, e1, e2, e3, r0, r1);
                    MMA_BF16(c10, c11, c12, c13, a0, a1, a2, a3, r2, r3);
                    MMA_BF16(c10, c11, c12, c13, a0, a1, a2, a3, f2, f3);
                    MMA_BF16(c10, c11, c12, c13, e0, e1, e2, e3, r2, r3);
                    aHi += 32; aLo += 32; bHi += 32; bLo += 32;
                }
                float* pp = (role == 0) ? (sPrt + kh * 576)
                                        : (sRec + (((l + 3) & 3) * 2 + kh) * 576);
                pp[(bl + 0) * 36 + jl]     = c00;
                pp[(bl + 1) * 36 + jl]     = c01;
                pp[(bl + 0) * 36 + jl + 8] = c02;
                pp[(bl + 1) * 36 + jl + 8] = c03;
                pp[(bl + 8) * 36 + jl]     = c10;
                pp[(bl + 9) * 36 + jl]     = c11;
                pp[(bl + 8) * 36 + jl + 8] = c12;
                pp[(bl + 9) * 36 + jl + 8] = c13;
            }
            __syncthreads();

            // ---- prefetch next phase's W (overlaps epilogue + barrier) ----
            if (!(t == NTGT - 1 && l == 3)) {
                const int ln = (l + 1) & 3;
                dec_prefetch_W(ln, (ln + 3) & 3, j0, tid, s2u(sWhi), s2u(sWlo));
            }

            // ---- owner epilogue: init + B partials + sRec[l], tanh, store ----
            {
                float v0 = sStg[sr * 36 + sj + 0];
                float v1 = sStg[sr * 36 + sj + 1];
                if (l >= 1) {
#pragma unroll
                    for (int q = 0; q < 2; q++) {
                        v0 += sPrt[q * 576 + sr * 36 + sj + 0];
                        v1 += sPrt[q * 576 + sr * 36 + sj + 1];
                    }
                }
#pragma unroll
                for (int q = 0; q < 2; q++) {
                    v0 += sRec[(l * 2 + q) * 576 + sr * 36 + sj + 0];
                    v1 += sRec[(l * 2 + q) * 576 + sr * 36 + sj + 1];
                }
                v0 = tanhf(v0); v1 = tanhf(v1);
                __nv_bfloat16 h0, h1, l0b, l1b;
                split_bf16(v0, h0, l0b);
                split_bf16(v1, h1, l1b);
                const int idx = (l * NB + b0 + sr) * NH + j0 + sj;
                uint32_t phi = (uint32_t)__bfloat16_as_ushort(h0) |
                               ((uint32_t)__bfloat16_as_ushort(h1) << 16);
                uint32_t plo = (uint32_t)__bfloat16_as_ushort(l0b) |
                               ((uint32_t)__bfloat16_as_ushort(l1b) << 16);
                *(uint32_t*)(g_dhhi[1 - p] + idx) = phi;
                *(uint32_t*)(g_dhlo[1 - p] + idx) = plo;

                if (l == 3) {
                    float part = v0 * linw0 + v1 * linw1;
#pragma unroll
                    for (int o = 8; o; o >>= 1)
                        part += __shfl_down_sync(0xffffffffu, part, o, 16);
                    if ((lane & 15) == 0)
                        g_o0p[1 - p][jt * NB + b0 + sr] = part;
                }
            }

            group_barrier(grp, 16);
        }
    }

    // ---- final output (t = NTGT-1) ----
    if (tid < 16 && jt == 0) {
        float o0 = lb0;
#pragma unroll
        for (int q = 0; q < 16; q++)
            o0 += __ldcg(&g_o0p[NTGT & 1][q * NB + b0 + tid]);
        out[(b0 + tid) * NTGT + (NTGT - 1)] = o0;
    }
}

// ---------------------------------------------------------------------------
// Launch sequence (graph-capturable: kernel launches only)
// ---------------------------------------------------------------------------
extern "C" void kernel_launch(void* const* d_in, const int* in_sizes, int n_in,
                              void* d_out, int out_size)
{
    const float* x        = (const float*)d_in[0];
    const float* enc_Wih0 = (const float*)d_in[2];
    const float* enc_Whh0 = (const float*)d_in[3];
    const float* enc_Wih1 = (const float*)d_in[4];
    const float* enc_Whh1 = (const float*)d_in[5];
    const float* enc_bih  = (const float*)d_in[6];
    const float* enc_bhh  = (const float*)d_in[7];
    const float* dec_Wih0 = (const float*)d_in[8];
    const float* dec_Wihr = (const float*)d_in[9];
    const float* dec_Whh  = (const float*)d_in[10];
    const float* dec_bih  = (const float*)d_in[11];
    const float* dec_bhh  = (const float*)d_in[12];
    const float* lin_W    = (const float*)d_in[13];
    const float* lin_b    = (const float*)d_in[14];
    float* out = (float*)d_out;

    cudaFuncSetAttribute(enc_mma, cudaFuncAttributeMaxDynamicSharedMemorySize,
                         ENC_SMEM);
    cudaFuncSetAttribute(dec_persist, cudaFuncAttributeMaxDynamicSharedMemorySize,
                         DEC_SMEM);
    cudaFuncSetAttribute(xs1_mma, cudaFuncAttributeMaxDynamicSharedMemorySize,
                         XS1_SMEM);

    // Pre-split Wih1 (independent of encoder)
    split_wih1<<<1024, 256>>>(enc_Wih1);

    // Encoder layer 0
    enc_mma<<<ENC_CTAS, 256, ENC_SMEM>>>(x, enc_Wih0, enc_Whh0,
                                         enc_bih, enc_bhh, 0);

    // Layer-1 input terms, pipelined tensor-core GEMM
    xs1_mma<<<dim3(8, 128, 2), 256, XS1_SMEM>>>(enc_bih, enc_bhh);

    // Encoder layer 1
    enc_mma<<<ENC_CTAS, 256, ENC_SMEM>>>(x, enc_Wih0, enc_Whh1,
                                         enc_bih, enc_bhh, 1);

    // Decoder (warp-specialized recurrent prefill)
    dec_persist<<<DEC_CTAS, 256, DEC_SMEM>>>(x, dec_Wih0, dec_Wihr, dec_Whh,
                                             dec_bih, dec_bhh, lin_W, lin_b, out);
}